// round 1
// baseline (speedup 1.0000x reference)
#include <cuda_runtime.h>
#include <cstdint>

// ---------------- problem constants ----------------
#define NLAT   181
#define NLON   360
#define NV     78
#define NGRID  (NLAT*NLON)      // 65160
#define NBATCH 2
#define NMESH  10242
#define NEDGE  163840
#define NODE_D 256
#define EDGE_D 64
#define HIDD   512
#define NLAYERS 16
#define ENC_IN  163             // 2*V + 7
#define ENC_LDA 164             // padded row stride
#define MSG_IN  576             // EDGE_D + 2*NODE_D
#define NIN     320             // NODE_D + EDGE_D

// ---------------- device scratch (static, allocation-free) ----------------
__device__ float g_encin[(size_t)NBATCH*NMESH*ENC_LDA];   // ~13 MB
__device__ float g_x    [(size_t)NBATCH*NMESH*NODE_D];    // ~21 MB
__device__ float g_e    [(size_t)NEDGE*EDGE_D];           // ~42 MB
__device__ float g_e0   [(size_t)NEDGE*EDGE_D];           // ~42 MB
__device__ float g_msg  [(size_t)NEDGE*MSG_IN];           // ~377 MB
__device__ float g_h    [(size_t)NEDGE*HIDD];             // ~335 MB (shared hidden scratch)
__device__ float g_agg  [(size_t)NMESH*EDGE_D];           // ~2.6 MB
__device__ float g_nin  [(size_t)NMESH*NIN];              // ~13 MB
__device__ float g_decin[(size_t)NBATCH*NGRID*NODE_D];    // ~133 MB

// ---------------- generic fused GEMM: C = [res +] (A@W + bias) [relu] ----------------
// A: M x K (row stride lda), W: K x N row-major, bias: N
// Block: BM x BN, K-step BK=16, thread tile TM x TN (TN in groups of 4 columns).
template<int BM, int BN, int BK, int TM, int TN>
__global__ void __launch_bounds__(256)
sgemm_bias(const float* __restrict__ A, int lda,
           const float* __restrict__ W,
           const float* __restrict__ bias,
           const float* res,          // may alias C (no restrict)
           float* C,
           int M, int N, int K, int doRelu)
{
    constexpr int GN      = TN / 4;       // column groups of 4
    constexpr int CSTRIDE = BN / GN;      // stride between column groups
    constexpr int NTC     = BN / TN;      // thread-columns (=16)
    constexpr int THREADS = (BM / TM) * NTC;
    static_assert(THREADS == 256, "expect 256 threads");
    static_assert(BK == 16 && THREADS == BM * 2, "A loader mapping");

    __shared__ float As[BK][BM + 4];
    __shared__ float Bs[BK][BN];

    const int tid  = threadIdx.x;
    const int tcol = tid % NTC;           // 0..15
    const int trow = tid / NTC;           // 0..15
    const int rowBase = blockIdx.y * BM;
    const int colBase = blockIdx.x * BN;

    float acc[TM][TN];
    #pragma unroll
    for (int i = 0; i < TM; i++)
        #pragma unroll
        for (int j = 0; j < TN; j++) acc[i][j] = 0.f;

    // A loader: thread t -> row m=t/2, k-half h=t%2 (8 k's each), transposed store
    const int am = tid >> 1;
    const int ah = (tid & 1) * 8;

    for (int k0 = 0; k0 < K; k0 += BK) {
        // ---- load A tile (coalesced rows, transposed into smem) ----
        {
            const int gm = rowBase + am;
            const bool mok = (gm < M);
            const float* Arow = A + (size_t)gm * lda + (k0 + ah);
            #pragma unroll
            for (int i = 0; i < 8; i++) {
                int gk = k0 + ah + i;
                As[ah + i][am] = (mok && gk < K) ? Arow[i] : 0.f;
            }
        }
        // ---- load B tile (coalesced in n) ----
        #pragma unroll
        for (int it = 0; it < (BK * BN) / THREADS; it++) {
            int idx = tid + it * THREADS;
            int k = idx / BN, n = idx % BN;
            int gk = k0 + k, gn = colBase + n;
            Bs[k][n] = (gk < K && gn < N) ? W[(size_t)gk * N + gn] : 0.f;
        }
        __syncthreads();

        #pragma unroll
        for (int k = 0; k < BK; k++) {
            float ra[TM], rb[TN];
            #pragma unroll
            for (int i = 0; i < TM; i++) ra[i] = As[k][trow * TM + i];
            #pragma unroll
            for (int cg = 0; cg < GN; cg++)
                #pragma unroll
                for (int j = 0; j < 4; j++)
                    rb[cg * 4 + j] = Bs[k][cg * CSTRIDE + tcol * 4 + j];
            #pragma unroll
            for (int i = 0; i < TM; i++)
                #pragma unroll
                for (int j = 0; j < TN; j++)
                    acc[i][j] = fmaf(ra[i], rb[j], acc[i][j]);
        }
        __syncthreads();
    }

    // ---- epilogue: bias, relu, residual ----
    #pragma unroll
    for (int i = 0; i < TM; i++) {
        int gm = rowBase + trow * TM + i;
        if (gm >= M) continue;
        #pragma unroll
        for (int cg = 0; cg < GN; cg++) {
            #pragma unroll
            for (int j = 0; j < 4; j++) {
                int gn = colBase + cg * CSTRIDE + tcol * 4 + j;
                if (gn >= N) continue;
                float v = acc[i][cg * 4 + j] + bias[gn];
                if (doRelu) v = fmaxf(v, 0.f);
                size_t off = (size_t)gm * N + gn;
                if (res) v += res[off];
                C[off] = v;
            }
        }
    }
}

// ---------------- builder / scatter kernels ----------------
__global__ void build_encin(const float* __restrict__ xc, const float* __restrict__ xp,
                            const float* __restrict__ geo, const int* __restrict__ g2m,
                            float* __restrict__ out)
{
    int idx = blockIdx.x * blockDim.x + threadIdx.x;
    const int total = NBATCH * NMESH * ENC_LDA;
    if (idx >= total) return;
    int row = idx / ENC_LDA;
    int c   = idx - row * ENC_LDA;
    int b   = row / NMESH;
    int m   = row - b * NMESH;
    float v = 0.f;
    if (c < NV) {
        v = xc[((size_t)b * NGRID + g2m[m]) * NV + c];
    } else if (c < 2 * NV) {
        v = xp[((size_t)b * NGRID + g2m[m]) * NV + (c - NV)];
    } else if (c < ENC_IN) {
        v = geo[m * 7 + (c - 2 * NV)];
    }
    out[idx] = v;
}

__global__ void build_msg(const float* __restrict__ e, const float* __restrict__ x,
                          const int* __restrict__ src, const int* __restrict__ dst,
                          float* __restrict__ msg)
{
    long long idx = (long long)blockIdx.x * blockDim.x + threadIdx.x;
    if (idx >= (long long)NEDGE * MSG_IN) return;
    int j = (int)(idx / MSG_IN);
    int c = (int)(idx - (long long)j * MSG_IN);
    float v;
    if (c < EDGE_D)               v = e[(size_t)j * EDGE_D + c];
    else if (c < EDGE_D + NODE_D) v = x[(size_t)src[j] * NODE_D + (c - EDGE_D)];
    else                          v = x[(size_t)dst[j] * NODE_D + (c - EDGE_D - NODE_D)];
    msg[idx] = v;
}

__global__ void scatter_add_edges(const float* __restrict__ e, const int* __restrict__ dst,
                                  float* __restrict__ agg)
{
    int idx = blockIdx.x * blockDim.x + threadIdx.x;
    if (idx >= NEDGE * EDGE_D) return;
    int j = idx >> 6;          // / EDGE_D
    int c = idx & 63;
    atomicAdd(&agg[(size_t)dst[j] * EDGE_D + c], e[idx]);
}

__global__ void build_nin(const float* __restrict__ x, const float* __restrict__ agg,
                          float* __restrict__ out)
{
    int idx = blockIdx.x * blockDim.x + threadIdx.x;
    if (idx >= NMESH * NIN) return;
    int m = idx / NIN;
    int c = idx - m * NIN;
    out[idx] = (c < NODE_D) ? x[(size_t)m * NODE_D + c]
                            : agg[(size_t)m * EDGE_D + (c - NODE_D)];
}

__global__ void build_decin(const float* __restrict__ x, const int* __restrict__ m2g,
                            float* __restrict__ out)
{
    int idx = blockIdx.x * blockDim.x + threadIdx.x;
    const int total = NBATCH * NGRID * NODE_D;
    if (idx >= total) return;
    int row = idx / NODE_D;
    int c   = idx - row * NODE_D;
    int b   = row / NGRID;
    int g   = row - b * NGRID;
    out[idx] = x[((size_t)b * NMESH + m2g[g]) * NODE_D + c];
}

// ---------------- launcher ----------------
static inline dim3 gemm_grid(int M, int N, int BM, int BN) {
    return dim3((unsigned)((N + BN - 1) / BN), (unsigned)((M + BM - 1) / BM));
}

extern "C" void kernel_launch(void* const* d_in, const int* in_sizes, int n_in,
                              void* d_out, int out_size)
{
    const float* xc     = (const float*)d_in[0];
    const float* xp     = (const float*)d_in[1];
    const float* geo    = (const float*)d_in[2];
    const float* redge  = (const float*)d_in[3];
    const int*   eidx   = (const int*)  d_in[4];
    const int*   g2m    = (const int*)  d_in[5];
    const int*   m2g    = (const int*)  d_in[6];
    const float* enc_w1 = (const float*)d_in[7];
    const float* enc_b1 = (const float*)d_in[8];
    const float* enc_w2 = (const float*)d_in[9];
    const float* enc_b2 = (const float*)d_in[10];
    const float* eme_w1 = (const float*)d_in[11];
    const float* eme_b1 = (const float*)d_in[12];
    const float* eme_w2 = (const float*)d_in[13];
    const float* eme_b2 = (const float*)d_in[14];
    const float* pe_w1  = (const float*)d_in[15];
    const float* pe_b1  = (const float*)d_in[16];
    const float* pe_w2  = (const float*)d_in[17];
    const float* pe_b2  = (const float*)d_in[18];
    const float* pn_w1  = (const float*)d_in[19];
    const float* pn_b1  = (const float*)d_in[20];
    const float* pn_w2  = (const float*)d_in[21];
    const float* pn_b2  = (const float*)d_in[22];
    const float* dec_w1 = (const float*)d_in[23];
    const float* dec_b1 = (const float*)d_in[24];
    const float* dec_w2 = (const float*)d_in[25];
    const float* dec_b2 = (const float*)d_in[26];
    float* out = (float*)d_out;

    float *encin, *x, *e, *e0, *msg, *h, *agg, *nin, *decin;
    cudaGetSymbolAddress((void**)&encin, g_encin);
    cudaGetSymbolAddress((void**)&x,     g_x);
    cudaGetSymbolAddress((void**)&e,     g_e);
    cudaGetSymbolAddress((void**)&e0,    g_e0);
    cudaGetSymbolAddress((void**)&msg,   g_msg);
    cudaGetSymbolAddress((void**)&h,     g_h);
    cudaGetSymbolAddress((void**)&agg,   g_agg);
    cudaGetSymbolAddress((void**)&nin,   g_nin);
    cudaGetSymbolAddress((void**)&decin, g_decin);

    const int* src = eidx;
    const int* dst = eidx + NEDGE;

    // ---------- encoder ----------
    {
        int total = NBATCH * NMESH * ENC_LDA;
        build_encin<<<(total + 255) / 256, 256>>>(xc, xp, geo, g2m, encin);
    }
    sgemm_bias<128,128,16,8,8><<<gemm_grid(NBATCH*NMESH, HIDD, 128, 128), 256>>>(
        encin, ENC_LDA, enc_w1, enc_b1, nullptr, h, NBATCH*NMESH, HIDD, ENC_IN, 1);
    sgemm_bias<128,128,16,8,8><<<gemm_grid(NBATCH*NMESH, NODE_D, 128, 128), 256>>>(
        h, HIDD, enc_w2, enc_b2, nullptr, x, NBATCH*NMESH, NODE_D, HIDD, 0);

    // ---------- edge embedder ----------
    sgemm_bias<128,64,16,8,4><<<gemm_grid(NEDGE, EDGE_D, 128, 64), 256>>>(
        redge, 4, eme_w1, eme_b1, nullptr, h, NEDGE, EDGE_D, 4, 1);
    sgemm_bias<128,64,16,8,4><<<gemm_grid(NEDGE, EDGE_D, 128, 64), 256>>>(
        h, EDGE_D, eme_w2, eme_b2, nullptr, e0, NEDGE, EDGE_D, EDGE_D, 0);

    // ---------- GNN layers, per batch ----------
    for (int b = 0; b < NBATCH; b++) {
        float* xb = x + (size_t)b * NMESH * NODE_D;
        for (int l = 0; l < NLAYERS; l++) {
            const float* ein = (l == 0) ? e0 : e;

            {
                long long total = (long long)NEDGE * MSG_IN;
                build_msg<<<(unsigned)((total + 255) / 256), 256>>>(ein, xb, src, dst, msg);
            }
            sgemm_bias<128,128,16,8,8><<<gemm_grid(NEDGE, HIDD, 128, 128), 256>>>(
                msg, MSG_IN, pe_w1 + (size_t)l * MSG_IN * HIDD, pe_b1 + (size_t)l * HIDD,
                nullptr, h, NEDGE, HIDD, MSG_IN, 1);
            sgemm_bias<128,64,16,8,4><<<gemm_grid(NEDGE, EDGE_D, 128, 64), 256>>>(
                h, HIDD, pe_w2 + (size_t)l * HIDD * EDGE_D, pe_b2 + (size_t)l * EDGE_D,
                ein, e, NEDGE, EDGE_D, HIDD, 0);

            cudaMemsetAsync(agg, 0, (size_t)NMESH * EDGE_D * sizeof(float), 0);
            scatter_add_edges<<<(NEDGE * EDGE_D + 255) / 256, 256>>>(e, dst, agg);

            build_nin<<<(NMESH * NIN + 255) / 256, 256>>>(xb, agg, nin);
            sgemm_bias<128,128,16,8,8><<<gemm_grid(NMESH, HIDD, 128, 128), 256>>>(
                nin, NIN, pn_w1 + (size_t)l * NIN * HIDD, pn_b1 + (size_t)l * HIDD,
                nullptr, h, NMESH, HIDD, NIN, 1);
            sgemm_bias<128,128,16,8,8><<<gemm_grid(NMESH, NODE_D, 128, 128), 256>>>(
                h, HIDD, pn_w2 + (size_t)l * HIDD * NODE_D, pn_b2 + (size_t)l * NODE_D,
                xb, xb, NMESH, NODE_D, HIDD, 0);
        }
    }

    // ---------- decoder ----------
    {
        int total = NBATCH * NGRID * NODE_D;
        build_decin<<<(total + 255) / 256, 256>>>(x, m2g, decin);
    }
    sgemm_bias<128,128,16,8,8><<<gemm_grid(NBATCH*NGRID, HIDD, 128, 128), 256>>>(
        decin, NODE_D, dec_w1, dec_b1, nullptr, h, NBATCH*NGRID, HIDD, NODE_D, 1);
    sgemm_bias<128,64,16,8,4><<<gemm_grid(NBATCH*NGRID, NV, 128, 64), 256>>>(
        h, HIDD, dec_w2, dec_b2, nullptr, out, NBATCH*NGRID, NV, HIDD, 0);
}

// round 3
// speedup vs baseline: 3.6548x; 3.6548x over previous
#include <cuda_runtime.h>
#include <cuda_bf16.h>
#include <cstdint>

// ---------------- problem constants ----------------
#define NLAT   181
#define NLON   360
#define NV     78
#define NGRID  (NLAT*NLON)      // 65160
#define NBATCH 2
#define NMESH  10242
#define NEDGE  163840
#define NODE_D 256
#define EDGE_D 64
#define HIDD   512
#define NLAYERS 16
#define ENC_IN  163
#define ENC_LDA 164

// ---------------- device scratch ----------------
__device__ float g_encin[(size_t)NBATCH*NMESH*ENC_LDA];
__device__ float g_x    [(size_t)NBATCH*NMESH*NODE_D];
__device__ float g_e    [(size_t)NEDGE*EDGE_D];
__device__ float g_e0   [(size_t)NEDGE*EDGE_D];
__device__ float g_h    [(size_t)NEDGE*HIDD];      // shared hidden scratch (largest M)
__device__ float g_agg  [(size_t)NMESH*EDGE_D];
// bf16 hi/lo split weights, layout [L][K][N] (same as source, elementwise split)
__device__ __nv_bfloat16 g_pe1hi[(size_t)NLAYERS*576*HIDD];
__device__ __nv_bfloat16 g_pe1lo[(size_t)NLAYERS*576*HIDD];
__device__ __nv_bfloat16 g_pe2hi[(size_t)NLAYERS*HIDD*EDGE_D];
__device__ __nv_bfloat16 g_pe2lo[(size_t)NLAYERS*HIDD*EDGE_D];
__device__ __nv_bfloat16 g_pn1hi[(size_t)NLAYERS*320*HIDD];
__device__ __nv_bfloat16 g_pn1lo[(size_t)NLAYERS*320*HIDD];
__device__ __nv_bfloat16 g_pn2hi[(size_t)NLAYERS*HIDD*NODE_D];
__device__ __nv_bfloat16 g_pn2lo[(size_t)NLAYERS*HIDD*NODE_D];
__device__ __nv_bfloat16 g_dc1hi[(size_t)NODE_D*HIDD];
__device__ __nv_bfloat16 g_dc1lo[(size_t)NODE_D*HIDD];
__device__ __nv_bfloat16 g_en2hi[(size_t)HIDD*NODE_D];
__device__ __nv_bfloat16 g_en2lo[(size_t)HIDD*NODE_D];

// ---------------- small asm helpers (all plain sm_103-legal) ----------------
__device__ __forceinline__ void ldsm_x4(uint32_t* r, uint32_t addr) {
    asm volatile("ldmatrix.sync.aligned.m8n8.x4.shared.b16 {%0,%1,%2,%3}, [%4];"
        : "=r"(r[0]), "=r"(r[1]), "=r"(r[2]), "=r"(r[3]) : "r"(addr));
}
__device__ __forceinline__ void ldsm_x4t(uint32_t* r, uint32_t addr) {
    asm volatile("ldmatrix.sync.aligned.m8n8.x4.trans.shared.b16 {%0,%1,%2,%3}, [%4];"
        : "=r"(r[0]), "=r"(r[1]), "=r"(r[2]), "=r"(r[3]) : "r"(addr));
}
__device__ __forceinline__ void mma16816(float* d, const uint32_t* a, const uint32_t* b) {
    asm volatile("mma.sync.aligned.m16n8k16.row.col.f32.bf16.bf16.f32 "
        "{%0,%1,%2,%3}, {%4,%5,%6,%7}, {%8,%9}, {%0,%1,%2,%3};"
        : "+f"(d[0]), "+f"(d[1]), "+f"(d[2]), "+f"(d[3])
        : "r"(a[0]), "r"(a[1]), "r"(a[2]), "r"(a[3]), "r"(b[0]), "r"(b[1]));
}
__device__ __forceinline__ uint32_t smem_u32(const void* p) {
    uint32_t a;
    asm("{ .reg .u64 t; cvta.to.shared.u64 t, %1; cvt.u32.u64 %0, t; }" : "=r"(a) : "l"(p));
    return a;
}
#define CP_ASYNC16(dst, src) \
    asm volatile("cp.async.cg.shared.global [%0], [%1], 16;" :: "r"(dst), "l"(src))
#define CP_COMMIT() asm volatile("cp.async.commit_group;" ::: "memory")
#define CP_WAIT0()  asm volatile("cp.async.wait_group 0;" ::: "memory")
#define STS_V2(addr, x, y) \
    asm volatile("st.shared.v2.u32 [%0], {%1,%2};" :: "r"(addr), "r"(x), "r"(y))

__device__ __forceinline__ void split4(float4 v, uint2& hh, uint2& ll) {
    __nv_bfloat16 h0 = __float2bfloat16_rn(v.x), h1 = __float2bfloat16_rn(v.y);
    __nv_bfloat16 h2 = __float2bfloat16_rn(v.z), h3 = __float2bfloat16_rn(v.w);
    __nv_bfloat16 g0 = __float2bfloat16_rn(v.x - __bfloat162float(h0));
    __nv_bfloat16 g1 = __float2bfloat16_rn(v.y - __bfloat162float(h1));
    __nv_bfloat16 g2 = __float2bfloat16_rn(v.z - __bfloat162float(h2));
    __nv_bfloat16 g3 = __float2bfloat16_rn(v.w - __bfloat162float(h3));
    hh.x = (uint32_t)__bfloat16_as_ushort(h0) | ((uint32_t)__bfloat16_as_ushort(h1) << 16);
    hh.y = (uint32_t)__bfloat16_as_ushort(h2) | ((uint32_t)__bfloat16_as_ushort(h3) << 16);
    ll.x = (uint32_t)__bfloat16_as_ushort(g0) | ((uint32_t)__bfloat16_as_ushort(g1) << 16);
    ll.y = (uint32_t)__bfloat16_as_ushort(g2) | ((uint32_t)__bfloat16_as_ushort(g3) << 16);
}

// ---------------- A-gather modes ----------------
// MODE 0: plain A[M][K]
// MODE 1: msg = [e(64) | x[src](256) | x[dst](256)]  (K=576)
// MODE 2: nin = [x(256) | agg(64)]                   (K=320)
// MODE 3: gathered rows A[idx1[gr]][256]             (K=256)
template<int MODE>
__device__ __forceinline__ void prefA(float4 (&Ra)[8], int c, int rowBase, int M,
    const float* __restrict__ A, const float* __restrict__ aux,
    const int (&sI)[8], const int (&dI)[8], int tid, int K)
{
    const int f = tid & 15;
    #pragma unroll
    for (int it = 0; it < 8; it++) {
        int gr = rowBase + it * 16 + (tid >> 4);
        if (gr < M) {
            const float* p;
            if (MODE == 0) {
                p = A + (size_t)gr * K + c * 64;
            } else if (MODE == 1) {
                if (c == 0)      p = A   + (size_t)gr * 64;
                else if (c < 5)  p = aux + (size_t)sI[it] * 256 + (c - 1) * 64;
                else             p = aux + (size_t)dI[it] * 256 + (c - 5) * 64;
            } else if (MODE == 2) {
                p = (c < 4) ? A + (size_t)gr * 256 + c * 64
                            : aux + (size_t)gr * 64;
            } else {
                p = A + (size_t)sI[it] * 256 + c * 64;
            }
            Ra[it] = reinterpret_cast<const float4*>(p)[f];
        } else {
            Ra[it] = make_float4(0.f, 0.f, 0.f, 0.f);
        }
    }
}

// =====================================================================
//  HMMA GEMM: C[M x Nfull slice] = [res +] relu?(gather(A) @ W + bias)
//  CTA tile 128 x BN, K = NC*64, bf16 hi/lo 3-MMA split, fp32 accum.
// =====================================================================
template<int BN, int WARPS_N, int NC, int MODE, bool RELU, bool HAS_RES>
__global__ void __launch_bounds__(256)
mma_gemm(const float* __restrict__ A, const float* __restrict__ aux,
         const int* __restrict__ idx1, const int* __restrict__ idx2,
         const __nv_bfloat16* __restrict__ Bhi, const __nv_bfloat16* __restrict__ Blo,
         const float* __restrict__ bias, const float* res, float* C,
         int M, int Nfull)
{
    constexpr int K       = NC * 64;
    constexpr int WARPS_M = 8 / WARPS_N;
    constexpr int WTM     = 128 / WARPS_M;
    constexpr int WTN     = BN / WARPS_N;
    constexpr int MT      = WTM / 16;
    constexpr int NT      = WTN / 8;
    constexpr int ASTRIDE = 72;                 // bf16 elems per A row
    constexpr int APLANE  = 128 * ASTRIDE * 2;  // bytes per hi/lo plane
    constexpr int ABUF    = 2 * APLANE;
    constexpr int BSTRIDE = BN + 8;
    constexpr int BPLANE  = 64 * BSTRIDE * 2;
    constexpr int BBUF    = 2 * BPLANE;
    constexpr int GRAN    = BN / 8;             // 16B granules per B row
    constexpr int BTOT    = 2 * 64 * GRAN;      // granules per chunk (hi+lo)

    extern __shared__ char sm[];
    const uint32_t smA = smem_u32(sm);
    const uint32_t smB = smA + 2 * ABUF;

    const int tid    = threadIdx.x;
    const int lane   = tid & 31;
    const int wid    = tid >> 5;
    const int warp_n = wid % WARPS_N;
    const int warp_m = wid / WARPS_N;
    const int rowBase = blockIdx.y * 128;
    const int colBase = blockIdx.x * BN;

    // preload gather indices for this thread's 8 rows
    int sI[8], dI[8];
    #pragma unroll
    for (int it = 0; it < 8; it++) {
        int gr = rowBase + it * 16 + (tid >> 4);
        int g  = (gr < M) ? gr : 0;
        sI[it] = (MODE == 1 || MODE == 3) ? idx1[g] : 0;
        dI[it] = (MODE == 1) ? idx2[g] : 0;
    }

    float acc[MT][NT][4];
    #pragma unroll
    for (int i = 0; i < MT; i++)
        #pragma unroll
        for (int j = 0; j < NT; j++)
            #pragma unroll
            for (int q = 0; q < 4; q++) acc[i][j][q] = 0.f;

    float4 Ra[8];
    prefA<MODE>(Ra, 0, rowBase, M, A, aux, sI, dI, tid, K);

    // issue B chunk 0
    {
        #pragma unroll
        for (int it = 0; it < BTOT / 256; it++) {
            int i = it * 256 + tid;
            int plane = i / (64 * GRAN);
            int rem   = i % (64 * GRAN);
            int k = rem / GRAN, g = rem % GRAN;
            const __nv_bfloat16* sp = (plane ? Blo : Bhi)
                + (size_t)k * Nfull + colBase + g * 8;
            CP_ASYNC16(smB + plane * BPLANE + (uint32_t)(k * BSTRIDE + g * 8) * 2, sp);
        }
        CP_COMMIT();
    }

    for (int c = 0; c < NC; c++) {
        const int buf = c & 1;
        // store A regs -> smem (split hi/lo)
        #pragma unroll
        for (int it = 0; it < 8; it++) {
            int r = it * 16 + (tid >> 4);
            int f = tid & 15;
            uint2 hh, ll;
            split4(Ra[it], hh, ll);
            uint32_t off = smA + buf * ABUF + (uint32_t)(r * ASTRIDE + f * 4) * 2;
            STS_V2(off, hh.x, hh.y);
            STS_V2(off + APLANE, ll.x, ll.y);
        }
        if (c + 1 < NC) prefA<MODE>(Ra, c + 1, rowBase, M, A, aux, sI, dI, tid, K);
        CP_WAIT0();
        __syncthreads();
        if (c + 1 < NC) {
            #pragma unroll
            for (int it = 0; it < BTOT / 256; it++) {
                int i = it * 256 + tid;
                int plane = i / (64 * GRAN);
                int rem   = i % (64 * GRAN);
                int k = rem / GRAN, g = rem % GRAN;
                const __nv_bfloat16* sp = (plane ? Blo : Bhi)
                    + (size_t)(c + 1) * 64 * Nfull + (size_t)k * Nfull + colBase + g * 8;
                CP_ASYNC16(smB + (1 - buf) * BBUF + plane * BPLANE
                           + (uint32_t)(k * BSTRIDE + g * 8) * 2, sp);
            }
            CP_COMMIT();
        }

        // ---- 4 k16 steps of MMA ----
        #pragma unroll
        for (int ks = 0; ks < 4; ks++) {
            uint32_t Ah[MT][4], Al[MT][4];
            #pragma unroll
            for (int mt = 0; mt < MT; mt++) {
                uint32_t addr = smA + buf * ABUF
                    + (uint32_t)((warp_m * WTM + mt * 16 + (lane & 15)) * ASTRIDE
                                 + ks * 16 + (lane >> 4) * 8) * 2;
                ldsm_x4(Ah[mt], addr);
                ldsm_x4(Al[mt], addr + APLANE);
            }
            uint32_t Bh[NT / 2][4], Bl[NT / 2][4];
            #pragma unroll
            for (int np = 0; np < NT / 2; np++) {
                uint32_t addr = smB + buf * BBUF
                    + (uint32_t)((ks * 16 + (lane & 15)) * BSTRIDE
                                 + warp_n * WTN + np * 16 + (lane >> 4) * 8) * 2;
                ldsm_x4t(Bh[np], addr);
                ldsm_x4t(Bl[np], addr + BPLANE);
            }
            #pragma unroll
            for (int mt = 0; mt < MT; mt++)
                #pragma unroll
                for (int nt = 0; nt < NT; nt++) {
                    const uint32_t* bh = &Bh[nt >> 1][(nt & 1) * 2];
                    const uint32_t* bl = &Bl[nt >> 1][(nt & 1) * 2];
                    mma16816(acc[mt][nt], Ah[mt], bh);
                    mma16816(acc[mt][nt], Ah[mt], bl);
                    mma16816(acc[mt][nt], Al[mt], bh);
                }
        }
    }

    // ---- epilogue ----
    #pragma unroll
    for (int nt = 0; nt < NT; nt++) {
        int n = colBase + warp_n * WTN + nt * 8 + (lane & 3) * 2;
        float2 bb = *reinterpret_cast<const float2*>(bias + n);
        #pragma unroll
        for (int mt = 0; mt < MT; mt++) {
            #pragma unroll
            for (int half = 0; half < 2; half++) {
                int row = rowBase + warp_m * WTM + mt * 16 + (lane >> 2) + half * 8;
                if (row < M) {
                    float vx = acc[mt][nt][half * 2 + 0] + bb.x;
                    float vy = acc[mt][nt][half * 2 + 1] + bb.y;
                    size_t off = (size_t)row * Nfull + n;
                    if (HAS_RES) {
                        float2 rr = *reinterpret_cast<const float2*>(res + off);
                        vx += rr.x; vy += rr.y;
                    }
                    if (RELU) { vx = fmaxf(vx, 0.f); vy = fmaxf(vy, 0.f); }
                    float2 o; o.x = vx; o.y = vy;
                    *reinterpret_cast<float2*>(C + off) = o;
                }
            }
        }
    }
}

// ---------------- weight split (elementwise, layout preserved [K][N]) ----------------
__global__ void wsplit(const float* __restrict__ w, __nv_bfloat16* __restrict__ hi,
                       __nv_bfloat16* __restrict__ lo, int total)
{
    int i = blockIdx.x * blockDim.x + threadIdx.x;
    if (i >= total) return;
    float v = w[i];
    __nv_bfloat16 h = __float2bfloat16_rn(v);
    hi[i] = h;
    lo[i] = __float2bfloat16_rn(v - __bfloat162float(h));
}

// =====================================================================
//  SIMT fp32 GEMM (encoder MLP1, embedder, decoder MLP2)
// =====================================================================
template<int BM, int BN, int BK, int TM, int TN>
__global__ void __launch_bounds__(256)
sgemm_bias(const float* __restrict__ A, int lda,
           const float* __restrict__ W,
           const float* __restrict__ bias,
           const float* res, float* C,
           int M, int N, int K, int doRelu)
{
    constexpr int GN      = TN / 4;
    constexpr int CSTRIDE = BN / GN;
    constexpr int NTC     = BN / TN;
    constexpr int THREADS = (BM / TM) * NTC;
    static_assert(THREADS == 256, "expect 256 threads");
    static_assert(BK == 16 && THREADS == BM * 2, "A loader mapping");

    __shared__ float As[BK][BM + 4];
    __shared__ float Bs[BK][BN];

    const int tid  = threadIdx.x;
    const int tcol = tid % NTC;
    const int trow = tid / NTC;
    const int rowBase = blockIdx.y * BM;
    const int colBase = blockIdx.x * BN;

    float acc[TM][TN];
    #pragma unroll
    for (int i = 0; i < TM; i++)
        #pragma unroll
        for (int j = 0; j < TN; j++) acc[i][j] = 0.f;

    const int am = tid >> 1;
    const int ah = (tid & 1) * 8;

    for (int k0 = 0; k0 < K; k0 += BK) {
        {
            const int gm = rowBase + am;
            const bool mok = (gm < M);
            const float* Arow = A + (size_t)gm * lda + (k0 + ah);
            #pragma unroll
            for (int i = 0; i < 8; i++) {
                int gk = k0 + ah + i;
                As[ah + i][am] = (mok && gk < K) ? Arow[i] : 0.f;
            }
        }
        #pragma unroll
        for (int it = 0; it < (BK * BN) / THREADS; it++) {
            int idx = tid + it * THREADS;
            int k = idx / BN, n = idx % BN;
            int gk = k0 + k, gn = colBase + n;
            Bs[k][n] = (gk < K && gn < N) ? W[(size_t)gk * N + gn] : 0.f;
        }
        __syncthreads();

        #pragma unroll
        for (int k = 0; k < BK; k++) {
            float ra[TM], rb[TN];
            #pragma unroll
            for (int i = 0; i < TM; i++) ra[i] = As[k][trow * TM + i];
            #pragma unroll
            for (int cg = 0; cg < GN; cg++)
                #pragma unroll
                for (int j = 0; j < 4; j++)
                    rb[cg * 4 + j] = Bs[k][cg * CSTRIDE + tcol * 4 + j];
            #pragma unroll
            for (int i = 0; i < TM; i++)
                #pragma unroll
                for (int j = 0; j < TN; j++)
                    acc[i][j] = fmaf(ra[i], rb[j], acc[i][j]);
        }
        __syncthreads();
    }

    #pragma unroll
    for (int i = 0; i < TM; i++) {
        int gm = rowBase + trow * TM + i;
        if (gm >= M) continue;
        #pragma unroll
        for (int cg = 0; cg < GN; cg++) {
            #pragma unroll
            for (int j = 0; j < 4; j++) {
                int gn = colBase + cg * CSTRIDE + tcol * 4 + j;
                if (gn >= N) continue;
                float v = acc[i][cg * 4 + j] + bias[gn];
                if (doRelu) v = fmaxf(v, 0.f);
                size_t off = (size_t)gm * N + gn;
                if (res) v += res[off];
                C[off] = v;
            }
        }
    }
}

// ---------------- builders / scatter ----------------
__global__ void build_encin(const float* __restrict__ xc, const float* __restrict__ xp,
                            const float* __restrict__ geo, const int* __restrict__ g2m,
                            float* __restrict__ out)
{
    int idx = blockIdx.x * blockDim.x + threadIdx.x;
    const int total = NBATCH * NMESH * ENC_LDA;
    if (idx >= total) return;
    int row = idx / ENC_LDA;
    int c   = idx - row * ENC_LDA;
    int b   = row / NMESH;
    int m   = row - b * NMESH;
    float v = 0.f;
    if (c < NV)            v = xc[((size_t)b * NGRID + g2m[m]) * NV + c];
    else if (c < 2 * NV)   v = xp[((size_t)b * NGRID + g2m[m]) * NV + (c - NV)];
    else if (c < ENC_IN)   v = geo[m * 7 + (c - 2 * NV)];
    out[idx] = v;
}

__global__ void scatter_add_edges(const float* __restrict__ e, const int* __restrict__ dst,
                                  float* __restrict__ agg)
{
    int idx = blockIdx.x * blockDim.x + threadIdx.x;
    if (idx >= NEDGE * EDGE_D) return;
    int j = idx >> 6;
    int c = idx & 63;
    atomicAdd(&agg[(size_t)dst[j] * EDGE_D + c], e[idx]);
}

// ---------------- launcher ----------------
static inline dim3 gemm_grid(int M, int N, int BM, int BN) {
    return dim3((unsigned)((N + BN - 1) / BN), (unsigned)((M + BM - 1) / BM));
}

extern "C" void kernel_launch(void* const* d_in, const int* in_sizes, int n_in,
                              void* d_out, int out_size)
{
    const float* xc     = (const float*)d_in[0];
    const float* xp     = (const float*)d_in[1];
    const float* geo    = (const float*)d_in[2];
    const float* redge  = (const float*)d_in[3];
    const int*   eidx   = (const int*)  d_in[4];
    const int*   g2m    = (const int*)  d_in[5];
    const int*   m2g    = (const int*)  d_in[6];
    const float* enc_w1 = (const float*)d_in[7];
    const float* enc_b1 = (const float*)d_in[8];
    const float* enc_w2 = (const float*)d_in[9];
    const float* enc_b2 = (const float*)d_in[10];
    const float* eme_w1 = (const float*)d_in[11];
    const float* eme_b1 = (const float*)d_in[12];
    const float* eme_w2 = (const float*)d_in[13];
    const float* eme_b2 = (const float*)d_in[14];
    const float* pe_w1  = (const float*)d_in[15];
    const float* pe_b1  = (const float*)d_in[16];
    const float* pe_w2  = (const float*)d_in[17];
    const float* pe_b2  = (const float*)d_in[18];
    const float* pn_w1  = (const float*)d_in[19];
    const float* pn_b1  = (const float*)d_in[20];
    const float* pn_w2  = (const float*)d_in[21];
    const float* pn_b2  = (const float*)d_in[22];
    const float* dec_w1 = (const float*)d_in[23];
    const float* dec_b1 = (const float*)d_in[24];
    const float* dec_w2 = (const float*)d_in[25];
    const float* dec_b2 = (const float*)d_in[26];
    float* out = (float*)d_out;

    float *encin, *x, *e, *e0, *h, *agg;
    __nv_bfloat16 *pe1hi,*pe1lo,*pe2hi,*pe2lo,*pn1hi,*pn1lo,*pn2hi,*pn2lo,*dc1hi,*dc1lo,*en2hi,*en2lo;
    cudaGetSymbolAddress((void**)&encin, g_encin);
    cudaGetSymbolAddress((void**)&x,     g_x);
    cudaGetSymbolAddress((void**)&e,     g_e);
    cudaGetSymbolAddress((void**)&e0,    g_e0);
    cudaGetSymbolAddress((void**)&h,     g_h);
    cudaGetSymbolAddress((void**)&agg,   g_agg);
    cudaGetSymbolAddress((void**)&pe1hi, g_pe1hi);
    cudaGetSymbolAddress((void**)&pe1lo, g_pe1lo);
    cudaGetSymbolAddress((void**)&pe2hi, g_pe2hi);
    cudaGetSymbolAddress((void**)&pe2lo, g_pe2lo);
    cudaGetSymbolAddress((void**)&pn1hi, g_pn1hi);
    cudaGetSymbolAddress((void**)&pn1lo, g_pn1lo);
    cudaGetSymbolAddress((void**)&pn2hi, g_pn2hi);
    cudaGetSymbolAddress((void**)&pn2lo, g_pn2lo);
    cudaGetSymbolAddress((void**)&dc1hi, g_dc1hi);
    cudaGetSymbolAddress((void**)&dc1lo, g_dc1lo);
    cudaGetSymbolAddress((void**)&en2hi, g_en2hi);
    cudaGetSymbolAddress((void**)&en2lo, g_en2lo);

    const int* src = eidx;
    const int* dst = eidx + NEDGE;

    // smem sizes
    constexpr int ASM   = 2 * (2 * 128 * 72 * 2);            // 73728
    constexpr int BSM128 = 2 * (2 * 64 * 136 * 2);           // 69632
    constexpr int BSM64  = 2 * (2 * 64 * 72 * 2);            // 36864
    constexpr int SM128 = ASM + BSM128;                       // 143360
    constexpr int SM64  = ASM + BSM64;                        // 110592

    cudaFuncSetAttribute((const void*)mma_gemm<128,4,9,1,true,false>,
                         cudaFuncAttributeMaxDynamicSharedMemorySize, SM128);
    cudaFuncSetAttribute((const void*)mma_gemm<64,2,8,0,false,true>,
                         cudaFuncAttributeMaxDynamicSharedMemorySize, SM64);
    cudaFuncSetAttribute((const void*)mma_gemm<128,4,5,2,true,false>,
                         cudaFuncAttributeMaxDynamicSharedMemorySize, SM128);
    cudaFuncSetAttribute((const void*)mma_gemm<128,4,8,0,false,true>,
                         cudaFuncAttributeMaxDynamicSharedMemorySize, SM128);
    cudaFuncSetAttribute((const void*)mma_gemm<128,4,4,3,true,false>,
                         cudaFuncAttributeMaxDynamicSharedMemorySize, SM128);
    cudaFuncSetAttribute((const void*)mma_gemm<128,4,8,0,false,false>,
                         cudaFuncAttributeMaxDynamicSharedMemorySize, SM128);

    // ---------- weight split ----------
    { int t = NLAYERS*576*HIDD;   wsplit<<<(t+255)/256,256>>>(pe_w1, pe1hi, pe1lo, t); }
    { int t = NLAYERS*HIDD*EDGE_D;wsplit<<<(t+255)/256,256>>>(pe_w2, pe2hi, pe2lo, t); }
    { int t = NLAYERS*320*HIDD;   wsplit<<<(t+255)/256,256>>>(pn_w1, pn1hi, pn1lo, t); }
    { int t = NLAYERS*HIDD*NODE_D;wsplit<<<(t+255)/256,256>>>(pn_w2, pn2hi, pn2lo, t); }
    { int t = NODE_D*HIDD;        wsplit<<<(t+255)/256,256>>>(dec_w1, dc1hi, dc1lo, t); }
    { int t = HIDD*NODE_D;        wsplit<<<(t+255)/256,256>>>(enc_w2, en2hi, en2lo, t); }

    // ---------- encoder ----------
    {
        int total = NBATCH * NMESH * ENC_LDA;
        build_encin<<<(total + 255) / 256, 256>>>(xc, xp, geo, g2m, encin);
    }
    sgemm_bias<128,128,16,8,8><<<gemm_grid(NBATCH*NMESH, HIDD, 128, 128), 256>>>(
        encin, ENC_LDA, enc_w1, enc_b1, nullptr, h, NBATCH*NMESH, HIDD, ENC_IN, 1);
    // encoder MLP2 on tensor cores: M=20484, K=512, N=256
    mma_gemm<128,4,8,0,false,false><<<dim3(2, (NBATCH*NMESH + 127)/128), 256, SM128>>>(
        h, nullptr, nullptr, nullptr, en2hi, en2lo, enc_b2, nullptr, x,
        NBATCH*NMESH, NODE_D);

    // ---------- edge embedder (SIMT, tiny) ----------
    sgemm_bias<128,64,16,8,4><<<gemm_grid(NEDGE, EDGE_D, 128, 64), 256>>>(
        redge, 4, eme_w1, eme_b1, nullptr, h, NEDGE, EDGE_D, 4, 1);
    sgemm_bias<128,64,16,8,4><<<gemm_grid(NEDGE, EDGE_D, 128, 64), 256>>>(
        h, EDGE_D, eme_w2, eme_b2, nullptr, e0, NEDGE, EDGE_D, EDGE_D, 0);

    // ---------- GNN layers ----------
    for (int b = 0; b < NBATCH; b++) {
        float* xb = x + (size_t)b * NMESH * NODE_D;
        for (int l = 0; l < NLAYERS; l++) {
            const float* ein = (l == 0) ? e0 : e;

            // edge MLP1: gathered [e | x[src] | x[dst]] @ W1 + b, relu  (K=576, N=512)
            mma_gemm<128,4,9,1,true,false><<<dim3(4, NEDGE/128), 256, SM128>>>(
                ein, xb, src, dst,
                pe1hi + (size_t)l*576*HIDD, pe1lo + (size_t)l*576*HIDD,
                pe_b1 + (size_t)l*HIDD, nullptr, h, NEDGE, HIDD);
            // edge MLP2: h @ W2 + b + e_in  (K=512, N=64)
            mma_gemm<64,2,8,0,false,true><<<dim3(1, NEDGE/128), 256, SM64>>>(
                h, nullptr, nullptr, nullptr,
                pe2hi + (size_t)l*HIDD*EDGE_D, pe2lo + (size_t)l*HIDD*EDGE_D,
                pe_b2 + (size_t)l*EDGE_D, ein, e, NEDGE, EDGE_D);

            cudaMemsetAsync(agg, 0, (size_t)NMESH * EDGE_D * sizeof(float), 0);
            scatter_add_edges<<<(NEDGE * EDGE_D + 255) / 256, 256>>>(e, dst, agg);

            // node MLP1: gathered [x | agg] @ W1 + b, relu  (K=320, N=512)
            mma_gemm<128,4,5,2,true,false><<<dim3(4, (NMESH+127)/128), 256, SM128>>>(
                xb, agg, nullptr, nullptr,
                pn1hi + (size_t)l*320*HIDD, pn1lo + (size_t)l*320*HIDD,
                pn_b1 + (size_t)l*HIDD, nullptr, h, NMESH, HIDD);
            // node MLP2: h @ W2 + b + x (in place)  (K=512, N=256)
            mma_gemm<128,4,8,0,false,true><<<dim3(2, (NMESH+127)/128), 256, SM128>>>(
                h, nullptr, nullptr, nullptr,
                pn2hi + (size_t)l*HIDD*NODE_D, pn2lo + (size_t)l*HIDD*NODE_D,
                pn_b2 + (size_t)l*NODE_D, xb, xb, NMESH, NODE_D);
        }
    }

    // ---------- decoder ----------
    // MLP1 per batch: gathered x[m2g] @ dec_w1 + b, relu  (K=256, N=512)
    for (int b = 0; b < NBATCH; b++) {
        mma_gemm<128,4,4,3,true,false><<<dim3(4, (NGRID+127)/128), 256, SM128>>>(
            x + (size_t)b*NMESH*NODE_D, nullptr, m2g, nullptr,
            dc1hi, dc1lo, dec_b1, nullptr,
            h + (size_t)b*NGRID*HIDD, NGRID, HIDD);
    }
    // MLP2: SIMT (N=78)
    sgemm_bias<128,64,16,8,4><<<gemm_grid(NBATCH*NGRID, NV, 128, 64), 256>>>(
        h, HIDD, dec_w2, dec_b2, nullptr, out, NBATCH*NGRID, NV, HIDD, 0);
}

// round 4
// speedup vs baseline: 6.3012x; 1.7241x over previous
#include <cuda_runtime.h>
#include <cuda_bf16.h>
#include <cstdint>

// ---------------- problem constants ----------------
#define NLAT   181
#define NLON   360
#define NV     78
#define NGRID  (NLAT*NLON)      // 65160
#define NBATCH 2
#define NMESH  10242
#define NEDGE  163840
#define NODE_D 256
#define EDGE_D 64
#define HIDD   512
#define NLAYERS 16
#define ENC_IN  163
#define ENC_LDA 164

// ---------------- device scratch ----------------
__device__ float g_encin[(size_t)NBATCH*NMESH*ENC_LDA];
__device__ float g_x    [(size_t)NBATCH*NMESH*NODE_D];
__device__ float g_e    [(size_t)NEDGE*EDGE_D];
__device__ float g_e0   [(size_t)NEDGE*EDGE_D];
__device__ float g_h    [(size_t)NEDGE*HIDD];      // eW scratch / hidden scratch
__device__ float g_agg  [(size_t)NMESH*EDGE_D];
__device__ float g_xs   [(size_t)NMESH*HIDD];      // x @ Wsrc
__device__ float g_xd   [(size_t)NMESH*HIDD];      // x @ Wdst
__device__ float g_zeros[HIDD];                    // zero bias (zero-initialized)
// bf16 hi/lo split weights, layout [L][K][N]
__device__ __nv_bfloat16 g_pe1hi[(size_t)NLAYERS*576*HIDD];
__device__ __nv_bfloat16 g_pe1lo[(size_t)NLAYERS*576*HIDD];
__device__ __nv_bfloat16 g_pe2hi[(size_t)NLAYERS*HIDD*EDGE_D];
__device__ __nv_bfloat16 g_pe2lo[(size_t)NLAYERS*HIDD*EDGE_D];
__device__ __nv_bfloat16 g_pn1hi[(size_t)NLAYERS*320*HIDD];
__device__ __nv_bfloat16 g_pn1lo[(size_t)NLAYERS*320*HIDD];
__device__ __nv_bfloat16 g_pn2hi[(size_t)NLAYERS*HIDD*NODE_D];
__device__ __nv_bfloat16 g_pn2lo[(size_t)NLAYERS*HIDD*NODE_D];
__device__ __nv_bfloat16 g_dc1hi[(size_t)NODE_D*HIDD];
__device__ __nv_bfloat16 g_dc1lo[(size_t)NODE_D*HIDD];
__device__ __nv_bfloat16 g_en2hi[(size_t)HIDD*NODE_D];
__device__ __nv_bfloat16 g_en2lo[(size_t)HIDD*NODE_D];

// ---------------- asm helpers ----------------
__device__ __forceinline__ void ldsm_x4(uint32_t* r, uint32_t addr) {
    asm volatile("ldmatrix.sync.aligned.m8n8.x4.shared.b16 {%0,%1,%2,%3}, [%4];"
        : "=r"(r[0]), "=r"(r[1]), "=r"(r[2]), "=r"(r[3]) : "r"(addr));
}
__device__ __forceinline__ void ldsm_x4t(uint32_t* r, uint32_t addr) {
    asm volatile("ldmatrix.sync.aligned.m8n8.x4.trans.shared.b16 {%0,%1,%2,%3}, [%4];"
        : "=r"(r[0]), "=r"(r[1]), "=r"(r[2]), "=r"(r[3]) : "r"(addr));
}
__device__ __forceinline__ void mma16816(float* d, const uint32_t* a, const uint32_t* b) {
    asm volatile("mma.sync.aligned.m16n8k16.row.col.f32.bf16.bf16.f32 "
        "{%0,%1,%2,%3}, {%4,%5,%6,%7}, {%8,%9}, {%0,%1,%2,%3};"
        : "+f"(d[0]), "+f"(d[1]), "+f"(d[2]), "+f"(d[3])
        : "r"(a[0]), "r"(a[1]), "r"(a[2]), "r"(a[3]), "r"(b[0]), "r"(b[1]));
}
__device__ __forceinline__ uint32_t smem_u32(const void* p) {
    uint32_t a;
    asm("{ .reg .u64 t; cvta.to.shared.u64 t, %1; cvt.u32.u64 %0, t; }" : "=r"(a) : "l"(p));
    return a;
}
#define CP_ASYNC16(dst, src) \
    asm volatile("cp.async.cg.shared.global [%0], [%1], 16;" :: "r"(dst), "l"(src))
#define CP_COMMIT() asm volatile("cp.async.commit_group;" ::: "memory")
#define CP_WAIT0()  asm volatile("cp.async.wait_group 0;" ::: "memory")
#define STS_V2(addr, x, y) \
    asm volatile("st.shared.v2.u32 [%0], {%1,%2};" :: "r"(addr), "r"(x), "r"(y))

__device__ __forceinline__ void split4(float4 v, uint2& hh, uint2& ll) {
    __nv_bfloat16 h0 = __float2bfloat16_rn(v.x), h1 = __float2bfloat16_rn(v.y);
    __nv_bfloat16 h2 = __float2bfloat16_rn(v.z), h3 = __float2bfloat16_rn(v.w);
    __nv_bfloat16 g0 = __float2bfloat16_rn(v.x - __bfloat162float(h0));
    __nv_bfloat16 g1 = __float2bfloat16_rn(v.y - __bfloat162float(h1));
    __nv_bfloat16 g2 = __float2bfloat16_rn(v.z - __bfloat162float(h2));
    __nv_bfloat16 g3 = __float2bfloat16_rn(v.w - __bfloat162float(h3));
    hh.x = (uint32_t)__bfloat16_as_ushort(h0) | ((uint32_t)__bfloat16_as_ushort(h1) << 16);
    hh.y = (uint32_t)__bfloat16_as_ushort(h2) | ((uint32_t)__bfloat16_as_ushort(h3) << 16);
    ll.x = (uint32_t)__bfloat16_as_ushort(g0) | ((uint32_t)__bfloat16_as_ushort(g1) << 16);
    ll.y = (uint32_t)__bfloat16_as_ushort(g2) | ((uint32_t)__bfloat16_as_ushort(g3) << 16);
}

// ---------------- A-gather modes ----------------
// MODE 0: plain A[M][K]
// MODE 1: relu(A[gr] + xs[src[gr]] + xd[dst[gr]])    (K=512, A=eW+b1)
// MODE 2: nin = [x(256) | agg(64)]                   (K=320)
// MODE 3: gathered rows A[idx1[gr]][256]             (K=256)
template<int MODE>
__device__ __forceinline__ void prefA(float4 (&Ra)[8], int c, int rowBase, int M,
    const float* __restrict__ A, const float* __restrict__ aux, const float* __restrict__ aux2,
    const int (&sI)[8], const int (&dI)[8], int tid, int K)
{
    const int f = tid & 15;
    #pragma unroll
    for (int it = 0; it < 8; it++) {
        int gr = rowBase + it * 16 + (tid >> 4);
        if (gr < M) {
            if (MODE == 1) {
                float4 a = reinterpret_cast<const float4*>(A    + (size_t)gr    * 512 + c * 64)[f];
                float4 s = reinterpret_cast<const float4*>(aux  + (size_t)sI[it]* 512 + c * 64)[f];
                float4 d = reinterpret_cast<const float4*>(aux2 + (size_t)dI[it]* 512 + c * 64)[f];
                float4 v;
                v.x = fmaxf(a.x + s.x + d.x, 0.f);
                v.y = fmaxf(a.y + s.y + d.y, 0.f);
                v.z = fmaxf(a.z + s.z + d.z, 0.f);
                v.w = fmaxf(a.w + s.w + d.w, 0.f);
                Ra[it] = v;
            } else {
                const float* p;
                if (MODE == 0)      p = A + (size_t)gr * K + c * 64;
                else if (MODE == 2) p = (c < 4) ? A + (size_t)gr * 256 + c * 64
                                                : aux + (size_t)gr * 64;
                else                p = A + (size_t)sI[it] * 256 + c * 64;
                Ra[it] = reinterpret_cast<const float4*>(p)[f];
            }
        } else {
            Ra[it] = make_float4(0.f, 0.f, 0.f, 0.f);
        }
    }
}

// =====================================================================
//  HMMA GEMM: C[M x Nfull] = [res +] relu?(gather(A) @ W + bias)
//  optional fused scatter-add of the result into scat[idx2[row]*Nfull + n]
// =====================================================================
template<int BN, int WARPS_N, int NC, int MODE, bool RELU, bool HAS_RES, bool SCAT>
__global__ void __launch_bounds__(256)
mma_gemm(const float* __restrict__ A, const float* __restrict__ aux,
         const float* __restrict__ aux2,
         const int* __restrict__ idx1, const int* __restrict__ idx2,
         const __nv_bfloat16* __restrict__ Bhi, const __nv_bfloat16* __restrict__ Blo,
         const float* __restrict__ bias, const float* res, float* C,
         float* scat, int M, int Nfull)
{
    constexpr int K       = NC * 64;
    constexpr int WARPS_M = 8 / WARPS_N;
    constexpr int WTM     = 128 / WARPS_M;
    constexpr int WTN     = BN / WARPS_N;
    constexpr int MT      = WTM / 16;
    constexpr int NT      = WTN / 8;
    constexpr int ASTRIDE = 72;
    constexpr int APLANE  = 128 * ASTRIDE * 2;
    constexpr int ABUF    = 2 * APLANE;
    constexpr int BSTRIDE = BN + 8;
    constexpr int BPLANE  = 64 * BSTRIDE * 2;
    constexpr int BBUF    = 2 * BPLANE;
    constexpr int GRAN    = BN / 8;
    constexpr int BTOT    = 2 * 64 * GRAN;

    extern __shared__ char sm[];
    const uint32_t smA = smem_u32(sm);
    const uint32_t smB = smA + 2 * ABUF;

    const int tid    = threadIdx.x;
    const int lane   = tid & 31;
    const int wid    = tid >> 5;
    const int warp_n = wid % WARPS_N;
    const int warp_m = wid / WARPS_N;
    const int rowBase = blockIdx.y * 128;
    const int colBase = blockIdx.x * BN;

    int sI[8], dI[8];
    #pragma unroll
    for (int it = 0; it < 8; it++) {
        int gr = rowBase + it * 16 + (tid >> 4);
        int g  = (gr < M) ? gr : 0;
        sI[it] = (MODE == 1 || MODE == 3) ? idx1[g] : 0;
        dI[it] = (MODE == 1) ? idx2[g] : 0;
    }

    float acc[MT][NT][4];
    #pragma unroll
    for (int i = 0; i < MT; i++)
        #pragma unroll
        for (int j = 0; j < NT; j++)
            #pragma unroll
            for (int q = 0; q < 4; q++) acc[i][j][q] = 0.f;

    float4 Ra[8];
    prefA<MODE>(Ra, 0, rowBase, M, A, aux, aux2, sI, dI, tid, K);

    {
        #pragma unroll
        for (int it = 0; it < BTOT / 256; it++) {
            int i = it * 256 + tid;
            int plane = i / (64 * GRAN);
            int rem   = i % (64 * GRAN);
            int k = rem / GRAN, g = rem % GRAN;
            const __nv_bfloat16* sp = (plane ? Blo : Bhi)
                + (size_t)k * Nfull + colBase + g * 8;
            CP_ASYNC16(smB + plane * BPLANE + (uint32_t)(k * BSTRIDE + g * 8) * 2, sp);
        }
        CP_COMMIT();
    }

    for (int c = 0; c < NC; c++) {
        const int buf = c & 1;
        #pragma unroll
        for (int it = 0; it < 8; it++) {
            int r = it * 16 + (tid >> 4);
            int f = tid & 15;
            uint2 hh, ll;
            split4(Ra[it], hh, ll);
            uint32_t off = smA + buf * ABUF + (uint32_t)(r * ASTRIDE + f * 4) * 2;
            STS_V2(off, hh.x, hh.y);
            STS_V2(off + APLANE, ll.x, ll.y);
        }
        if (c + 1 < NC) prefA<MODE>(Ra, c + 1, rowBase, M, A, aux, aux2, sI, dI, tid, K);
        CP_WAIT0();
        __syncthreads();
        if (c + 1 < NC) {
            #pragma unroll
            for (int it = 0; it < BTOT / 256; it++) {
                int i = it * 256 + tid;
                int plane = i / (64 * GRAN);
                int rem   = i % (64 * GRAN);
                int k = rem / GRAN, g = rem % GRAN;
                const __nv_bfloat16* sp = (plane ? Blo : Bhi)
                    + (size_t)(c + 1) * 64 * Nfull + (size_t)k * Nfull + colBase + g * 8;
                CP_ASYNC16(smB + (1 - buf) * BBUF + plane * BPLANE
                           + (uint32_t)(k * BSTRIDE + g * 8) * 2, sp);
            }
            CP_COMMIT();
        }

        #pragma unroll
        for (int ks = 0; ks < 4; ks++) {
            uint32_t Ah[MT][4], Al[MT][4];
            #pragma unroll
            for (int mt = 0; mt < MT; mt++) {
                uint32_t addr = smA + buf * ABUF
                    + (uint32_t)((warp_m * WTM + mt * 16 + (lane & 15)) * ASTRIDE
                                 + ks * 16 + (lane >> 4) * 8) * 2;
                ldsm_x4(Ah[mt], addr);
                ldsm_x4(Al[mt], addr + APLANE);
            }
            uint32_t Bh[NT / 2][4], Bl[NT / 2][4];
            #pragma unroll
            for (int np = 0; np < NT / 2; np++) {
                uint32_t addr = smB + buf * BBUF
                    + (uint32_t)((ks * 16 + (lane & 15)) * BSTRIDE
                                 + warp_n * WTN + np * 16 + (lane >> 4) * 8) * 2;
                ldsm_x4t(Bh[np], addr);
                ldsm_x4t(Bl[np], addr + BPLANE);
            }
            #pragma unroll
            for (int mt = 0; mt < MT; mt++)
                #pragma unroll
                for (int nt = 0; nt < NT; nt++) {
                    const uint32_t* bh = &Bh[nt >> 1][(nt & 1) * 2];
                    const uint32_t* bl = &Bl[nt >> 1][(nt & 1) * 2];
                    mma16816(acc[mt][nt], Ah[mt], bh);
                    mma16816(acc[mt][nt], Ah[mt], bl);
                    mma16816(acc[mt][nt], Al[mt], bh);
                }
        }
    }

    // ---- epilogue ----
    #pragma unroll
    for (int nt = 0; nt < NT; nt++) {
        int n = colBase + warp_n * WTN + nt * 8 + (lane & 3) * 2;
        float2 bb = *reinterpret_cast<const float2*>(bias + n);
        #pragma unroll
        for (int mt = 0; mt < MT; mt++) {
            #pragma unroll
            for (int half = 0; half < 2; half++) {
                int row = rowBase + warp_m * WTM + mt * 16 + (lane >> 2) + half * 8;
                if (row < M) {
                    float vx = acc[mt][nt][half * 2 + 0] + bb.x;
                    float vy = acc[mt][nt][half * 2 + 1] + bb.y;
                    size_t off = (size_t)row * Nfull + n;
                    if (HAS_RES) {
                        float2 rr = *reinterpret_cast<const float2*>(res + off);
                        vx += rr.x; vy += rr.y;
                    }
                    if (RELU) { vx = fmaxf(vx, 0.f); vy = fmaxf(vy, 0.f); }
                    float2 o; o.x = vx; o.y = vy;
                    *reinterpret_cast<float2*>(C + off) = o;
                    if (SCAT) {
                        int dd = idx2[row];
                        atomicAdd(scat + (size_t)dd * Nfull + n,     vx);
                        atomicAdd(scat + (size_t)dd * Nfull + n + 1, vy);
                    }
                }
            }
        }
    }
}

// ---------------- weight split ----------------
__global__ void wsplit(const float* __restrict__ w, __nv_bfloat16* __restrict__ hi,
                       __nv_bfloat16* __restrict__ lo, int total)
{
    int i = blockIdx.x * blockDim.x + threadIdx.x;
    if (i >= total) return;
    float v = w[i];
    __nv_bfloat16 h = __float2bfloat16_rn(v);
    hi[i] = h;
    lo[i] = __float2bfloat16_rn(v - __bfloat162float(h));
}

// =====================================================================
//  SIMT fp32 GEMM (encoder MLP1, embedder, decoder MLP2)
// =====================================================================
template<int BM, int BN, int BK, int TM, int TN>
__global__ void __launch_bounds__(256)
sgemm_bias(const float* __restrict__ A, int lda,
           const float* __restrict__ W,
           const float* __restrict__ bias,
           const float* res, float* C,
           int M, int N, int K, int doRelu)
{
    constexpr int GN      = TN / 4;
    constexpr int CSTRIDE = BN / GN;
    constexpr int NTC     = BN / TN;
    constexpr int THREADS = (BM / TM) * NTC;
    static_assert(THREADS == 256, "expect 256 threads");
    static_assert(BK == 16 && THREADS == BM * 2, "A loader mapping");

    __shared__ float As[BK][BM + 4];
    __shared__ float Bs[BK][BN];

    const int tid  = threadIdx.x;
    const int tcol = tid % NTC;
    const int trow = tid / NTC;
    const int rowBase = blockIdx.y * BM;
    const int colBase = blockIdx.x * BN;

    float acc[TM][TN];
    #pragma unroll
    for (int i = 0; i < TM; i++)
        #pragma unroll
        for (int j = 0; j < TN; j++) acc[i][j] = 0.f;

    const int am = tid >> 1;
    const int ah = (tid & 1) * 8;

    for (int k0 = 0; k0 < K; k0 += BK) {
        {
            const int gm = rowBase + am;
            const bool mok = (gm < M);
            const float* Arow = A + (size_t)gm * lda + (k0 + ah);
            #pragma unroll
            for (int i = 0; i < 8; i++) {
                int gk = k0 + ah + i;
                As[ah + i][am] = (mok && gk < K) ? Arow[i] : 0.f;
            }
        }
        #pragma unroll
        for (int it = 0; it < (BK * BN) / THREADS; it++) {
            int idx = tid + it * THREADS;
            int k = idx / BN, n = idx % BN;
            int gk = k0 + k, gn = colBase + n;
            Bs[k][n] = (gk < K && gn < N) ? W[(size_t)gk * N + gn] : 0.f;
        }
        __syncthreads();

        #pragma unroll
        for (int k = 0; k < BK; k++) {
            float ra[TM], rb[TN];
            #pragma unroll
            for (int i = 0; i < TM; i++) ra[i] = As[k][trow * TM + i];
            #pragma unroll
            for (int cg = 0; cg < GN; cg++)
                #pragma unroll
                for (int j = 0; j < 4; j++)
                    rb[cg * 4 + j] = Bs[k][cg * CSTRIDE + tcol * 4 + j];
            #pragma unroll
            for (int i = 0; i < TM; i++)
                #pragma unroll
                for (int j = 0; j < TN; j++)
                    acc[i][j] = fmaf(ra[i], rb[j], acc[i][j]);
        }
        __syncthreads();
    }

    #pragma unroll
    for (int i = 0; i < TM; i++) {
        int gm = rowBase + trow * TM + i;
        if (gm >= M) continue;
        #pragma unroll
        for (int cg = 0; cg < GN; cg++) {
            #pragma unroll
            for (int j = 0; j < 4; j++) {
                int gn = colBase + cg * CSTRIDE + tcol * 4 + j;
                if (gn >= N) continue;
                float v = acc[i][cg * 4 + j] + bias[gn];
                if (doRelu) v = fmaxf(v, 0.f);
                size_t off = (size_t)gm * N + gn;
                if (res) v += res[off];
                C[off] = v;
            }
        }
    }
}

// ---------------- builders ----------------
__global__ void build_encin(const float* __restrict__ xc, const float* __restrict__ xp,
                            const float* __restrict__ geo, const int* __restrict__ g2m,
                            float* __restrict__ out)
{
    int idx = blockIdx.x * blockDim.x + threadIdx.x;
    const int total = NBATCH * NMESH * ENC_LDA;
    if (idx >= total) return;
    int row = idx / ENC_LDA;
    int c   = idx - row * ENC_LDA;
    int b   = row / NMESH;
    int m   = row - b * NMESH;
    float v = 0.f;
    if (c < NV)            v = xc[((size_t)b * NGRID + g2m[m]) * NV + c];
    else if (c < 2 * NV)   v = xp[((size_t)b * NGRID + g2m[m]) * NV + (c - NV)];
    else if (c < ENC_IN)   v = geo[m * 7 + (c - 2 * NV)];
    out[idx] = v;
}

// ---------------- launcher ----------------
static inline dim3 gemm_grid(int M, int N, int BM, int BN) {
    return dim3((unsigned)((N + BN - 1) / BN), (unsigned)((M + BM - 1) / BM));
}

extern "C" void kernel_launch(void* const* d_in, const int* in_sizes, int n_in,
                              void* d_out, int out_size)
{
    const float* xc     = (const float*)d_in[0];
    const float* xp     = (const float*)d_in[1];
    const float* geo    = (const float*)d_in[2];
    const float* redge  = (const float*)d_in[3];
    const int*   eidx   = (const int*)  d_in[4];
    const int*   g2m    = (const int*)  d_in[5];
    const int*   m2g    = (const int*)  d_in[6];
    const float* enc_w1 = (const float*)d_in[7];
    const float* enc_b1 = (const float*)d_in[8];
    const float* enc_w2 = (const float*)d_in[9];
    const float* enc_b2 = (const float*)d_in[10];
    const float* eme_w1 = (const float*)d_in[11];
    const float* eme_b1 = (const float*)d_in[12];
    const float* eme_w2 = (const float*)d_in[13];
    const float* eme_b2 = (const float*)d_in[14];
    const float* pe_w1  = (const float*)d_in[15];
    const float* pe_b1  = (const float*)d_in[16];
    const float* pe_w2  = (const float*)d_in[17];
    const float* pe_b2  = (const float*)d_in[18];
    const float* pn_w1  = (const float*)d_in[19];
    const float* pn_b1  = (const float*)d_in[20];
    const float* pn_w2  = (const float*)d_in[21];
    const float* pn_b2  = (const float*)d_in[22];
    const float* dec_w1 = (const float*)d_in[23];
    const float* dec_b1 = (const float*)d_in[24];
    const float* dec_w2 = (const float*)d_in[25];
    const float* dec_b2 = (const float*)d_in[26];
    float* out = (float*)d_out;

    float *encin, *x, *e, *e0, *h, *agg, *xs, *xd, *zeros;
    __nv_bfloat16 *pe1hi,*pe1lo,*pe2hi,*pe2lo,*pn1hi,*pn1lo,*pn2hi,*pn2lo,*dc1hi,*dc1lo,*en2hi,*en2lo;
    cudaGetSymbolAddress((void**)&encin, g_encin);
    cudaGetSymbolAddress((void**)&x,     g_x);
    cudaGetSymbolAddress((void**)&e,     g_e);
    cudaGetSymbolAddress((void**)&e0,    g_e0);
    cudaGetSymbolAddress((void**)&h,     g_h);
    cudaGetSymbolAddress((void**)&agg,   g_agg);
    cudaGetSymbolAddress((void**)&xs,    g_xs);
    cudaGetSymbolAddress((void**)&xd,    g_xd);
    cudaGetSymbolAddress((void**)&zeros, g_zeros);
    cudaGetSymbolAddress((void**)&pe1hi, g_pe1hi);
    cudaGetSymbolAddress((void**)&pe1lo, g_pe1lo);
    cudaGetSymbolAddress((void**)&pe2hi, g_pe2hi);
    cudaGetSymbolAddress((void**)&pe2lo, g_pe2lo);
    cudaGetSymbolAddress((void**)&pn1hi, g_pn1hi);
    cudaGetSymbolAddress((void**)&pn1lo, g_pn1lo);
    cudaGetSymbolAddress((void**)&pn2hi, g_pn2hi);
    cudaGetSymbolAddress((void**)&pn2lo, g_pn2lo);
    cudaGetSymbolAddress((void**)&dc1hi, g_dc1hi);
    cudaGetSymbolAddress((void**)&dc1lo, g_dc1lo);
    cudaGetSymbolAddress((void**)&en2hi, g_en2hi);
    cudaGetSymbolAddress((void**)&en2lo, g_en2lo);

    const int* src = eidx;
    const int* dst = eidx + NEDGE;

    constexpr int ASM    = 2 * (2 * 128 * 72 * 2);   // 73728
    constexpr int BSM128 = 2 * (2 * 64 * 136 * 2);   // 69632
    constexpr int BSM64  = 2 * (2 * 64 * 72 * 2);    // 36864
    constexpr int SM128  = ASM + BSM128;             // 143360
    constexpr int SM64   = ASM + BSM64;              // 110592

    cudaFuncSetAttribute((const void*)mma_gemm<128,4,8,0,false,false,false>,
                         cudaFuncAttributeMaxDynamicSharedMemorySize, SM128);
    cudaFuncSetAttribute((const void*)mma_gemm<128,4,8,0,false,true,false>,
                         cudaFuncAttributeMaxDynamicSharedMemorySize, SM128);
    cudaFuncSetAttribute((const void*)mma_gemm<128,4,5,2,true,false,false>,
                         cudaFuncAttributeMaxDynamicSharedMemorySize, SM128);
    cudaFuncSetAttribute((const void*)mma_gemm<128,4,4,3,true,false,false>,
                         cudaFuncAttributeMaxDynamicSharedMemorySize, SM128);
    cudaFuncSetAttribute((const void*)mma_gemm<128,4,4,0,false,false,false>,
                         cudaFuncAttributeMaxDynamicSharedMemorySize, SM128);
    cudaFuncSetAttribute((const void*)mma_gemm<128,4,1,0,false,false,false>,
                         cudaFuncAttributeMaxDynamicSharedMemorySize, SM128);
    cudaFuncSetAttribute((const void*)mma_gemm<64,2,8,1,false,true,true>,
                         cudaFuncAttributeMaxDynamicSharedMemorySize, SM64);

    // ---------- weight split ----------
    { int t = NLAYERS*576*HIDD;   wsplit<<<(t+255)/256,256>>>(pe_w1, pe1hi, pe1lo, t); }
    { int t = NLAYERS*HIDD*EDGE_D;wsplit<<<(t+255)/256,256>>>(pe_w2, pe2hi, pe2lo, t); }
    { int t = NLAYERS*320*HIDD;   wsplit<<<(t+255)/256,256>>>(pn_w1, pn1hi, pn1lo, t); }
    { int t = NLAYERS*HIDD*NODE_D;wsplit<<<(t+255)/256,256>>>(pn_w2, pn2hi, pn2lo, t); }
    { int t = NODE_D*HIDD;        wsplit<<<(t+255)/256,256>>>(dec_w1, dc1hi, dc1lo, t); }
    { int t = HIDD*NODE_D;        wsplit<<<(t+255)/256,256>>>(enc_w2, en2hi, en2lo, t); }

    // ---------- encoder ----------
    {
        int total = NBATCH * NMESH * ENC_LDA;
        build_encin<<<(total + 255) / 256, 256>>>(xc, xp, geo, g2m, encin);
    }
    sgemm_bias<128,128,16,8,8><<<gemm_grid(NBATCH*NMESH, HIDD, 128, 128), 256>>>(
        encin, ENC_LDA, enc_w1, enc_b1, nullptr, h, NBATCH*NMESH, HIDD, ENC_IN, 1);
    mma_gemm<128,4,8,0,false,false,false><<<dim3(2, (NBATCH*NMESH + 127)/128), 256, SM128>>>(
        h, nullptr, nullptr, nullptr, nullptr, en2hi, en2lo, enc_b2, nullptr, x,
        nullptr, NBATCH*NMESH, NODE_D);

    // ---------- edge embedder ----------
    sgemm_bias<128,64,16,8,4><<<gemm_grid(NEDGE, EDGE_D, 128, 64), 256>>>(
        redge, 4, eme_w1, eme_b1, nullptr, h, NEDGE, EDGE_D, 4, 1);
    sgemm_bias<128,64,16,8,4><<<gemm_grid(NEDGE, EDGE_D, 128, 64), 256>>>(
        h, EDGE_D, eme_w2, eme_b2, nullptr, e0, NEDGE, EDGE_D, EDGE_D, 0);

    // ---------- GNN layers ----------
    for (int b = 0; b < NBATCH; b++) {
        float* xb = x + (size_t)b * NMESH * NODE_D;
        for (int l = 0; l < NLAYERS; l++) {
            const float* ein = (l == 0) ? e0 : e;
            const size_t w1off = (size_t)l * 576 * HIDD;

            // xs = x @ Wsrc (rows 64..319 of pe_w1), zero bias
            mma_gemm<128,4,4,0,false,false,false><<<dim3(4, (NMESH+127)/128), 256, SM128>>>(
                xb, nullptr, nullptr, nullptr, nullptr,
                pe1hi + w1off + (size_t)64*HIDD, pe1lo + w1off + (size_t)64*HIDD,
                zeros, nullptr, xs, nullptr, NMESH, HIDD);
            // xd = x @ Wdst (rows 320..575), zero bias
            mma_gemm<128,4,4,0,false,false,false><<<dim3(4, (NMESH+127)/128), 256, SM128>>>(
                xb, nullptr, nullptr, nullptr, nullptr,
                pe1hi + w1off + (size_t)320*HIDD, pe1lo + w1off + (size_t)320*HIDD,
                zeros, nullptr, xd, nullptr, NMESH, HIDD);
            // eWb = e @ We (rows 0..63) + b1
            mma_gemm<128,4,1,0,false,false,false><<<dim3(4, NEDGE/128), 256, SM128>>>(
                ein, nullptr, nullptr, nullptr, nullptr,
                pe1hi + w1off, pe1lo + w1off,
                pe_b1 + (size_t)l*HIDD, nullptr, h, nullptr, NEDGE, HIDD);

            cudaMemsetAsync(agg, 0, (size_t)NMESH * EDGE_D * sizeof(float), 0);

            // edge MLP2 with fused combine-gather-relu A and fused scatter-add:
            // e = ein + relu(eWb + xs[src] + xd[dst]) @ W2 + b2 ; agg += e
            mma_gemm<64,2,8,1,false,true,true><<<dim3(1, NEDGE/128), 256, SM64>>>(
                h, xs, xd, src, dst,
                pe2hi + (size_t)l*HIDD*EDGE_D, pe2lo + (size_t)l*HIDD*EDGE_D,
                pe_b2 + (size_t)l*EDGE_D, ein, e, agg, NEDGE, EDGE_D);

            // node MLP1: [x | agg] @ W1 + b, relu
            mma_gemm<128,4,5,2,true,false,false><<<dim3(4, (NMESH+127)/128), 256, SM128>>>(
                xb, agg, nullptr, nullptr, nullptr,
                pn1hi + (size_t)l*320*HIDD, pn1lo + (size_t)l*320*HIDD,
                pn_b1 + (size_t)l*HIDD, nullptr, h, nullptr, NMESH, HIDD);
            // node MLP2: h @ W2 + b + x (in place)
            mma_gemm<128,4,8,0,false,true,false><<<dim3(2, (NMESH+127)/128), 256, SM128>>>(
                h, nullptr, nullptr, nullptr, nullptr,
                pn2hi + (size_t)l*HIDD*NODE_D, pn2lo + (size_t)l*HIDD*NODE_D,
                pn_b2 + (size_t)l*NODE_D, xb, xb, nullptr, NMESH, NODE_D);
        }
    }

    // ---------- decoder ----------
    for (int b = 0; b < NBATCH; b++) {
        mma_gemm<128,4,4,3,true,false,false><<<dim3(4, (NGRID+127)/128), 256, SM128>>>(
            x + (size_t)b*NMESH*NODE_D, nullptr, nullptr, m2g, nullptr,
            dc1hi, dc1lo, dec_b1, nullptr,
            h + (size_t)b*NGRID*HIDD, nullptr, NGRID, HIDD);
    }
    sgemm_bias<128,64,16,8,4><<<gemm_grid(NBATCH*NGRID, NV, 128, 64), 256>>>(
        h, HIDD, dec_w2, dec_b2, nullptr, out, NBATCH*NGRID, NV, HIDD, 0);
}

// round 6
// speedup vs baseline: 8.5052x; 1.3498x over previous
#include <cuda_runtime.h>
#include <cuda_bf16.h>
#include <cstdint>

// ---------------- problem constants ----------------
#define NLAT   181
#define NLON   360
#define NV     78
#define NGRID  (NLAT*NLON)      // 65160
#define NBATCH 2
#define NMESH  10242
#define NEDGE  163840
#define NODE_D 256
#define EDGE_D 64
#define HIDD   512
#define NLAYERS 16
#define ENC_IN  163
#define ENC_LDA 164

// ---------------- device scratch ----------------
__device__ float g_encin[(size_t)NBATCH*NMESH*ENC_LDA];
__device__ float g_x    [(size_t)NBATCH*NMESH*NODE_D];
__device__ float g_e    [(size_t)NEDGE*EDGE_D];
__device__ float g_e0   [(size_t)NEDGE*EDGE_D];
__device__ float g_h    [(size_t)NEDGE*HIDD];
__device__ float g_agg  [(size_t)NMESH*EDGE_D];
__device__ float g_xsd  [(size_t)NMESH*1024];        // [xs | xd] merged
__device__ float g_zeros[1024];
__device__ float g_dcb2p[80];                        // padded dec_b2
// bf16 hi/lo split weights
__device__ __nv_bfloat16 g_pe1hi[(size_t)NLAYERS*576*HIDD];
__device__ __nv_bfloat16 g_pe1lo[(size_t)NLAYERS*576*HIDD];
__device__ __nv_bfloat16 g_wsdhi[(size_t)NLAYERS*256*1024];  // repacked [Wsrc|Wdst]
__device__ __nv_bfloat16 g_wsdlo[(size_t)NLAYERS*256*1024];
__device__ __nv_bfloat16 g_pe2hi[(size_t)NLAYERS*HIDD*EDGE_D];
__device__ __nv_bfloat16 g_pe2lo[(size_t)NLAYERS*HIDD*EDGE_D];
__device__ __nv_bfloat16 g_pn1hi[(size_t)NLAYERS*320*HIDD];
__device__ __nv_bfloat16 g_pn1lo[(size_t)NLAYERS*320*HIDD];
__device__ __nv_bfloat16 g_pn2hi[(size_t)NLAYERS*HIDD*NODE_D];
__device__ __nv_bfloat16 g_pn2lo[(size_t)NLAYERS*HIDD*NODE_D];
__device__ __nv_bfloat16 g_dc1hi[(size_t)NODE_D*HIDD];
__device__ __nv_bfloat16 g_dc1lo[(size_t)NODE_D*HIDD];
__device__ __nv_bfloat16 g_dc2hi[(size_t)HIDD*80];   // padded dec_w2
__device__ __nv_bfloat16 g_dc2lo[(size_t)HIDD*80];
__device__ __nv_bfloat16 g_en2hi[(size_t)HIDD*NODE_D];
__device__ __nv_bfloat16 g_en2lo[(size_t)HIDD*NODE_D];

// ---------------- asm helpers ----------------
__device__ __forceinline__ void ldsm_x4(uint32_t* r, uint32_t addr) {
    asm volatile("ldmatrix.sync.aligned.m8n8.x4.shared.b16 {%0,%1,%2,%3}, [%4];"
        : "=r"(r[0]), "=r"(r[1]), "=r"(r[2]), "=r"(r[3]) : "r"(addr));
}
__device__ __forceinline__ void ldsm_x4t(uint32_t* r, uint32_t addr) {
    asm volatile("ldmatrix.sync.aligned.m8n8.x4.trans.shared.b16 {%0,%1,%2,%3}, [%4];"
        : "=r"(r[0]), "=r"(r[1]), "=r"(r[2]), "=r"(r[3]) : "r"(addr));
}
__device__ __forceinline__ void mma16816(float* d, const uint32_t* a, const uint32_t* b) {
    asm volatile("mma.sync.aligned.m16n8k16.row.col.f32.bf16.bf16.f32 "
        "{%0,%1,%2,%3}, {%4,%5,%6,%7}, {%8,%9}, {%0,%1,%2,%3};"
        : "+f"(d[0]), "+f"(d[1]), "+f"(d[2]), "+f"(d[3])
        : "r"(a[0]), "r"(a[1]), "r"(a[2]), "r"(a[3]), "r"(b[0]), "r"(b[1]));
}
__device__ __forceinline__ uint32_t smem_u32(const void* p) {
    uint32_t a;
    asm("{ .reg .u64 t; cvta.to.shared.u64 t, %1; cvt.u32.u64 %0, t; }" : "=r"(a) : "l"(p));
    return a;
}
#define CP_ASYNC16(dst, src) \
    asm volatile("cp.async.cg.shared.global [%0], [%1], 16;" :: "r"(dst), "l"(src))
#define CP_COMMIT() asm volatile("cp.async.commit_group;" ::: "memory")
#define CP_WAIT0()  asm volatile("cp.async.wait_group 0;" ::: "memory")
#define STS_V2(addr, x, y) \
    asm volatile("st.shared.v2.u32 [%0], {%1,%2};" :: "r"(addr), "r"(x), "r"(y))
#define STS_U32(addr, x) \
    asm volatile("st.shared.u32 [%0], %1;" :: "r"(addr), "r"(x))

__device__ __forceinline__ void split4(float4 v, uint2& hh, uint2& ll) {
    __nv_bfloat16 h0 = __float2bfloat16_rn(v.x), h1 = __float2bfloat16_rn(v.y);
    __nv_bfloat16 h2 = __float2bfloat16_rn(v.z), h3 = __float2bfloat16_rn(v.w);
    __nv_bfloat16 g0 = __float2bfloat16_rn(v.x - __bfloat162float(h0));
    __nv_bfloat16 g1 = __float2bfloat16_rn(v.y - __bfloat162float(h1));
    __nv_bfloat16 g2 = __float2bfloat16_rn(v.z - __bfloat162float(h2));
    __nv_bfloat16 g3 = __float2bfloat16_rn(v.w - __bfloat162float(h3));
    hh.x = (uint32_t)__bfloat16_as_ushort(h0) | ((uint32_t)__bfloat16_as_ushort(h1) << 16);
    hh.y = (uint32_t)__bfloat16_as_ushort(h2) | ((uint32_t)__bfloat16_as_ushort(h3) << 16);
    ll.x = (uint32_t)__bfloat16_as_ushort(g0) | ((uint32_t)__bfloat16_as_ushort(g1) << 16);
    ll.y = (uint32_t)__bfloat16_as_ushort(g2) | ((uint32_t)__bfloat16_as_ushort(g3) << 16);
}
__device__ __forceinline__ void split2(float vx, float vy, uint32_t& hp, uint32_t& lp) {
    __nv_bfloat16 hx = __float2bfloat16_rn(vx), hy = __float2bfloat16_rn(vy);
    __nv_bfloat16 lx = __float2bfloat16_rn(vx - __bfloat162float(hx));
    __nv_bfloat16 ly = __float2bfloat16_rn(vy - __bfloat162float(hy));
    hp = (uint32_t)__bfloat16_as_ushort(hx) | ((uint32_t)__bfloat16_as_ushort(hy) << 16);
    lp = (uint32_t)__bfloat16_as_ushort(lx) | ((uint32_t)__bfloat16_as_ushort(ly) << 16);
}

// ---------------- A-gather modes ----------------
// MODE 0: plain A[M][K]    MODE 2: [x(256)|agg(64)]    MODE 3: A[idx1[gr]][256]
template<int MODE>
__device__ __forceinline__ void prefA(float4 (&Ra)[8], int c, int rowBase, int M,
    const float* __restrict__ A, const float* __restrict__ aux,
    const int (&sI)[8], int tid, int K)
{
    const int f = tid & 15;
    #pragma unroll
    for (int it = 0; it < 8; it++) {
        int gr = rowBase + it * 16 + (tid >> 4);
        if (gr < M) {
            const float* p;
            if (MODE == 0)      p = A + (size_t)gr * K + c * 64;
            else if (MODE == 2) p = (c < 4) ? A + (size_t)gr * 256 + c * 64
                                            : aux + (size_t)gr * 64;
            else                p = A + (size_t)sI[it] * 256 + c * 64;
            Ra[it] = reinterpret_cast<const float4*>(p)[f];
        } else {
            Ra[it] = make_float4(0.f, 0.f, 0.f, 0.f);
        }
    }
}

// =====================================================================
//  HMMA GEMM: C[M x Nclip (pitch Cpitch)] = [res+] relu?(gather(A)@W + bias)
// =====================================================================
template<int BN, int WARPS_N, int NC, int MODE, bool RELU, bool HAS_RES>
__global__ void __launch_bounds__(256)
mma_gemm(const float* __restrict__ A, const float* __restrict__ aux,
         const int* __restrict__ idx1,
         const __nv_bfloat16* __restrict__ Bhi, const __nv_bfloat16* __restrict__ Blo,
         const float* __restrict__ bias, const float* res, float* C,
         int M, int Nfull, int Cpitch, int Nclip)
{
    constexpr int K       = NC * 64;
    constexpr int WARPS_M = 8 / WARPS_N;
    constexpr int WTM     = 128 / WARPS_M;
    constexpr int WTN     = BN / WARPS_N;
    constexpr int MT      = WTM / 16;
    constexpr int NT      = WTN / 8;
    constexpr int ASTRIDE = 72;
    constexpr int APLANE  = 128 * ASTRIDE * 2;
    constexpr int ABUF    = 2 * APLANE;
    constexpr int BSTRIDE = BN + 8;
    constexpr int BPLANE  = 64 * BSTRIDE * 2;
    constexpr int BBUF    = 2 * BPLANE;
    constexpr int GRAN    = BN / 8;
    constexpr int BTOT    = 2 * 64 * GRAN;

    extern __shared__ char sm[];
    const uint32_t smA = smem_u32(sm);
    const uint32_t smB = smA + 2 * ABUF;

    const int tid    = threadIdx.x;
    const int lane   = tid & 31;
    const int wid    = tid >> 5;
    const int warp_n = wid % WARPS_N;
    const int warp_m = wid / WARPS_N;
    const int rowBase = blockIdx.y * 128;
    const int colBase = blockIdx.x * BN;

    int sI[8];
    #pragma unroll
    for (int it = 0; it < 8; it++) {
        int gr = rowBase + it * 16 + (tid >> 4);
        int g  = (gr < M) ? gr : 0;
        sI[it] = (MODE == 3) ? idx1[g] : 0;
    }

    float acc[MT][NT][4];
    #pragma unroll
    for (int i = 0; i < MT; i++)
        #pragma unroll
        for (int j = 0; j < NT; j++)
            #pragma unroll
            for (int q = 0; q < 4; q++) acc[i][j][q] = 0.f;

    float4 Ra[8];
    prefA<MODE>(Ra, 0, rowBase, M, A, aux, sI, tid, K);

    {
        #pragma unroll
        for (int it = 0; it < BTOT / 256; it++) {
            int i = it * 256 + tid;
            int plane = i / (64 * GRAN);
            int rem   = i % (64 * GRAN);
            int k = rem / GRAN, g = rem % GRAN;
            const __nv_bfloat16* sp = (plane ? Blo : Bhi)
                + (size_t)k * Nfull + colBase + g * 8;
            CP_ASYNC16(smB + plane * BPLANE + (uint32_t)(k * BSTRIDE + g * 8) * 2, sp);
        }
        CP_COMMIT();
    }

    for (int c = 0; c < NC; c++) {
        const int buf = c & 1;
        #pragma unroll
        for (int it = 0; it < 8; it++) {
            int r = it * 16 + (tid >> 4);
            int f = tid & 15;
            uint2 hh, ll;
            split4(Ra[it], hh, ll);
            uint32_t off = smA + buf * ABUF + (uint32_t)(r * ASTRIDE + f * 4) * 2;
            STS_V2(off, hh.x, hh.y);
            STS_V2(off + APLANE, ll.x, ll.y);
        }
        if (c + 1 < NC) prefA<MODE>(Ra, c + 1, rowBase, M, A, aux, sI, tid, K);
        CP_WAIT0();
        __syncthreads();
        if (c + 1 < NC) {
            #pragma unroll
            for (int it = 0; it < BTOT / 256; it++) {
                int i = it * 256 + tid;
                int plane = i / (64 * GRAN);
                int rem   = i % (64 * GRAN);
                int k = rem / GRAN, g = rem % GRAN;
                const __nv_bfloat16* sp = (plane ? Blo : Bhi)
                    + (size_t)(c + 1) * 64 * Nfull + (size_t)k * Nfull + colBase + g * 8;
                CP_ASYNC16(smB + (1 - buf) * BBUF + plane * BPLANE
                           + (uint32_t)(k * BSTRIDE + g * 8) * 2, sp);
            }
            CP_COMMIT();
        }

        #pragma unroll
        for (int ks = 0; ks < 4; ks++) {
            uint32_t Ah[MT][4], Al[MT][4];
            #pragma unroll
            for (int mt = 0; mt < MT; mt++) {
                uint32_t addr = smA + buf * ABUF
                    + (uint32_t)((warp_m * WTM + mt * 16 + (lane & 15)) * ASTRIDE
                                 + ks * 16 + (lane >> 4) * 8) * 2;
                ldsm_x4(Ah[mt], addr);
                ldsm_x4(Al[mt], addr + APLANE);
            }
            uint32_t Bh[NT / 2][4], Bl[NT / 2][4];
            #pragma unroll
            for (int np = 0; np < NT / 2; np++) {
                uint32_t addr = smB + buf * BBUF
                    + (uint32_t)((ks * 16 + (lane & 15)) * BSTRIDE
                                 + warp_n * WTN + np * 16 + (lane >> 4) * 8) * 2;
                ldsm_x4t(Bh[np], addr);
                ldsm_x4t(Bl[np], addr + BPLANE);
            }
            #pragma unroll
            for (int mt = 0; mt < MT; mt++)
                #pragma unroll
                for (int nt = 0; nt < NT; nt++) {
                    const uint32_t* bh = &Bh[nt >> 1][(nt & 1) * 2];
                    const uint32_t* bl = &Bl[nt >> 1][(nt & 1) * 2];
                    mma16816(acc[mt][nt], Ah[mt], bh);
                    mma16816(acc[mt][nt], Ah[mt], bl);
                    mma16816(acc[mt][nt], Al[mt], bh);
                }
        }
    }

    #pragma unroll
    for (int nt = 0; nt < NT; nt++) {
        int n = colBase + warp_n * WTN + nt * 8 + (lane & 3) * 2;
        if (n >= Nclip) continue;
        float2 bb = *reinterpret_cast<const float2*>(bias + n);
        #pragma unroll
        for (int mt = 0; mt < MT; mt++) {
            #pragma unroll
            for (int half = 0; half < 2; half++) {
                int row = rowBase + warp_m * WTM + mt * 16 + (lane >> 2) + half * 8;
                if (row < M) {
                    float vx = acc[mt][nt][half * 2 + 0] + bb.x;
                    float vy = acc[mt][nt][half * 2 + 1] + bb.y;
                    size_t off = (size_t)row * Cpitch + n;
                    if (HAS_RES) {
                        float2 rr = *reinterpret_cast<const float2*>(res + off);
                        vx += rr.x; vy += rr.y;
                    }
                    if (RELU) { vx = fmaxf(vx, 0.f); vy = fmaxf(vy, 0.f); }
                    float2 o; o.x = vx; o.y = vy;
                    *reinterpret_cast<float2*>(C + off) = o;
                }
            }
        }
    }
}

// =====================================================================
//  Fused edge layer: per 128-edge CTA
//  hidden = relu(e@We + b1 + xs[src] + xd[dst])  (chunks of 128 cols, smem)
//  eout   = ein + hidden @ W2 + b2 ;  agg[dst] += eout   (atomics)
// =====================================================================
__global__ void __launch_bounds__(256)
fused_edge(const float* __restrict__ ein,
           const float* __restrict__ xsd,
           const int* __restrict__ src, const int* __restrict__ dst,
           const __nv_bfloat16* __restrict__ W1hi, const __nv_bfloat16* __restrict__ W1lo,
           const __nv_bfloat16* __restrict__ W2hi, const __nv_bfloat16* __restrict__ W2lo,
           const float* __restrict__ b1, const float* __restrict__ b2,
           float* __restrict__ eout, float* __restrict__ agg)
{
    constexpr int A_STR  = 72;
    constexpr int A_PL   = 128 * A_STR * 2;     // 18432
    constexpr int OFF_A  = 0;
    constexpr int B1_STR = 136;
    constexpr int B1_PL  = 64 * B1_STR * 2;     // 17408
    constexpr int OFF_B1 = 2 * A_PL;            // 36864
    constexpr int H_STR  = 136;
    constexpr int H_PL   = 128 * H_STR * 2;     // 34816
    constexpr int OFF_H  = OFF_B1 + 2 * B1_PL;  // 71680
    constexpr int B2_STR = 72;
    constexpr int B2_PL  = 128 * B2_STR * 2;    // 18432
    constexpr int OFF_B2 = OFF_H + 2 * H_PL;    // 141312; total 178176

    extern __shared__ char sm[];
    const uint32_t base = smem_u32(sm);

    const int tid  = threadIdx.x;
    const int lane = tid & 31;
    const int wid  = tid >> 5;
    const int warp_m = wid >> 1;       // 0..3
    const int warp_n = wid & 1;        // 0..1
    const int rowBase = blockIdx.x * 128;

    int sidx[2][2], didx[2][2];
    #pragma unroll
    for (int mt = 0; mt < 2; mt++)
        #pragma unroll
        for (int half = 0; half < 2; half++) {
            int g = rowBase + warp_m * 32 + mt * 16 + (lane >> 2) + half * 8;
            sidx[mt][half] = src[g];
            didx[mt][half] = dst[g];
        }

    // ---- load e tile (128 x 64 fp32) into A smem hi/lo ----
    {
        const float4* E4 = reinterpret_cast<const float4*>(ein + (size_t)rowBase * 64);
        #pragma unroll
        for (int it = 0; it < 8; it++) {
            int i = tid + it * 256;
            int r = i >> 4, f = i & 15;
            float4 v = E4[r * 16 + f];
            uint2 hh, ll;
            split4(v, hh, ll);
            uint32_t off = base + OFF_A + (uint32_t)(r * A_STR + f * 4) * 2;
            STS_V2(off, hh.x, hh.y);
            STS_V2(off + A_PL, ll.x, ll.y);
        }
    }

    float acc2[2][4][4];
    #pragma unroll
    for (int i = 0; i < 2; i++)
        #pragma unroll
        for (int j = 0; j < 4; j++)
            #pragma unroll
            for (int q = 0; q < 4; q++) acc2[i][j][q] = 0.f;

    for (int nc = 0; nc < 4; nc++) {
        __syncthreads();
        // B1 chunk: We[0:64][nc*128 : +128], hi+lo
        #pragma unroll
        for (int it = 0; it < 8; it++) {
            int i = tid + it * 256;
            int plane = i >> 10;
            int rem = i & 1023;
            int k = rem >> 4, g = rem & 15;
            const __nv_bfloat16* sp = (plane ? W1lo : W1hi)
                + (size_t)k * 512 + nc * 128 + g * 8;
            CP_ASYNC16(base + OFF_B1 + plane * B1_PL + (uint32_t)(k * B1_STR + g * 8) * 2, sp);
        }
        // B2 chunk: W2[nc*128 : +128][0:64], hi+lo
        #pragma unroll
        for (int it = 0; it < 8; it++) {
            int i = tid + it * 256;
            int plane = i >> 10;
            int rem = i & 1023;
            int k = rem >> 3, g = rem & 7;
            const __nv_bfloat16* sp = (plane ? W2lo : W2hi)
                + (size_t)(nc * 128 + k) * 64 + g * 8;
            CP_ASYNC16(base + OFF_B2 + plane * B2_PL + (uint32_t)(k * B2_STR + g * 8) * 2, sp);
        }
        CP_COMMIT();
        CP_WAIT0();
        __syncthreads();

        // ---- stage 1: acc1 = e @ We_chunk (128x128, K=64) ----
        float acc1[2][8][4];
        #pragma unroll
        for (int i = 0; i < 2; i++)
            #pragma unroll
            for (int j = 0; j < 8; j++)
                #pragma unroll
                for (int q = 0; q < 4; q++) acc1[i][j][q] = 0.f;

        #pragma unroll
        for (int ks = 0; ks < 4; ks++) {
            uint32_t Ah[2][4], Al[2][4];
            #pragma unroll
            for (int mt = 0; mt < 2; mt++) {
                uint32_t addr = base + OFF_A
                    + (uint32_t)((warp_m * 32 + mt * 16 + (lane & 15)) * A_STR
                                 + ks * 16 + (lane >> 4) * 8) * 2;
                ldsm_x4(Ah[mt], addr);
                ldsm_x4(Al[mt], addr + A_PL);
            }
            uint32_t Bh[4][4], Bl[4][4];
            #pragma unroll
            for (int np = 0; np < 4; np++) {
                uint32_t addr = base + OFF_B1
                    + (uint32_t)((ks * 16 + (lane & 15)) * B1_STR
                                 + warp_n * 64 + np * 16 + (lane >> 4) * 8) * 2;
                ldsm_x4t(Bh[np], addr);
                ldsm_x4t(Bl[np], addr + B1_PL);
            }
            #pragma unroll
            for (int mt = 0; mt < 2; mt++)
                #pragma unroll
                for (int nt = 0; nt < 8; nt++) {
                    const uint32_t* bh = &Bh[nt >> 1][(nt & 1) * 2];
                    const uint32_t* bl = &Bl[nt >> 1][(nt & 1) * 2];
                    mma16816(acc1[mt][nt], Ah[mt], bh);
                    mma16816(acc1[mt][nt], Ah[mt], bl);
                    mma16816(acc1[mt][nt], Al[mt], bh);
                }
        }

        // ---- stage1 epilogue: + b1 + xs[src] + xd[dst], relu, -> H smem ----
        #pragma unroll
        for (int nt = 0; nt < 8; nt++) {
            int col  = warp_n * 64 + nt * 8 + (lane & 3) * 2;
            int gcol = nc * 128 + col;
            float2 bb = *reinterpret_cast<const float2*>(b1 + gcol);
            #pragma unroll
            for (int mt = 0; mt < 2; mt++) {
                #pragma unroll
                for (int half = 0; half < 2; half++) {
                    int row_l = warp_m * 32 + mt * 16 + (lane >> 2) + half * 8;
                    float2 sv = *reinterpret_cast<const float2*>(
                        xsd + (size_t)sidx[mt][half] * 1024 + gcol);
                    float2 dv = *reinterpret_cast<const float2*>(
                        xsd + (size_t)didx[mt][half] * 1024 + 512 + gcol);
                    float vx = fmaxf(acc1[mt][nt][half * 2 + 0] + bb.x + sv.x + dv.x, 0.f);
                    float vy = fmaxf(acc1[mt][nt][half * 2 + 1] + bb.y + sv.y + dv.y, 0.f);
                    uint32_t hp, lp;
                    split2(vx, vy, hp, lp);
                    uint32_t off = base + OFF_H + (uint32_t)(row_l * H_STR + col) * 2;
                    STS_U32(off, hp);
                    STS_U32(off + H_PL, lp);
                }
            }
        }
        __syncthreads();

        // ---- stage 2: acc2 += hidden_chunk @ W2_chunk (K=128) ----
        #pragma unroll
        for (int ks = 0; ks < 8; ks++) {
            uint32_t Ah[2][4], Al[2][4];
            #pragma unroll
            for (int mt = 0; mt < 2; mt++) {
                uint32_t addr = base + OFF_H
                    + (uint32_t)((warp_m * 32 + mt * 16 + (lane & 15)) * H_STR
                                 + ks * 16 + (lane >> 4) * 8) * 2;
                ldsm_x4(Ah[mt], addr);
                ldsm_x4(Al[mt], addr + H_PL);
            }
            uint32_t Bh[2][4], Bl[2][4];
            #pragma unroll
            for (int np = 0; np < 2; np++) {
                uint32_t addr = base + OFF_B2
                    + (uint32_t)((ks * 16 + (lane & 15)) * B2_STR
                                 + warp_n * 32 + np * 16 + (lane >> 4) * 8) * 2;
                ldsm_x4t(Bh[np], addr);
                ldsm_x4t(Bl[np], addr + B2_PL);
            }
            #pragma unroll
            for (int mt = 0; mt < 2; mt++)
                #pragma unroll
                for (int nt = 0; nt < 4; nt++) {
                    const uint32_t* bh = &Bh[nt >> 1][(nt & 1) * 2];
                    const uint32_t* bl = &Bl[nt >> 1][(nt & 1) * 2];
                    mma16816(acc2[mt][nt], Ah[mt], bh);
                    mma16816(acc2[mt][nt], Ah[mt], bl);
                    mma16816(acc2[mt][nt], Al[mt], bh);
                }
        }
    }

    // ---- final epilogue: + b2 + ein residual, write e, scatter-add agg ----
    #pragma unroll
    for (int nt = 0; nt < 4; nt++) {
        int n = warp_n * 32 + nt * 8 + (lane & 3) * 2;
        float2 bb = *reinterpret_cast<const float2*>(b2 + n);
        #pragma unroll
        for (int mt = 0; mt < 2; mt++) {
            #pragma unroll
            for (int half = 0; half < 2; half++) {
                int row_l = warp_m * 32 + mt * 16 + (lane >> 2) + half * 8;
                size_t off = (size_t)(rowBase + row_l) * 64 + n;
                float2 rr = *reinterpret_cast<const float2*>(ein + off);
                float vx = acc2[mt][nt][half * 2 + 0] + bb.x + rr.x;
                float vy = acc2[mt][nt][half * 2 + 1] + bb.y + rr.y;
                float2 o; o.x = vx; o.y = vy;
                *reinterpret_cast<float2*>(eout + off) = o;
                float* ap = agg + (size_t)didx[mt][half] * 64 + n;
                atomicAdd(ap,     vx);
                atomicAdd(ap + 1, vy);
            }
        }
    }
}

// ---------------- weight prep kernels ----------------
__global__ void wsplit(const float* __restrict__ w, __nv_bfloat16* __restrict__ hi,
                       __nv_bfloat16* __restrict__ lo, int total)
{
    int i = blockIdx.x * blockDim.x + threadIdx.x;
    if (i >= total) return;
    float v = w[i];
    __nv_bfloat16 h = __float2bfloat16_rn(v);
    hi[i] = h;
    lo[i] = __float2bfloat16_rn(v - __bfloat162float(h));
}

// repack pe_w1 rows 64..575 into [L][256][1024]: cols 0-511 = Wsrc, 512-1023 = Wdst
__global__ void wsd_pack(const float* __restrict__ w, __nv_bfloat16* __restrict__ hi,
                         __nv_bfloat16* __restrict__ lo)
{
    int i = blockIdx.x * blockDim.x + threadIdx.x;
    const int total = NLAYERS * 256 * 1024;
    if (i >= total) return;
    int l = i >> 18;
    int rem = i & 262143;
    int r = rem >> 10;
    int n = rem & 1023;
    int srow = (n < 512) ? (64 + r) : (320 + r);
    int scol = n & 511;
    float v = w[(size_t)l * 576 * 512 + (size_t)srow * 512 + scol];
    __nv_bfloat16 h = __float2bfloat16_rn(v);
    hi[i] = h;
    lo[i] = __float2bfloat16_rn(v - __bfloat162float(h));
}

// pad dec_w2 [512][78] -> [512][80] split
__global__ void wpad80(const float* __restrict__ w, __nv_bfloat16* __restrict__ hi,
                       __nv_bfloat16* __restrict__ lo)
{
    int i = blockIdx.x * blockDim.x + threadIdx.x;
    if (i >= 512 * 80) return;
    int k = i / 80, n = i % 80;
    float v = (n < 78) ? w[k * 78 + n] : 0.f;
    __nv_bfloat16 h = __float2bfloat16_rn(v);
    hi[i] = h;
    lo[i] = __float2bfloat16_rn(v - __bfloat162float(h));
}
__global__ void bpad80(const float* __restrict__ b, float* __restrict__ o)
{
    int i = threadIdx.x;
    if (i < 80) o[i] = (i < 78) ? b[i] : 0.f;
}

// =====================================================================
//  SIMT fp32 GEMM (encoder MLP1, embedder)
// =====================================================================
template<int BM, int BN, int BK, int TM, int TN>
__global__ void __launch_bounds__(256)
sgemm_bias(const float* __restrict__ A, int lda,
           const float* __restrict__ W,
           const float* __restrict__ bias,
           const float* res, float* C,
           int M, int N, int K, int doRelu)
{
    constexpr int GN      = TN / 4;
    constexpr int CSTRIDE = BN / GN;
    constexpr int NTC     = BN / TN;
    constexpr int THREADS = (BM / TM) * NTC;
    static_assert(THREADS == 256, "expect 256 threads");
    static_assert(BK == 16 && THREADS == BM * 2, "A loader mapping");

    __shared__ float As[BK][BM + 4];
    __shared__ float Bs[BK][BN];

    const int tid  = threadIdx.x;
    const int tcol = tid % NTC;
    const int trow = tid / NTC;
    const int rowBase = blockIdx.y * BM;
    const int colBase = blockIdx.x * BN;

    float acc[TM][TN];
    #pragma unroll
    for (int i = 0; i < TM; i++)
        #pragma unroll
        for (int j = 0; j < TN; j++) acc[i][j] = 0.f;

    const int am = tid >> 1;
    const int ah = (tid & 1) * 8;

    for (int k0 = 0; k0 < K; k0 += BK) {
        {
            const int gm = rowBase + am;
            const bool mok = (gm < M);
            const float* Arow = A + (size_t)gm * lda + (k0 + ah);
            #pragma unroll
            for (int i = 0; i < 8; i++) {
                int gk = k0 + ah + i;
                As[ah + i][am] = (mok && gk < K) ? Arow[i] : 0.f;
            }
        }
        #pragma unroll
        for (int it = 0; it < (BK * BN) / THREADS; it++) {
            int idx = tid + it * THREADS;
            int k = idx / BN, n = idx % BN;
            int gk = k0 + k, gn = colBase + n;
            Bs[k][n] = (gk < K && gn < N) ? W[(size_t)gk * N + gn] : 0.f;
        }
        __syncthreads();

        #pragma unroll
        for (int k = 0; k < BK; k++) {
            float ra[TM], rb[TN];
            #pragma unroll
            for (int i = 0; i < TM; i++) ra[i] = As[k][trow * TM + i];
            #pragma unroll
            for (int cg = 0; cg < GN; cg++)
                #pragma unroll
                for (int j = 0; j < 4; j++)
                    rb[cg * 4 + j] = Bs[k][cg * CSTRIDE + tcol * 4 + j];
            #pragma unroll
            for (int i = 0; i < TM; i++)
                #pragma unroll
                for (int j = 0; j < TN; j++)
                    acc[i][j] = fmaf(ra[i], rb[j], acc[i][j]);
        }
        __syncthreads();
    }

    #pragma unroll
    for (int i = 0; i < TM; i++) {
        int gm = rowBase + trow * TM + i;
        if (gm >= M) continue;
        #pragma unroll
        for (int cg = 0; cg < GN; cg++) {
            #pragma unroll
            for (int j = 0; j < 4; j++) {
                int gn = colBase + cg * CSTRIDE + tcol * 4 + j;
                if (gn >= N) continue;
                float v = acc[i][cg * 4 + j] + bias[gn];
                if (doRelu) v = fmaxf(v, 0.f);
                size_t off = (size_t)gm * N + gn;
                if (res) v += res[off];
                C[off] = v;
            }
        }
    }
}

// ---------------- builders ----------------
__global__ void build_encin(const float* __restrict__ xc, const float* __restrict__ xp,
                            const float* __restrict__ geo, const int* __restrict__ g2m,
                            float* __restrict__ out)
{
    int idx = blockIdx.x * blockDim.x + threadIdx.x;
    const int total = NBATCH * NMESH * ENC_LDA;
    if (idx >= total) return;
    int row = idx / ENC_LDA;
    int c   = idx - row * ENC_LDA;
    int b   = row / NMESH;
    int m   = row - b * NMESH;
    float v = 0.f;
    if (c < NV)            v = xc[((size_t)b * NGRID + g2m[m]) * NV + c];
    else if (c < 2 * NV)   v = xp[((size_t)b * NGRID + g2m[m]) * NV + (c - NV)];
    else if (c < ENC_IN)   v = geo[m * 7 + (c - 2 * NV)];
    out[idx] = v;
}

// ---------------- launcher ----------------
static inline dim3 gemm_grid(int M, int N, int BM, int BN) {
    return dim3((unsigned)((N + BN - 1) / BN), (unsigned)((M + BM - 1) / BM));
}

extern "C" void kernel_launch(void* const* d_in, const int* in_sizes, int n_in,
                              void* d_out, int out_size)
{
    const float* xc     = (const float*)d_in[0];
    const float* xp     = (const float*)d_in[1];
    const float* geo    = (const float*)d_in[2];
    const float* redge  = (const float*)d_in[3];
    const int*   eidx   = (const int*)  d_in[4];
    const int*   g2m    = (const int*)  d_in[5];
    const int*   m2g    = (const int*)  d_in[6];
    const float* enc_w1 = (const float*)d_in[7];
    const float* enc_b1 = (const float*)d_in[8];
    const float* enc_w2 = (const float*)d_in[9];
    const float* enc_b2 = (const float*)d_in[10];
    const float* eme_w1 = (const float*)d_in[11];
    const float* eme_b1 = (const float*)d_in[12];
    const float* eme_w2 = (const float*)d_in[13];
    const float* eme_b2 = (const float*)d_in[14];
    const float* pe_w1  = (const float*)d_in[15];
    const float* pe_b1  = (const float*)d_in[16];
    const float* pe_w2  = (const float*)d_in[17];
    const float* pe_b2  = (const float*)d_in[18];
    const float* pn_w1  = (const float*)d_in[19];
    const float* pn_b1  = (const float*)d_in[20];
    const float* pn_w2  = (const float*)d_in[21];
    const float* pn_b2  = (const float*)d_in[22];
    const float* dec_w1 = (const float*)d_in[23];
    const float* dec_b1 = (const float*)d_in[24];
    const float* dec_w2 = (const float*)d_in[25];
    const float* dec_b2 = (const float*)d_in[26];
    float* out = (float*)d_out;

    float *encin, *x, *e, *e0, *h, *agg, *xsd, *zeros, *dcb2p;
    __nv_bfloat16 *pe1hi,*pe1lo,*wsdhi,*wsdlo,*pe2hi,*pe2lo,*pn1hi,*pn1lo,*pn2hi,*pn2lo;
    __nv_bfloat16 *dc1hi,*dc1lo,*dc2hi,*dc2lo,*en2hi,*en2lo;
    cudaGetSymbolAddress((void**)&encin, g_encin);
    cudaGetSymbolAddress((void**)&x,     g_x);
    cudaGetSymbolAddress((void**)&e,     g_e);
    cudaGetSymbolAddress((void**)&e0,    g_e0);
    cudaGetSymbolAddress((void**)&h,     g_h);
    cudaGetSymbolAddress((void**)&agg,   g_agg);
    cudaGetSymbolAddress((void**)&xsd,   g_xsd);
    cudaGetSymbolAddress((void**)&zeros, g_zeros);
    cudaGetSymbolAddress((void**)&dcb2p, g_dcb2p);
    cudaGetSymbolAddress((void**)&pe1hi, g_pe1hi);
    cudaGetSymbolAddress((void**)&pe1lo, g_pe1lo);
    cudaGetSymbolAddress((void**)&wsdhi, g_wsdhi);
    cudaGetSymbolAddress((void**)&wsdlo, g_wsdlo);
    cudaGetSymbolAddress((void**)&pe2hi, g_pe2hi);
    cudaGetSymbolAddress((void**)&pe2lo, g_pe2lo);
    cudaGetSymbolAddress((void**)&pn1hi, g_pn1hi);
    cudaGetSymbolAddress((void**)&pn1lo, g_pn1lo);
    cudaGetSymbolAddress((void**)&pn2hi, g_pn2hi);
    cudaGetSymbolAddress((void**)&pn2lo, g_pn2lo);
    cudaGetSymbolAddress((void**)&dc1hi, g_dc1hi);
    cudaGetSymbolAddress((void**)&dc1lo, g_dc1lo);
    cudaGetSymbolAddress((void**)&dc2hi, g_dc2hi);
    cudaGetSymbolAddress((void**)&dc2lo, g_dc2lo);
    cudaGetSymbolAddress((void**)&en2hi, g_en2hi);
    cudaGetSymbolAddress((void**)&en2lo, g_en2lo);

    const int* src = eidx;
    const int* dst = eidx + NEDGE;

    constexpr int ASM    = 2 * (2 * 128 * 72 * 2);
    constexpr int SM128  = ASM + 2 * (2 * 64 * 136 * 2);  // 143360
    constexpr int SM80   = ASM + 2 * (2 * 64 * 88 * 2);   // 118784
    constexpr int SMFUSE = 178176;

    cudaFuncSetAttribute((const void*)mma_gemm<128,4,8,0,false,false>,
                         cudaFuncAttributeMaxDynamicSharedMemorySize, SM128);
    cudaFuncSetAttribute((const void*)mma_gemm<128,4,8,0,false,true>,
                         cudaFuncAttributeMaxDynamicSharedMemorySize, SM128);
    cudaFuncSetAttribute((const void*)mma_gemm<128,4,5,2,true,false>,
                         cudaFuncAttributeMaxDynamicSharedMemorySize, SM128);
    cudaFuncSetAttribute((const void*)mma_gemm<128,4,4,3,true,false>,
                         cudaFuncAttributeMaxDynamicSharedMemorySize, SM128);
    cudaFuncSetAttribute((const void*)mma_gemm<128,4,4,0,false,false>,
                         cudaFuncAttributeMaxDynamicSharedMemorySize, SM128);
    cudaFuncSetAttribute((const void*)mma_gemm<80,1,8,0,false,false>,
                         cudaFuncAttributeMaxDynamicSharedMemorySize, SM80);
    cudaFuncSetAttribute((const void*)fused_edge,
                         cudaFuncAttributeMaxDynamicSharedMemorySize, SMFUSE);

    // ---------- weight prep ----------
    { int t = NLAYERS*576*HIDD;   wsplit<<<(t+255)/256,256>>>(pe_w1, pe1hi, pe1lo, t); }
    { int t = NLAYERS*256*1024;   wsd_pack<<<(t+255)/256,256>>>(pe_w1, wsdhi, wsdlo); }
    { int t = NLAYERS*HIDD*EDGE_D;wsplit<<<(t+255)/256,256>>>(pe_w2, pe2hi, pe2lo, t); }
    { int t = NLAYERS*320*HIDD;   wsplit<<<(t+255)/256,256>>>(pn_w1, pn1hi, pn1lo, t); }
    { int t = NLAYERS*HIDD*NODE_D;wsplit<<<(t+255)/256,256>>>(pn_w2, pn2hi, pn2lo, t); }
    { int t = NODE_D*HIDD;        wsplit<<<(t+255)/256,256>>>(dec_w1, dc1hi, dc1lo, t); }
    { int t = HIDD*NODE_D;        wsplit<<<(t+255)/256,256>>>(enc_w2, en2hi, en2lo, t); }
    wpad80<<<(512*80+255)/256,256>>>(dec_w2, dc2hi, dc2lo);
    bpad80<<<1,80>>>(dec_b2, dcb2p);

    // ---------- encoder ----------
    {
        int total = NBATCH * NMESH * ENC_LDA;
        build_encin<<<(total + 255) / 256, 256>>>(xc, xp, geo, g2m, encin);
    }
    sgemm_bias<128,128,16,8,8><<<gemm_grid(NBATCH*NMESH, HIDD, 128, 128), 256>>>(
        encin, ENC_LDA, enc_w1, enc_b1, nullptr, h, NBATCH*NMESH, HIDD, ENC_IN, 1);
    mma_gemm<128,4,8,0,false,false><<<dim3(2, (NBATCH*NMESH + 127)/128), 256, SM128>>>(
        h, nullptr, nullptr, en2hi, en2lo, enc_b2, nullptr, x,
        NBATCH*NMESH, NODE_D, NODE_D, NODE_D);

    // ---------- edge embedder ----------
    sgemm_bias<128,64,16,8,4><<<gemm_grid(NEDGE, EDGE_D, 128, 64), 256>>>(
        redge, 4, eme_w1, eme_b1, nullptr, h, NEDGE, EDGE_D, 4, 1);
    sgemm_bias<128,64,16,8,4><<<gemm_grid(NEDGE, EDGE_D, 128, 64), 256>>>(
        h, EDGE_D, eme_w2, eme_b2, nullptr, e0, NEDGE, EDGE_D, EDGE_D, 0);

    // ---------- GNN layers ----------
    for (int b = 0; b < NBATCH; b++) {
        float* xb = x + (size_t)b * NMESH * NODE_D;
        for (int l = 0; l < NLAYERS; l++) {
            const float* ein = (l == 0) ? e0 : e;

            // xsd = x @ [Wsrc | Wdst]  (M=10242, K=256, N=1024)
            mma_gemm<128,4,4,0,false,false><<<dim3(8, (NMESH+127)/128), 256, SM128>>>(
                xb, nullptr, nullptr,
                wsdhi + (size_t)l*256*1024, wsdlo + (size_t)l*256*1024,
                zeros, nullptr, xsd, NMESH, 1024, 1024, 1024);

            cudaMemsetAsync(agg, 0, (size_t)NMESH * EDGE_D * sizeof(float), 0);

            // fused edge MLP (both stages) + residual + scatter-add
            fused_edge<<<NEDGE/128, 256, SMFUSE>>>(
                ein, xsd, src, dst,
                pe1hi + (size_t)l*576*HIDD, pe1lo + (size_t)l*576*HIDD,
                pe2hi + (size_t)l*HIDD*EDGE_D, pe2lo + (size_t)l*HIDD*EDGE_D,
                pe_b1 + (size_t)l*HIDD, pe_b2 + (size_t)l*EDGE_D,
                e, agg);

            // node MLP1: [x | agg] @ W1 + b, relu
            mma_gemm<128,4,5,2,true,false><<<dim3(4, (NMESH+127)/128), 256, SM128>>>(
                xb, agg, nullptr,
                pn1hi + (size_t)l*320*HIDD, pn1lo + (size_t)l*320*HIDD,
                pn_b1 + (size_t)l*HIDD, nullptr, h, NMESH, HIDD, HIDD, HIDD);
            // node MLP2: h @ W2 + b + x (in place)
            mma_gemm<128,4,8,0,false,true><<<dim3(2, (NMESH+127)/128), 256, SM128>>>(
                h, nullptr, nullptr,
                pn2hi + (size_t)l*HIDD*NODE_D, pn2lo + (size_t)l*HIDD*NODE_D,
                pn_b2 + (size_t)l*NODE_D, xb, xb, NMESH, NODE_D, NODE_D, NODE_D);
        }
    }

    // ---------- decoder ----------
    for (int b = 0; b < NBATCH; b++) {
        mma_gemm<128,4,4,3,true,false><<<dim3(4, (NGRID+127)/128), 256, SM128>>>(
            x + (size_t)b*NMESH*NODE_D, nullptr, m2g,
            dc1hi, dc1lo, dec_b1, nullptr,
            h + (size_t)b*NGRID*HIDD, NGRID, HIDD, HIDD, HIDD);
    }
    // decoder MLP2 on HMMA (N padded 78->80, clipped on store)
    mma_gemm<80,1,8,0,false,false><<<dim3(1, (NBATCH*NGRID + 127)/128), 256, SM80>>>(
        h, nullptr, nullptr, dc2hi, dc2lo, dcb2p, nullptr, out,
        NBATCH*NGRID, 80, 78, 78);
}

// round 7
// speedup vs baseline: 9.4372x; 1.1096x over previous
#include <cuda_runtime.h>
#include <cuda_bf16.h>
#include <cstdint>

// ---------------- problem constants ----------------
#define NLAT   181
#define NLON   360
#define NV     78
#define NGRID  (NLAT*NLON)      // 65160
#define NBATCH 2
#define NMESH  10242
#define NEDGE  163840
#define NODE_D 256
#define EDGE_D 64
#define HIDD   512
#define NLAYERS 16
#define ENC_IN  163
#define ENC_LDA 164

// ---------------- device scratch ----------------
__device__ float g_encin[(size_t)NBATCH*NMESH*ENC_LDA];
__device__ float g_x    [(size_t)NBATCH*NMESH*NODE_D];
__device__ float g_e    [(size_t)NBATCH*NEDGE*EDGE_D];
__device__ float g_e0   [(size_t)NEDGE*EDGE_D];
__device__ float g_h    [(size_t)NEDGE*HIDD];
__device__ float g_agg  [(size_t)NBATCH*NMESH*EDGE_D];
__device__ float g_xsd  [(size_t)NBATCH*NMESH*1024];
__device__ float g_zeros[1024];
__device__ float g_dcb2p[80];
// bf16 hi/lo split weights
__device__ __nv_bfloat16 g_pe1hi[(size_t)NLAYERS*576*HIDD];
__device__ __nv_bfloat16 g_pe1lo[(size_t)NLAYERS*576*HIDD];
__device__ __nv_bfloat16 g_wsdhi[(size_t)NLAYERS*256*1024];
__device__ __nv_bfloat16 g_wsdlo[(size_t)NLAYERS*256*1024];
__device__ __nv_bfloat16 g_pe2hi[(size_t)NLAYERS*HIDD*EDGE_D];
__device__ __nv_bfloat16 g_pe2lo[(size_t)NLAYERS*HIDD*EDGE_D];
__device__ __nv_bfloat16 g_pn1hi[(size_t)NLAYERS*320*HIDD];
__device__ __nv_bfloat16 g_pn1lo[(size_t)NLAYERS*320*HIDD];
__device__ __nv_bfloat16 g_pn2hi[(size_t)NLAYERS*HIDD*NODE_D];
__device__ __nv_bfloat16 g_pn2lo[(size_t)NLAYERS*HIDD*NODE_D];
__device__ __nv_bfloat16 g_dc1hi[(size_t)NODE_D*HIDD];
__device__ __nv_bfloat16 g_dc1lo[(size_t)NODE_D*HIDD];
__device__ __nv_bfloat16 g_dc2hi[(size_t)HIDD*80];
__device__ __nv_bfloat16 g_dc2lo[(size_t)HIDD*80];
__device__ __nv_bfloat16 g_en2hi[(size_t)HIDD*NODE_D];
__device__ __nv_bfloat16 g_en2lo[(size_t)HIDD*NODE_D];

// ---------------- asm helpers ----------------
__device__ __forceinline__ void ldsm_x4(uint32_t* r, uint32_t addr) {
    asm volatile("ldmatrix.sync.aligned.m8n8.x4.shared.b16 {%0,%1,%2,%3}, [%4];"
        : "=r"(r[0]), "=r"(r[1]), "=r"(r[2]), "=r"(r[3]) : "r"(addr));
}
__device__ __forceinline__ void ldsm_x4t(uint32_t* r, uint32_t addr) {
    asm volatile("ldmatrix.sync.aligned.m8n8.x4.trans.shared.b16 {%0,%1,%2,%3}, [%4];"
        : "=r"(r[0]), "=r"(r[1]), "=r"(r[2]), "=r"(r[3]) : "r"(addr));
}
__device__ __forceinline__ void mma16816(float* d, const uint32_t* a, const uint32_t* b) {
    asm volatile("mma.sync.aligned.m16n8k16.row.col.f32.bf16.bf16.f32 "
        "{%0,%1,%2,%3}, {%4,%5,%6,%7}, {%8,%9}, {%0,%1,%2,%3};"
        : "+f"(d[0]), "+f"(d[1]), "+f"(d[2]), "+f"(d[3])
        : "r"(a[0]), "r"(a[1]), "r"(a[2]), "r"(a[3]), "r"(b[0]), "r"(b[1]));
}
__device__ __forceinline__ uint32_t smem_u32(const void* p) {
    uint32_t a;
    asm("{ .reg .u64 t; cvta.to.shared.u64 t, %1; cvt.u32.u64 %0, t; }" : "=r"(a) : "l"(p));
    return a;
}
#define CP_ASYNC16(dst, src) \
    asm volatile("cp.async.cg.shared.global [%0], [%1], 16;" :: "r"(dst), "l"(src))
#define CP_COMMIT() asm volatile("cp.async.commit_group;" ::: "memory")
#define CP_WAIT0()  asm volatile("cp.async.wait_group 0;" ::: "memory")
#define STS_V2(addr, x, y) \
    asm volatile("st.shared.v2.u32 [%0], {%1,%2};" :: "r"(addr), "r"(x), "r"(y))
#define STS_U32(addr, x) \
    asm volatile("st.shared.u32 [%0], %1;" :: "r"(addr), "r"(x))

__device__ __forceinline__ void split4(float4 v, uint2& hh, uint2& ll) {
    __nv_bfloat16 h0 = __float2bfloat16_rn(v.x), h1 = __float2bfloat16_rn(v.y);
    __nv_bfloat16 h2 = __float2bfloat16_rn(v.z), h3 = __float2bfloat16_rn(v.w);
    __nv_bfloat16 g0 = __float2bfloat16_rn(v.x - __bfloat162float(h0));
    __nv_bfloat16 g1 = __float2bfloat16_rn(v.y - __bfloat162float(h1));
    __nv_bfloat16 g2 = __float2bfloat16_rn(v.z - __bfloat162float(h2));
    __nv_bfloat16 g3 = __float2bfloat16_rn(v.w - __bfloat162float(h3));
    hh.x = (uint32_t)__bfloat16_as_ushort(h0) | ((uint32_t)__bfloat16_as_ushort(h1) << 16);
    hh.y = (uint32_t)__bfloat16_as_ushort(h2) | ((uint32_t)__bfloat16_as_ushort(h3) << 16);
    ll.x = (uint32_t)__bfloat16_as_ushort(g0) | ((uint32_t)__bfloat16_as_ushort(g1) << 16);
    ll.y = (uint32_t)__bfloat16_as_ushort(g2) | ((uint32_t)__bfloat16_as_ushort(g3) << 16);
}
__device__ __forceinline__ void split2(float vx, float vy, uint32_t& hp, uint32_t& lp) {
    __nv_bfloat16 hx = __float2bfloat16_rn(vx), hy = __float2bfloat16_rn(vy);
    __nv_bfloat16 lx = __float2bfloat16_rn(vx - __bfloat162float(hx));
    __nv_bfloat16 ly = __float2bfloat16_rn(vy - __bfloat162float(hy));
    hp = (uint32_t)__bfloat16_as_ushort(hx) | ((uint32_t)__bfloat16_as_ushort(hy) << 16);
    lp = (uint32_t)__bfloat16_as_ushort(lx) | ((uint32_t)__bfloat16_as_ushort(ly) << 16);
}

// ---------------- A-gather modes ----------------
// MODE 0: plain A[M][K]
// MODE 2: [x(256)|agg(64)]
// MODE 4: gathered rows A[m2g[g%NGRID] + (g/NGRID)*NMESH][256]
template<int MODE>
__device__ __forceinline__ void prefA(float4 (&Ra)[8], int c, int rowBase, int M,
    const float* __restrict__ A, const float* __restrict__ aux,
    const int (&sI)[8], int tid, int K)
{
    const int f = tid & 15;
    #pragma unroll
    for (int it = 0; it < 8; it++) {
        int gr = rowBase + it * 16 + (tid >> 4);
        if (gr < M) {
            const float* p;
            if (MODE == 0)      p = A + (size_t)gr * K + c * 64;
            else if (MODE == 2) p = (c < 4) ? A + (size_t)gr * 256 + c * 64
                                            : aux + (size_t)gr * 64;
            else                p = A + (size_t)sI[it] * 256 + c * 64;
            Ra[it] = reinterpret_cast<const float4*>(p)[f];
        } else {
            Ra[it] = make_float4(0.f, 0.f, 0.f, 0.f);
        }
    }
}

// =====================================================================
//  HMMA GEMM: C[M x Nclip (pitch Cpitch)] = [res+] relu?(gather(A)@W + bias)
// =====================================================================
template<int BN, int WARPS_N, int NC, int MODE, bool RELU, bool HAS_RES>
__global__ void __launch_bounds__(256)
mma_gemm(const float* __restrict__ A, const float* __restrict__ aux,
         const int* __restrict__ idx1,
         const __nv_bfloat16* __restrict__ Bhi, const __nv_bfloat16* __restrict__ Blo,
         const float* __restrict__ bias, const float* res, float* C,
         int M, int Nfull, int Cpitch, int Nclip)
{
    constexpr int K       = NC * 64;
    constexpr int WARPS_M = 8 / WARPS_N;
    constexpr int WTM     = 128 / WARPS_M;
    constexpr int WTN     = BN / WARPS_N;
    constexpr int MT      = WTM / 16;
    constexpr int NT      = WTN / 8;
    constexpr int ASTRIDE = 72;
    constexpr int APLANE  = 128 * ASTRIDE * 2;
    constexpr int ABUF    = 2 * APLANE;
    constexpr int BSTRIDE = BN + 8;
    constexpr int BPLANE  = 64 * BSTRIDE * 2;
    constexpr int BBUF    = 2 * BPLANE;
    constexpr int GRAN    = BN / 8;
    constexpr int BTOT    = 2 * 64 * GRAN;

    extern __shared__ char sm[];
    const uint32_t smA = smem_u32(sm);
    const uint32_t smB = smA + 2 * ABUF;

    const int tid    = threadIdx.x;
    const int lane   = tid & 31;
    const int wid    = tid >> 5;
    const int warp_n = wid % WARPS_N;
    const int warp_m = wid / WARPS_N;
    const int rowBase = blockIdx.y * 128;
    const int colBase = blockIdx.x * BN;

    int sI[8];
    #pragma unroll
    for (int it = 0; it < 8; it++) {
        int gr = rowBase + it * 16 + (tid >> 4);
        int g  = (gr < M) ? gr : 0;
        if (MODE == 4) {
            int b = g / NGRID;
            sI[it] = idx1[g - b * NGRID] + b * NMESH;
        } else {
            sI[it] = 0;
        }
    }

    float acc[MT][NT][4];
    #pragma unroll
    for (int i = 0; i < MT; i++)
        #pragma unroll
        for (int j = 0; j < NT; j++)
            #pragma unroll
            for (int q = 0; q < 4; q++) acc[i][j][q] = 0.f;

    float4 Ra[8];
    prefA<MODE>(Ra, 0, rowBase, M, A, aux, sI, tid, K);

    {
        #pragma unroll
        for (int it = 0; it < BTOT / 256; it++) {
            int i = it * 256 + tid;
            int plane = i / (64 * GRAN);
            int rem   = i % (64 * GRAN);
            int k = rem / GRAN, g = rem % GRAN;
            const __nv_bfloat16* sp = (plane ? Blo : Bhi)
                + (size_t)k * Nfull + colBase + g * 8;
            CP_ASYNC16(smB + plane * BPLANE + (uint32_t)(k * BSTRIDE + g * 8) * 2, sp);
        }
        CP_COMMIT();
    }

    for (int c = 0; c < NC; c++) {
        const int buf = c & 1;
        #pragma unroll
        for (int it = 0; it < 8; it++) {
            int r = it * 16 + (tid >> 4);
            int f = tid & 15;
            uint2 hh, ll;
            split4(Ra[it], hh, ll);
            uint32_t off = smA + buf * ABUF + (uint32_t)(r * ASTRIDE + f * 4) * 2;
            STS_V2(off, hh.x, hh.y);
            STS_V2(off + APLANE, ll.x, ll.y);
        }
        if (c + 1 < NC) prefA<MODE>(Ra, c + 1, rowBase, M, A, aux, sI, tid, K);
        CP_WAIT0();
        __syncthreads();
        if (c + 1 < NC) {
            #pragma unroll
            for (int it = 0; it < BTOT / 256; it++) {
                int i = it * 256 + tid;
                int plane = i / (64 * GRAN);
                int rem   = i % (64 * GRAN);
                int k = rem / GRAN, g = rem % GRAN;
                const __nv_bfloat16* sp = (plane ? Blo : Bhi)
                    + (size_t)(c + 1) * 64 * Nfull + (size_t)k * Nfull + colBase + g * 8;
                CP_ASYNC16(smB + (1 - buf) * BBUF + plane * BPLANE
                           + (uint32_t)(k * BSTRIDE + g * 8) * 2, sp);
            }
            CP_COMMIT();
        }

        #pragma unroll
        for (int ks = 0; ks < 4; ks++) {
            uint32_t Ah[MT][4], Al[MT][4];
            #pragma unroll
            for (int mt = 0; mt < MT; mt++) {
                uint32_t addr = smA + buf * ABUF
                    + (uint32_t)((warp_m * WTM + mt * 16 + (lane & 15)) * ASTRIDE
                                 + ks * 16 + (lane >> 4) * 8) * 2;
                ldsm_x4(Ah[mt], addr);
                ldsm_x4(Al[mt], addr + APLANE);
            }
            uint32_t Bh[NT / 2][4], Bl[NT / 2][4];
            #pragma unroll
            for (int np = 0; np < NT / 2; np++) {
                uint32_t addr = smB + buf * BBUF
                    + (uint32_t)((ks * 16 + (lane & 15)) * BSTRIDE
                                 + warp_n * WTN + np * 16 + (lane >> 4) * 8) * 2;
                ldsm_x4t(Bh[np], addr);
                ldsm_x4t(Bl[np], addr + BPLANE);
            }
            #pragma unroll
            for (int mt = 0; mt < MT; mt++)
                #pragma unroll
                for (int nt = 0; nt < NT; nt++) {
                    const uint32_t* bh = &Bh[nt >> 1][(nt & 1) * 2];
                    const uint32_t* bl = &Bl[nt >> 1][(nt & 1) * 2];
                    mma16816(acc[mt][nt], Ah[mt], bh);
                    mma16816(acc[mt][nt], Ah[mt], bl);
                    mma16816(acc[mt][nt], Al[mt], bh);
                }
        }
    }

    #pragma unroll
    for (int nt = 0; nt < NT; nt++) {
        int n = colBase + warp_n * WTN + nt * 8 + (lane & 3) * 2;
        if (n >= Nclip) continue;
        float2 bb = *reinterpret_cast<const float2*>(bias + n);
        #pragma unroll
        for (int mt = 0; mt < MT; mt++) {
            #pragma unroll
            for (int half = 0; half < 2; half++) {
                int row = rowBase + warp_m * WTM + mt * 16 + (lane >> 2) + half * 8;
                if (row < M) {
                    float vx = acc[mt][nt][half * 2 + 0] + bb.x;
                    float vy = acc[mt][nt][half * 2 + 1] + bb.y;
                    size_t off = (size_t)row * Cpitch + n;
                    if (HAS_RES) {
                        float2 rr = *reinterpret_cast<const float2*>(res + off);
                        vx += rr.x; vy += rr.y;
                    }
                    if (RELU) { vx = fmaxf(vx, 0.f); vy = fmaxf(vy, 0.f); }
                    float2 o; o.x = vx; o.y = vy;
                    *reinterpret_cast<float2*>(C + off) = o;
                }
            }
        }
    }
}

// =====================================================================
//  Fused edge layer (batched via blockIdx.y):
//  hidden = relu(e@We + b1 + xs[src] + xd[dst])  (chunks of 128 cols, smem)
//  eout   = ein + hidden @ W2 + b2 ;  agg[dst] += eout   (atomics)
// =====================================================================
__global__ void __launch_bounds__(256)
fused_edge(const float* __restrict__ ein,
           const float* __restrict__ xsd,
           const int* __restrict__ src, const int* __restrict__ dst,
           const __nv_bfloat16* __restrict__ W1hi, const __nv_bfloat16* __restrict__ W1lo,
           const __nv_bfloat16* __restrict__ W2hi, const __nv_bfloat16* __restrict__ W2lo,
           const float* __restrict__ b1, const float* __restrict__ b2,
           float* __restrict__ eout, float* __restrict__ agg,
           size_t einBatchStride)
{
    constexpr int A_STR  = 72;
    constexpr int A_PL   = 128 * A_STR * 2;
    constexpr int OFF_A  = 0;
    constexpr int B1_STR = 136;
    constexpr int B1_PL  = 64 * B1_STR * 2;
    constexpr int OFF_B1 = 2 * A_PL;
    constexpr int H_STR  = 136;
    constexpr int H_PL   = 128 * H_STR * 2;
    constexpr int OFF_H  = OFF_B1 + 2 * B1_PL;
    constexpr int B2_STR = 72;
    constexpr int B2_PL  = 128 * B2_STR * 2;
    constexpr int OFF_B2 = OFF_H + 2 * H_PL;   // total 178176

    extern __shared__ char sm[];
    const uint32_t base = smem_u32(sm);

    const int tid  = threadIdx.x;
    const int lane = tid & 31;
    const int wid  = tid >> 5;
    const int warp_m = wid >> 1;
    const int warp_n = wid & 1;
    const int rowBase = blockIdx.x * 128;
    const int batch   = blockIdx.y;

    const float* einb = ein + (size_t)batch * einBatchStride;
    const float* xsdb = xsd + (size_t)batch * NMESH * 1024;
    float* eoutb = eout + (size_t)batch * NEDGE * EDGE_D;
    float* aggb  = agg  + (size_t)batch * NMESH * EDGE_D;

    int sidx[2][2], didx[2][2];
    #pragma unroll
    for (int mt = 0; mt < 2; mt++)
        #pragma unroll
        for (int half = 0; half < 2; half++) {
            int g = rowBase + warp_m * 32 + mt * 16 + (lane >> 2) + half * 8;
            sidx[mt][half] = src[g];
            didx[mt][half] = dst[g];
        }

    // ---- load e tile (128 x 64 fp32) into A smem hi/lo ----
    {
        const float4* E4 = reinterpret_cast<const float4*>(einb + (size_t)rowBase * 64);
        #pragma unroll
        for (int it = 0; it < 8; it++) {
            int i = tid + it * 256;
            int r = i >> 4, f = i & 15;
            float4 v = E4[r * 16 + f];
            uint2 hh, ll;
            split4(v, hh, ll);
            uint32_t off = base + OFF_A + (uint32_t)(r * A_STR + f * 4) * 2;
            STS_V2(off, hh.x, hh.y);
            STS_V2(off + A_PL, ll.x, ll.y);
        }
    }

    float acc2[2][4][4];
    #pragma unroll
    for (int i = 0; i < 2; i++)
        #pragma unroll
        for (int j = 0; j < 4; j++)
            #pragma unroll
            for (int q = 0; q < 4; q++) acc2[i][j][q] = 0.f;

    for (int nc = 0; nc < 4; nc++) {
        __syncthreads();
        // B1 chunk: We[0:64][nc*128 : +128], hi+lo
        #pragma unroll
        for (int it = 0; it < 8; it++) {
            int i = tid + it * 256;
            int plane = i >> 10;
            int rem = i & 1023;
            int k = rem >> 4, g = rem & 15;
            const __nv_bfloat16* sp = (plane ? W1lo : W1hi)
                + (size_t)k * 512 + nc * 128 + g * 8;
            CP_ASYNC16(base + OFF_B1 + plane * B1_PL + (uint32_t)(k * B1_STR + g * 8) * 2, sp);
        }
        // B2 chunk: W2[nc*128 : +128][0:64], hi+lo
        #pragma unroll
        for (int it = 0; it < 8; it++) {
            int i = tid + it * 256;
            int plane = i >> 10;
            int rem = i & 1023;
            int k = rem >> 3, g = rem & 7;
            const __nv_bfloat16* sp = (plane ? W2lo : W2hi)
                + (size_t)(nc * 128 + k) * 64 + g * 8;
            CP_ASYNC16(base + OFF_B2 + plane * B2_PL + (uint32_t)(k * B2_STR + g * 8) * 2, sp);
        }
        CP_COMMIT();
        CP_WAIT0();
        __syncthreads();

        // ---- stage 1: acc1 = e @ We_chunk (128x128, K=64) ----
        float acc1[2][8][4];
        #pragma unroll
        for (int i = 0; i < 2; i++)
            #pragma unroll
            for (int j = 0; j < 8; j++)
                #pragma unroll
                for (int q = 0; q < 4; q++) acc1[i][j][q] = 0.f;

        #pragma unroll
        for (int ks = 0; ks < 4; ks++) {
            uint32_t Ah[2][4], Al[2][4];
            #pragma unroll
            for (int mt = 0; mt < 2; mt++) {
                uint32_t addr = base + OFF_A
                    + (uint32_t)((warp_m * 32 + mt * 16 + (lane & 15)) * A_STR
                                 + ks * 16 + (lane >> 4) * 8) * 2;
                ldsm_x4(Ah[mt], addr);
                ldsm_x4(Al[mt], addr + A_PL);
            }
            uint32_t Bh[4][4], Bl[4][4];
            #pragma unroll
            for (int np = 0; np < 4; np++) {
                uint32_t addr = base + OFF_B1
                    + (uint32_t)((ks * 16 + (lane & 15)) * B1_STR
                                 + warp_n * 64 + np * 16 + (lane >> 4) * 8) * 2;
                ldsm_x4t(Bh[np], addr);
                ldsm_x4t(Bl[np], addr + B1_PL);
            }
            #pragma unroll
            for (int mt = 0; mt < 2; mt++)
                #pragma unroll
                for (int nt = 0; nt < 8; nt++) {
                    const uint32_t* bh = &Bh[nt >> 1][(nt & 1) * 2];
                    const uint32_t* bl = &Bl[nt >> 1][(nt & 1) * 2];
                    mma16816(acc1[mt][nt], Ah[mt], bh);
                    mma16816(acc1[mt][nt], Ah[mt], bl);
                    mma16816(acc1[mt][nt], Al[mt], bh);
                }
        }

        // ---- stage1 epilogue: + b1 + xs[src] + xd[dst], relu, -> H smem ----
        #pragma unroll
        for (int nt = 0; nt < 8; nt++) {
            int col  = warp_n * 64 + nt * 8 + (lane & 3) * 2;
            int gcol = nc * 128 + col;
            float2 bb = *reinterpret_cast<const float2*>(b1 + gcol);
            #pragma unroll
            for (int mt = 0; mt < 2; mt++) {
                #pragma unroll
                for (int half = 0; half < 2; half++) {
                    int row_l = warp_m * 32 + mt * 16 + (lane >> 2) + half * 8;
                    float2 sv = *reinterpret_cast<const float2*>(
                        xsdb + (size_t)sidx[mt][half] * 1024 + gcol);
                    float2 dv = *reinterpret_cast<const float2*>(
                        xsdb + (size_t)didx[mt][half] * 1024 + 512 + gcol);
                    float vx = fmaxf(acc1[mt][nt][half * 2 + 0] + bb.x + sv.x + dv.x, 0.f);
                    float vy = fmaxf(acc1[mt][nt][half * 2 + 1] + bb.y + sv.y + dv.y, 0.f);
                    uint32_t hp, lp;
                    split2(vx, vy, hp, lp);
                    uint32_t off = base + OFF_H + (uint32_t)(row_l * H_STR + col) * 2;
                    STS_U32(off, hp);
                    STS_U32(off + H_PL, lp);
                }
            }
        }
        __syncthreads();

        // ---- stage 2: acc2 += hidden_chunk @ W2_chunk (K=128) ----
        #pragma unroll
        for (int ks = 0; ks < 8; ks++) {
            uint32_t Ah[2][4], Al[2][4];
            #pragma unroll
            for (int mt = 0; mt < 2; mt++) {
                uint32_t addr = base + OFF_H
                    + (uint32_t)((warp_m * 32 + mt * 16 + (lane & 15)) * H_STR
                                 + ks * 16 + (lane >> 4) * 8) * 2;
                ldsm_x4(Ah[mt], addr);
                ldsm_x4(Al[mt], addr + H_PL);
            }
            uint32_t Bh[2][4], Bl[2][4];
            #pragma unroll
            for (int np = 0; np < 2; np++) {
                uint32_t addr = base + OFF_B2
                    + (uint32_t)((ks * 16 + (lane & 15)) * B2_STR
                                 + warp_n * 32 + np * 16 + (lane >> 4) * 8) * 2;
                ldsm_x4t(Bh[np], addr);
                ldsm_x4t(Bl[np], addr + B2_PL);
            }
            #pragma unroll
            for (int mt = 0; mt < 2; mt++)
                #pragma unroll
                for (int nt = 0; nt < 4; nt++) {
                    const uint32_t* bh = &Bh[nt >> 1][(nt & 1) * 2];
                    const uint32_t* bl = &Bl[nt >> 1][(nt & 1) * 2];
                    mma16816(acc2[mt][nt], Ah[mt], bh);
                    mma16816(acc2[mt][nt], Ah[mt], bl);
                    mma16816(acc2[mt][nt], Al[mt], bh);
                }
        }
    }

    // ---- final epilogue: + b2 + ein residual, write e, scatter-add agg ----
    #pragma unroll
    for (int nt = 0; nt < 4; nt++) {
        int n = warp_n * 32 + nt * 8 + (lane & 3) * 2;
        float2 bb = *reinterpret_cast<const float2*>(b2 + n);
        #pragma unroll
        for (int mt = 0; mt < 2; mt++) {
            #pragma unroll
            for (int half = 0; half < 2; half++) {
                int row_l = warp_m * 32 + mt * 16 + (lane >> 2) + half * 8;
                size_t off = (size_t)(rowBase + row_l) * 64 + n;
                float2 rr = *reinterpret_cast<const float2*>(einb + off);
                float vx = acc2[mt][nt][half * 2 + 0] + bb.x + rr.x;
                float vy = acc2[mt][nt][half * 2 + 1] + bb.y + rr.y;
                float2 o; o.x = vx; o.y = vy;
                *reinterpret_cast<float2*>(eoutb + off) = o;
                float* ap = aggb + (size_t)didx[mt][half] * 64 + n;
                atomicAdd(ap,     vx);
                atomicAdd(ap + 1, vy);
            }
        }
    }
}

// ---------------- weight prep kernels ----------------
__global__ void wsplit(const float* __restrict__ w, __nv_bfloat16* __restrict__ hi,
                       __nv_bfloat16* __restrict__ lo, int total)
{
    int i = blockIdx.x * blockDim.x + threadIdx.x;
    if (i >= total) return;
    float v = w[i];
    __nv_bfloat16 h = __float2bfloat16_rn(v);
    hi[i] = h;
    lo[i] = __float2bfloat16_rn(v - __bfloat162float(h));
}

__global__ void wsd_pack(const float* __restrict__ w, __nv_bfloat16* __restrict__ hi,
                         __nv_bfloat16* __restrict__ lo)
{
    int i = blockIdx.x * blockDim.x + threadIdx.x;
    const int total = NLAYERS * 256 * 1024;
    if (i >= total) return;
    int l = i >> 18;
    int rem = i & 262143;
    int r = rem >> 10;
    int n = rem & 1023;
    int srow = (n < 512) ? (64 + r) : (320 + r);
    int scol = n & 511;
    float v = w[(size_t)l * 576 * 512 + (size_t)srow * 512 + scol];
    __nv_bfloat16 h = __float2bfloat16_rn(v);
    hi[i] = h;
    lo[i] = __float2bfloat16_rn(v - __bfloat162float(h));
}

__global__ void wpad80(const float* __restrict__ w, __nv_bfloat16* __restrict__ hi,
                       __nv_bfloat16* __restrict__ lo)
{
    int i = blockIdx.x * blockDim.x + threadIdx.x;
    if (i >= 512 * 80) return;
    int k = i / 80, n = i % 80;
    float v = (n < 78) ? w[k * 78 + n] : 0.f;
    __nv_bfloat16 h = __float2bfloat16_rn(v);
    hi[i] = h;
    lo[i] = __float2bfloat16_rn(v - __bfloat162float(h));
}
__global__ void bpad80(const float* __restrict__ b, float* __restrict__ o)
{
    int i = threadIdx.x;
    if (i < 80) o[i] = (i < 78) ? b[i] : 0.f;
}

// =====================================================================
//  SIMT fp32 GEMM (encoder MLP1, embedder)
// =====================================================================
template<int BM, int BN, int BK, int TM, int TN>
__global__ void __launch_bounds__(256)
sgemm_bias(const float* __restrict__ A, int lda,
           const float* __restrict__ W,
           const float* __restrict__ bias,
           const float* res, float* C,
           int M, int N, int K, int doRelu)
{
    constexpr int GN      = TN / 4;
    constexpr int CSTRIDE = BN / GN;
    constexpr int NTC     = BN / TN;
    constexpr int THREADS = (BM / TM) * NTC;
    static_assert(THREADS == 256, "expect 256 threads");
    static_assert(BK == 16 && THREADS == BM * 2, "A loader mapping");

    __shared__ float As[BK][BM + 4];
    __shared__ float Bs[BK][BN];

    const int tid  = threadIdx.x;
    const int tcol = tid % NTC;
    const int trow = tid / NTC;
    const int rowBase = blockIdx.y * BM;
    const int colBase = blockIdx.x * BN;

    float acc[TM][TN];
    #pragma unroll
    for (int i = 0; i < TM; i++)
        #pragma unroll
        for (int j = 0; j < TN; j++) acc[i][j] = 0.f;

    const int am = tid >> 1;
    const int ah = (tid & 1) * 8;

    for (int k0 = 0; k0 < K; k0 += BK) {
        {
            const int gm = rowBase + am;
            const bool mok = (gm < M);
            const float* Arow = A + (size_t)gm * lda + (k0 + ah);
            #pragma unroll
            for (int i = 0; i < 8; i++) {
                int gk = k0 + ah + i;
                As[ah + i][am] = (mok && gk < K) ? Arow[i] : 0.f;
            }
        }
        #pragma unroll
        for (int it = 0; it < (BK * BN) / THREADS; it++) {
            int idx = tid + it * THREADS;
            int k = idx / BN, n = idx % BN;
            int gk = k0 + k, gn = colBase + n;
            Bs[k][n] = (gk < K && gn < N) ? W[(size_t)gk * N + gn] : 0.f;
        }
        __syncthreads();

        #pragma unroll
        for (int k = 0; k < BK; k++) {
            float ra[TM], rb[TN];
            #pragma unroll
            for (int i = 0; i < TM; i++) ra[i] = As[k][trow * TM + i];
            #pragma unroll
            for (int cg = 0; cg < GN; cg++)
                #pragma unroll
                for (int j = 0; j < 4; j++)
                    rb[cg * 4 + j] = Bs[k][cg * CSTRIDE + tcol * 4 + j];
            #pragma unroll
            for (int i = 0; i < TM; i++)
                #pragma unroll
                for (int j = 0; j < TN; j++)
                    acc[i][j] = fmaf(ra[i], rb[j], acc[i][j]);
        }
        __syncthreads();
    }

    #pragma unroll
    for (int i = 0; i < TM; i++) {
        int gm = rowBase + trow * TM + i;
        if (gm >= M) continue;
        #pragma unroll
        for (int cg = 0; cg < GN; cg++) {
            #pragma unroll
            for (int j = 0; j < 4; j++) {
                int gn = colBase + cg * CSTRIDE + tcol * 4 + j;
                if (gn >= N) continue;
                float v = acc[i][cg * 4 + j] + bias[gn];
                if (doRelu) v = fmaxf(v, 0.f);
                size_t off = (size_t)gm * N + gn;
                if (res) v += res[off];
                C[off] = v;
            }
        }
    }
}

// ---------------- builders ----------------
__global__ void build_encin(const float* __restrict__ xc, const float* __restrict__ xp,
                            const float* __restrict__ geo, const int* __restrict__ g2m,
                            float* __restrict__ out)
{
    int idx = blockIdx.x * blockDim.x + threadIdx.x;
    const int total = NBATCH * NMESH * ENC_LDA;
    if (idx >= total) return;
    int row = idx / ENC_LDA;
    int c   = idx - row * ENC_LDA;
    int b   = row / NMESH;
    int m   = row - b * NMESH;
    float v = 0.f;
    if (c < NV)            v = xc[((size_t)b * NGRID + g2m[m]) * NV + c];
    else if (c < 2 * NV)   v = xp[((size_t)b * NGRID + g2m[m]) * NV + (c - NV)];
    else if (c < ENC_IN)   v = geo[m * 7 + (c - 2 * NV)];
    out[idx] = v;
}

// ---------------- launcher ----------------
static inline dim3 gemm_grid(int M, int N, int BM, int BN) {
    return dim3((unsigned)((N + BN - 1) / BN), (unsigned)((M + BM - 1) / BM));
}

extern "C" void kernel_launch(void* const* d_in, const int* in_sizes, int n_in,
                              void* d_out, int out_size)
{
    const float* xc     = (const float*)d_in[0];
    const float* xp     = (const float*)d_in[1];
    const float* geo    = (const float*)d_in[2];
    const float* redge  = (const float*)d_in[3];
    const int*   eidx   = (const int*)  d_in[4];
    const int*   g2m    = (const int*)  d_in[5];
    const int*   m2g    = (const int*)  d_in[6];
    const float* enc_w1 = (const float*)d_in[7];
    const float* enc_b1 = (const float*)d_in[8];
    const float* enc_w2 = (const float*)d_in[9];
    const float* enc_b2 = (const float*)d_in[10];
    const float* eme_w1 = (const float*)d_in[11];
    const float* eme_b1 = (const float*)d_in[12];
    const float* eme_w2 = (const float*)d_in[13];
    const float* eme_b2 = (const float*)d_in[14];
    const float* pe_w1  = (const float*)d_in[15];
    const float* pe_b1  = (const float*)d_in[16];
    const float* pe_w2  = (const float*)d_in[17];
    const float* pe_b2  = (const float*)d_in[18];
    const float* pn_w1  = (const float*)d_in[19];
    const float* pn_b1  = (const float*)d_in[20];
    const float* pn_w2  = (const float*)d_in[21];
    const float* pn_b2  = (const float*)d_in[22];
    const float* dec_w1 = (const float*)d_in[23];
    const float* dec_b1 = (const float*)d_in[24];
    const float* dec_w2 = (const float*)d_in[25];
    const float* dec_b2 = (const float*)d_in[26];
    float* out = (float*)d_out;

    float *encin, *x, *e, *e0, *h, *agg, *xsd, *zeros, *dcb2p;
    __nv_bfloat16 *pe1hi,*pe1lo,*wsdhi,*wsdlo,*pe2hi,*pe2lo,*pn1hi,*pn1lo,*pn2hi,*pn2lo;
    __nv_bfloat16 *dc1hi,*dc1lo,*dc2hi,*dc2lo,*en2hi,*en2lo;
    cudaGetSymbolAddress((void**)&encin, g_encin);
    cudaGetSymbolAddress((void**)&x,     g_x);
    cudaGetSymbolAddress((void**)&e,     g_e);
    cudaGetSymbolAddress((void**)&e0,    g_e0);
    cudaGetSymbolAddress((void**)&h,     g_h);
    cudaGetSymbolAddress((void**)&agg,   g_agg);
    cudaGetSymbolAddress((void**)&xsd,   g_xsd);
    cudaGetSymbolAddress((void**)&zeros, g_zeros);
    cudaGetSymbolAddress((void**)&dcb2p, g_dcb2p);
    cudaGetSymbolAddress((void**)&pe1hi, g_pe1hi);
    cudaGetSymbolAddress((void**)&pe1lo, g_pe1lo);
    cudaGetSymbolAddress((void**)&wsdhi, g_wsdhi);
    cudaGetSymbolAddress((void**)&wsdlo, g_wsdlo);
    cudaGetSymbolAddress((void**)&pe2hi, g_pe2hi);
    cudaGetSymbolAddress((void**)&pe2lo, g_pe2lo);
    cudaGetSymbolAddress((void**)&pn1hi, g_pn1hi);
    cudaGetSymbolAddress((void**)&pn1lo, g_pn1lo);
    cudaGetSymbolAddress((void**)&pn2hi, g_pn2hi);
    cudaGetSymbolAddress((void**)&pn2lo, g_pn2lo);
    cudaGetSymbolAddress((void**)&dc1hi, g_dc1hi);
    cudaGetSymbolAddress((void**)&dc1lo, g_dc1lo);
    cudaGetSymbolAddress((void**)&dc2hi, g_dc2hi);
    cudaGetSymbolAddress((void**)&dc2lo, g_dc2lo);
    cudaGetSymbolAddress((void**)&en2hi, g_en2hi);
    cudaGetSymbolAddress((void**)&en2lo, g_en2lo);

    const int* src = eidx;
    const int* dst = eidx + NEDGE;

    constexpr int ASM    = 2 * (2 * 128 * 72 * 2);
    constexpr int SM128  = ASM + 2 * (2 * 64 * 136 * 2);  // 143360
    constexpr int SM80   = ASM + 2 * (2 * 64 * 88 * 2);   // 118784
    constexpr int SMFUSE = 178176;

    cudaFuncSetAttribute((const void*)mma_gemm<128,4,8,0,false,false>,
                         cudaFuncAttributeMaxDynamicSharedMemorySize, SM128);
    cudaFuncSetAttribute((const void*)mma_gemm<128,4,8,0,false,true>,
                         cudaFuncAttributeMaxDynamicSharedMemorySize, SM128);
    cudaFuncSetAttribute((const void*)mma_gemm<128,4,5,2,true,false>,
                         cudaFuncAttributeMaxDynamicSharedMemorySize, SM128);
    cudaFuncSetAttribute((const void*)mma_gemm<128,4,4,4,true,false>,
                         cudaFuncAttributeMaxDynamicSharedMemorySize, SM128);
    cudaFuncSetAttribute((const void*)mma_gemm<128,4,4,0,false,false>,
                         cudaFuncAttributeMaxDynamicSharedMemorySize, SM128);
    cudaFuncSetAttribute((const void*)mma_gemm<80,1,8,0,false,false>,
                         cudaFuncAttributeMaxDynamicSharedMemorySize, SM80);
    cudaFuncSetAttribute((const void*)fused_edge,
                         cudaFuncAttributeMaxDynamicSharedMemorySize, SMFUSE);

    // ---------- weight prep ----------
    { int t = NLAYERS*576*HIDD;   wsplit<<<(t+255)/256,256>>>(pe_w1, pe1hi, pe1lo, t); }
    { int t = NLAYERS*256*1024;   wsd_pack<<<(t+255)/256,256>>>(pe_w1, wsdhi, wsdlo); }
    { int t = NLAYERS*HIDD*EDGE_D;wsplit<<<(t+255)/256,256>>>(pe_w2, pe2hi, pe2lo, t); }
    { int t = NLAYERS*320*HIDD;   wsplit<<<(t+255)/256,256>>>(pn_w1, pn1hi, pn1lo, t); }
    { int t = NLAYERS*HIDD*NODE_D;wsplit<<<(t+255)/256,256>>>(pn_w2, pn2hi, pn2lo, t); }
    { int t = NODE_D*HIDD;        wsplit<<<(t+255)/256,256>>>(dec_w1, dc1hi, dc1lo, t); }
    { int t = HIDD*NODE_D;        wsplit<<<(t+255)/256,256>>>(enc_w2, en2hi, en2lo, t); }
    wpad80<<<(512*80+255)/256,256>>>(dec_w2, dc2hi, dc2lo);
    bpad80<<<1,80>>>(dec_b2, dcb2p);

    // ---------- encoder ----------
    {
        int total = NBATCH * NMESH * ENC_LDA;
        build_encin<<<(total + 255) / 256, 256>>>(xc, xp, geo, g2m, encin);
    }
    sgemm_bias<128,128,16,8,8><<<gemm_grid(NBATCH*NMESH, HIDD, 128, 128), 256>>>(
        encin, ENC_LDA, enc_w1, enc_b1, nullptr, h, NBATCH*NMESH, HIDD, ENC_IN, 1);
    mma_gemm<128,4,8,0,false,false><<<dim3(2, (NBATCH*NMESH + 127)/128), 256, SM128>>>(
        h, nullptr, nullptr, en2hi, en2lo, enc_b2, nullptr, x,
        NBATCH*NMESH, NODE_D, NODE_D, NODE_D);

    // ---------- edge embedder (shared across batches) ----------
    sgemm_bias<128,64,16,8,4><<<gemm_grid(NEDGE, EDGE_D, 128, 64), 256>>>(
        redge, 4, eme_w1, eme_b1, nullptr, h, NEDGE, EDGE_D, 4, 1);
    sgemm_bias<128,64,16,8,4><<<gemm_grid(NEDGE, EDGE_D, 128, 64), 256>>>(
        h, EDGE_D, eme_w2, eme_b2, nullptr, e0, NEDGE, EDGE_D, EDGE_D, 0);

    // ---------- GNN layers (both batches per launch) ----------
    const int MN = NBATCH * NMESH;   // 20484
    for (int l = 0; l < NLAYERS; l++) {
        const float* ein = (l == 0) ? e0 : e;
        size_t einStride = (l == 0) ? 0 : (size_t)NEDGE * EDGE_D;

        // xsd = x @ [Wsrc | Wdst]  (M=20484, K=256, N=1024)
        mma_gemm<128,4,4,0,false,false><<<dim3(8, (MN+127)/128), 256, SM128>>>(
            x, nullptr, nullptr,
            wsdhi + (size_t)l*256*1024, wsdlo + (size_t)l*256*1024,
            zeros, nullptr, xsd, MN, 1024, 1024, 1024);

        cudaMemsetAsync(agg, 0, (size_t)NBATCH * NMESH * EDGE_D * sizeof(float), 0);

        // fused edge MLP for both batches
        fused_edge<<<dim3(NEDGE/128, NBATCH), 256, SMFUSE>>>(
            ein, xsd, src, dst,
            pe1hi + (size_t)l*576*HIDD, pe1lo + (size_t)l*576*HIDD,
            pe2hi + (size_t)l*HIDD*EDGE_D, pe2lo + (size_t)l*HIDD*EDGE_D,
            pe_b1 + (size_t)l*HIDD, pe_b2 + (size_t)l*EDGE_D,
            e, agg, einStride);

        // node MLP1: [x | agg] @ W1 + b, relu  (M=20484)
        mma_gemm<128,4,5,2,true,false><<<dim3(4, (MN+127)/128), 256, SM128>>>(
            x, agg, nullptr,
            pn1hi + (size_t)l*320*HIDD, pn1lo + (size_t)l*320*HIDD,
            pn_b1 + (size_t)l*HIDD, nullptr, h, MN, HIDD, HIDD, HIDD);
        // node MLP2: h @ W2 + b + x (in place, M=20484)
        mma_gemm<128,4,8,0,false,true><<<dim3(2, (MN+127)/128), 256, SM128>>>(
            h, nullptr, nullptr,
            pn2hi + (size_t)l*HIDD*NODE_D, pn2lo + (size_t)l*HIDD*NODE_D,
            pn_b2 + (size_t)l*NODE_D, x, x, MN, NODE_D, NODE_D, NODE_D);
    }

    // ---------- decoder ----------
    // MLP1, both batches: gather x[m2g[g%NGRID] + (g/NGRID)*NMESH]
    mma_gemm<128,4,4,4,true,false><<<dim3(4, (NBATCH*NGRID+127)/128), 256, SM128>>>(
        x, nullptr, m2g,
        dc1hi, dc1lo, dec_b1, nullptr,
        h, NBATCH*NGRID, HIDD, HIDD, HIDD);
    // MLP2 on HMMA (N padded 78->80, clipped on store)
    mma_gemm<80,1,8,0,false,false><<<dim3(1, (NBATCH*NGRID + 127)/128), 256, SM80>>>(
        h, nullptr, nullptr, dc2hi, dc2lo, dcb2p, nullptr, out,
        NBATCH*NGRID, 80, 78, 78);
}

// round 8
// speedup vs baseline: 9.7032x; 1.0282x over previous
#include <cuda_runtime.h>
#include <cuda_bf16.h>
#include <cstdint>

// ---------------- problem constants ----------------
#define NLAT   181
#define NLON   360
#define NV     78
#define NGRID  (NLAT*NLON)      // 65160
#define NBATCH 2
#define NMESH  10242
#define NEDGE  163840
#define NODE_D 256
#define EDGE_D 64
#define HIDD   512
#define NLAYERS 16
#define ENC_IN  163
#define ENC_LDA 164

// ---------------- device scratch ----------------
__device__ float g_encin[(size_t)NBATCH*NMESH*ENC_LDA];
__device__ float g_x    [(size_t)NBATCH*NMESH*NODE_D];
__device__ float g_e    [(size_t)NBATCH*NEDGE*EDGE_D];
__device__ float g_e0   [(size_t)NEDGE*EDGE_D];
__device__ float g_h    [(size_t)NEDGE*HIDD];
__device__ float g_agg  [(size_t)NBATCH*NMESH*EDGE_D];
__device__ float g_xsd  [(size_t)NBATCH*NMESH*1024];
__device__ float g_zeros[1024];
__device__ float g_dcb2p[80];
// edge sort (dst-sorted order; edge state lives in sorted space forever)
__device__ int   g_cnt  [NMESH];
__device__ int   g_off  [NMESH];
__device__ int   g_srcS [NEDGE];
__device__ int   g_dstS [NEDGE];
__device__ float g_redgeS[(size_t)NEDGE*4];
// bf16 hi/lo split weights
__device__ __nv_bfloat16 g_pe1hi[(size_t)NLAYERS*576*HIDD];
__device__ __nv_bfloat16 g_pe1lo[(size_t)NLAYERS*576*HIDD];
__device__ __nv_bfloat16 g_wsdhi[(size_t)NLAYERS*256*1024];
__device__ __nv_bfloat16 g_wsdlo[(size_t)NLAYERS*256*1024];
__device__ __nv_bfloat16 g_pe2hi[(size_t)NLAYERS*HIDD*EDGE_D];
__device__ __nv_bfloat16 g_pe2lo[(size_t)NLAYERS*HIDD*EDGE_D];
__device__ __nv_bfloat16 g_pn1hi[(size_t)NLAYERS*320*HIDD];
__device__ __nv_bfloat16 g_pn1lo[(size_t)NLAYERS*320*HIDD];
__device__ __nv_bfloat16 g_pn2hi[(size_t)NLAYERS*HIDD*NODE_D];
__device__ __nv_bfloat16 g_pn2lo[(size_t)NLAYERS*HIDD*NODE_D];
__device__ __nv_bfloat16 g_dc1hi[(size_t)NODE_D*HIDD];
__device__ __nv_bfloat16 g_dc1lo[(size_t)NODE_D*HIDD];
__device__ __nv_bfloat16 g_dc2hi[(size_t)HIDD*80];
__device__ __nv_bfloat16 g_dc2lo[(size_t)HIDD*80];
__device__ __nv_bfloat16 g_en2hi[(size_t)HIDD*NODE_D];
__device__ __nv_bfloat16 g_en2lo[(size_t)HIDD*NODE_D];

// ---------------- asm helpers ----------------
__device__ __forceinline__ void ldsm_x4(uint32_t* r, uint32_t addr) {
    asm volatile("ldmatrix.sync.aligned.m8n8.x4.shared.b16 {%0,%1,%2,%3}, [%4];"
        : "=r"(r[0]), "=r"(r[1]), "=r"(r[2]), "=r"(r[3]) : "r"(addr));
}
__device__ __forceinline__ void ldsm_x4t(uint32_t* r, uint32_t addr) {
    asm volatile("ldmatrix.sync.aligned.m8n8.x4.trans.shared.b16 {%0,%1,%2,%3}, [%4];"
        : "=r"(r[0]), "=r"(r[1]), "=r"(r[2]), "=r"(r[3]) : "r"(addr));
}
__device__ __forceinline__ void mma16816(float* d, const uint32_t* a, const uint32_t* b) {
    asm volatile("mma.sync.aligned.m16n8k16.row.col.f32.bf16.bf16.f32 "
        "{%0,%1,%2,%3}, {%4,%5,%6,%7}, {%8,%9}, {%0,%1,%2,%3};"
        : "+f"(d[0]), "+f"(d[1]), "+f"(d[2]), "+f"(d[3])
        : "r"(a[0]), "r"(a[1]), "r"(a[2]), "r"(a[3]), "r"(b[0]), "r"(b[1]));
}
__device__ __forceinline__ uint32_t smem_u32(const void* p) {
    uint32_t a;
    asm("{ .reg .u64 t; cvta.to.shared.u64 t, %1; cvt.u32.u64 %0, t; }" : "=r"(a) : "l"(p));
    return a;
}
#define CP_ASYNC16(dst, src) \
    asm volatile("cp.async.cg.shared.global [%0], [%1], 16;" :: "r"(dst), "l"(src))
#define CP_COMMIT() asm volatile("cp.async.commit_group;" ::: "memory")
#define CP_WAIT0()  asm volatile("cp.async.wait_group 0;" ::: "memory")
#define STS_V2(addr, x, y) \
    asm volatile("st.shared.v2.u32 [%0], {%1,%2};" :: "r"(addr), "r"(x), "r"(y))
#define STS_U32(addr, x) \
    asm volatile("st.shared.u32 [%0], %1;" :: "r"(addr), "r"(x))

__device__ __forceinline__ void split4(float4 v, uint2& hh, uint2& ll) {
    __nv_bfloat16 h0 = __float2bfloat16_rn(v.x), h1 = __float2bfloat16_rn(v.y);
    __nv_bfloat16 h2 = __float2bfloat16_rn(v.z), h3 = __float2bfloat16_rn(v.w);
    __nv_bfloat16 g0 = __float2bfloat16_rn(v.x - __bfloat162float(h0));
    __nv_bfloat16 g1 = __float2bfloat16_rn(v.y - __bfloat162float(h1));
    __nv_bfloat16 g2 = __float2bfloat16_rn(v.z - __bfloat162float(h2));
    __nv_bfloat16 g3 = __float2bfloat16_rn(v.w - __bfloat162float(h3));
    hh.x = (uint32_t)__bfloat16_as_ushort(h0) | ((uint32_t)__bfloat16_as_ushort(h1) << 16);
    hh.y = (uint32_t)__bfloat16_as_ushort(h2) | ((uint32_t)__bfloat16_as_ushort(h3) << 16);
    ll.x = (uint32_t)__bfloat16_as_ushort(g0) | ((uint32_t)__bfloat16_as_ushort(g1) << 16);
    ll.y = (uint32_t)__bfloat16_as_ushort(g2) | ((uint32_t)__bfloat16_as_ushort(g3) << 16);
}
__device__ __forceinline__ void split2(float vx, float vy, uint32_t& hp, uint32_t& lp) {
    __nv_bfloat16 hx = __float2bfloat16_rn(vx), hy = __float2bfloat16_rn(vy);
    __nv_bfloat16 lx = __float2bfloat16_rn(vx - __bfloat162float(hx));
    __nv_bfloat16 ly = __float2bfloat16_rn(vy - __bfloat162float(hy));
    hp = (uint32_t)__bfloat16_as_ushort(hx) | ((uint32_t)__bfloat16_as_ushort(hy) << 16);
    lp = (uint32_t)__bfloat16_as_ushort(lx) | ((uint32_t)__bfloat16_as_ushort(ly) << 16);
}

// ---------------- A-gather modes ----------------
// MODE 0: plain A[M][K]
// MODE 2: [x(256)|agg(64)]
// MODE 4: gathered rows A[m2g[g%NGRID] + (g/NGRID)*NMESH][256]
template<int MODE>
__device__ __forceinline__ void prefA(float4 (&Ra)[8], int c, int rowBase, int M,
    const float* __restrict__ A, const float* __restrict__ aux,
    const int (&sI)[8], int tid, int K)
{
    const int f = tid & 15;
    #pragma unroll
    for (int it = 0; it < 8; it++) {
        int gr = rowBase + it * 16 + (tid >> 4);
        if (gr < M) {
            const float* p;
            if (MODE == 0)      p = A + (size_t)gr * K + c * 64;
            else if (MODE == 2) p = (c < 4) ? A + (size_t)gr * 256 + c * 64
                                            : aux + (size_t)gr * 64;
            else                p = A + (size_t)sI[it] * 256 + c * 64;
            Ra[it] = reinterpret_cast<const float4*>(p)[f];
        } else {
            Ra[it] = make_float4(0.f, 0.f, 0.f, 0.f);
        }
    }
}

// =====================================================================
//  HMMA GEMM: C[M x Nclip (pitch Cpitch)] = [res+] relu?(gather(A)@W + bias)
// =====================================================================
template<int BN, int WARPS_N, int NC, int MODE, bool RELU, bool HAS_RES>
__global__ void __launch_bounds__(256)
mma_gemm(const float* __restrict__ A, const float* __restrict__ aux,
         const int* __restrict__ idx1,
         const __nv_bfloat16* __restrict__ Bhi, const __nv_bfloat16* __restrict__ Blo,
         const float* __restrict__ bias, const float* res, float* C,
         int M, int Nfull, int Cpitch, int Nclip)
{
    constexpr int K       = NC * 64;
    constexpr int WARPS_M = 8 / WARPS_N;
    constexpr int WTM     = 128 / WARPS_M;
    constexpr int WTN     = BN / WARPS_N;
    constexpr int MT      = WTM / 16;
    constexpr int NT      = WTN / 8;
    constexpr int ASTRIDE = 72;
    constexpr int APLANE  = 128 * ASTRIDE * 2;
    constexpr int ABUF    = 2 * APLANE;
    constexpr int BSTRIDE = BN + 8;
    constexpr int BPLANE  = 64 * BSTRIDE * 2;
    constexpr int BBUF    = 2 * BPLANE;
    constexpr int GRAN    = BN / 8;
    constexpr int BTOT    = 2 * 64 * GRAN;

    extern __shared__ char sm[];
    const uint32_t smA = smem_u32(sm);
    const uint32_t smB = smA + 2 * ABUF;

    const int tid    = threadIdx.x;
    const int lane   = tid & 31;
    const int wid    = tid >> 5;
    const int warp_n = wid % WARPS_N;
    const int warp_m = wid / WARPS_N;
    const int rowBase = blockIdx.y * 128;
    const int colBase = blockIdx.x * BN;

    int sI[8];
    #pragma unroll
    for (int it = 0; it < 8; it++) {
        int gr = rowBase + it * 16 + (tid >> 4);
        int g  = (gr < M) ? gr : 0;
        if (MODE == 4) {
            int b = g / NGRID;
            sI[it] = idx1[g - b * NGRID] + b * NMESH;
        } else {
            sI[it] = 0;
        }
    }

    float acc[MT][NT][4];
    #pragma unroll
    for (int i = 0; i < MT; i++)
        #pragma unroll
        for (int j = 0; j < NT; j++)
            #pragma unroll
            for (int q = 0; q < 4; q++) acc[i][j][q] = 0.f;

    float4 Ra[8];
    prefA<MODE>(Ra, 0, rowBase, M, A, aux, sI, tid, K);

    {
        #pragma unroll
        for (int it = 0; it < BTOT / 256; it++) {
            int i = it * 256 + tid;
            int plane = i / (64 * GRAN);
            int rem   = i % (64 * GRAN);
            int k = rem / GRAN, g = rem % GRAN;
            const __nv_bfloat16* sp = (plane ? Blo : Bhi)
                + (size_t)k * Nfull + colBase + g * 8;
            CP_ASYNC16(smB + plane * BPLANE + (uint32_t)(k * BSTRIDE + g * 8) * 2, sp);
        }
        CP_COMMIT();
    }

    for (int c = 0; c < NC; c++) {
        const int buf = c & 1;
        #pragma unroll
        for (int it = 0; it < 8; it++) {
            int r = it * 16 + (tid >> 4);
            int f = tid & 15;
            uint2 hh, ll;
            split4(Ra[it], hh, ll);
            uint32_t off = smA + buf * ABUF + (uint32_t)(r * ASTRIDE + f * 4) * 2;
            STS_V2(off, hh.x, hh.y);
            STS_V2(off + APLANE, ll.x, ll.y);
        }
        if (c + 1 < NC) prefA<MODE>(Ra, c + 1, rowBase, M, A, aux, sI, tid, K);
        CP_WAIT0();
        __syncthreads();
        if (c + 1 < NC) {
            #pragma unroll
            for (int it = 0; it < BTOT / 256; it++) {
                int i = it * 256 + tid;
                int plane = i / (64 * GRAN);
                int rem   = i % (64 * GRAN);
                int k = rem / GRAN, g = rem % GRAN;
                const __nv_bfloat16* sp = (plane ? Blo : Bhi)
                    + (size_t)(c + 1) * 64 * Nfull + (size_t)k * Nfull + colBase + g * 8;
                CP_ASYNC16(smB + (1 - buf) * BBUF + plane * BPLANE
                           + (uint32_t)(k * BSTRIDE + g * 8) * 2, sp);
            }
            CP_COMMIT();
        }

        #pragma unroll
        for (int ks = 0; ks < 4; ks++) {
            uint32_t Ah[MT][4], Al[MT][4];
            #pragma unroll
            for (int mt = 0; mt < MT; mt++) {
                uint32_t addr = smA + buf * ABUF
                    + (uint32_t)((warp_m * WTM + mt * 16 + (lane & 15)) * ASTRIDE
                                 + ks * 16 + (lane >> 4) * 8) * 2;
                ldsm_x4(Ah[mt], addr);
                ldsm_x4(Al[mt], addr + APLANE);
            }
            uint32_t Bh[NT / 2][4], Bl[NT / 2][4];
            #pragma unroll
            for (int np = 0; np < NT / 2; np++) {
                uint32_t addr = smB + buf * BBUF
                    + (uint32_t)((ks * 16 + (lane & 15)) * BSTRIDE
                                 + warp_n * WTN + np * 16 + (lane >> 4) * 8) * 2;
                ldsm_x4t(Bh[np], addr);
                ldsm_x4t(Bl[np], addr + BPLANE);
            }
            #pragma unroll
            for (int mt = 0; mt < MT; mt++)
                #pragma unroll
                for (int nt = 0; nt < NT; nt++) {
                    const uint32_t* bh = &Bh[nt >> 1][(nt & 1) * 2];
                    const uint32_t* bl = &Bl[nt >> 1][(nt & 1) * 2];
                    mma16816(acc[mt][nt], Ah[mt], bh);
                    mma16816(acc[mt][nt], Ah[mt], bl);
                    mma16816(acc[mt][nt], Al[mt], bh);
                }
        }
    }

    #pragma unroll
    for (int nt = 0; nt < NT; nt++) {
        int n = colBase + warp_n * WTN + nt * 8 + (lane & 3) * 2;
        if (n >= Nclip) continue;
        float2 bb = *reinterpret_cast<const float2*>(bias + n);
        #pragma unroll
        for (int mt = 0; mt < MT; mt++) {
            #pragma unroll
            for (int half = 0; half < 2; half++) {
                int row = rowBase + warp_m * WTM + mt * 16 + (lane >> 2) + half * 8;
                if (row < M) {
                    float vx = acc[mt][nt][half * 2 + 0] + bb.x;
                    float vy = acc[mt][nt][half * 2 + 1] + bb.y;
                    size_t off = (size_t)row * Cpitch + n;
                    if (HAS_RES) {
                        float2 rr = *reinterpret_cast<const float2*>(res + off);
                        vx += rr.x; vy += rr.y;
                    }
                    if (RELU) { vx = fmaxf(vx, 0.f); vy = fmaxf(vy, 0.f); }
                    float2 o; o.x = vx; o.y = vy;
                    *reinterpret_cast<float2*>(C + off) = o;
                }
            }
        }
    }
}

// =====================================================================
//  Fused edge layer (batched via blockIdx.y, edges dst-sorted):
//  hidden = relu(e@We + b1 + xs[src] + xd[dst])  (chunks of 128 cols, smem)
//  eout   = ein + hidden @ W2 + b2 ;  agg[dst] += eout (segmented reduce)
// =====================================================================
__global__ void __launch_bounds__(256)
fused_edge(const float* __restrict__ ein,
           const float* __restrict__ xsd,
           const int* __restrict__ src, const int* __restrict__ dst,
           const __nv_bfloat16* __restrict__ W1hi, const __nv_bfloat16* __restrict__ W1lo,
           const __nv_bfloat16* __restrict__ W2hi, const __nv_bfloat16* __restrict__ W2lo,
           const float* __restrict__ b1, const float* __restrict__ b2,
           float* __restrict__ eout, float* __restrict__ agg,
           size_t einBatchStride)
{
    constexpr int A_STR  = 72;
    constexpr int A_PL   = 128 * A_STR * 2;
    constexpr int OFF_A  = 0;
    constexpr int B1_STR = 136;
    constexpr int B1_PL  = 64 * B1_STR * 2;
    constexpr int OFF_B1 = 2 * A_PL;
    constexpr int H_STR  = 136;
    constexpr int H_PL   = 128 * H_STR * 2;
    constexpr int OFF_H  = OFF_B1 + 2 * B1_PL;
    constexpr int B2_STR = 72;
    constexpr int B2_PL  = 128 * B2_STR * 2;
    constexpr int OFF_B2 = OFF_H + 2 * H_PL;   // total 178176

    extern __shared__ char sm[];
    const uint32_t base = smem_u32(sm);

    const int tid  = threadIdx.x;
    const int lane = tid & 31;
    const int wid  = tid >> 5;
    const int warp_m = wid >> 1;
    const int warp_n = wid & 1;
    const int rowBase = blockIdx.x * 128;
    const int batch   = blockIdx.y;

    const float* einb = ein + (size_t)batch * einBatchStride;
    const float* xsdb = xsd + (size_t)batch * NMESH * 1024;
    float* eoutb = eout + (size_t)batch * NEDGE * EDGE_D;
    float* aggb  = agg  + (size_t)batch * NMESH * EDGE_D;

    int sidx[2][2], didx[2][2];
    #pragma unroll
    for (int mt = 0; mt < 2; mt++)
        #pragma unroll
        for (int half = 0; half < 2; half++) {
            int g = rowBase + warp_m * 32 + mt * 16 + (lane >> 2) + half * 8;
            sidx[mt][half] = src[g];
            didx[mt][half] = dst[g];
        }

    // ---- load e tile (128 x 64 fp32) into A smem hi/lo ----
    {
        const float4* E4 = reinterpret_cast<const float4*>(einb + (size_t)rowBase * 64);
        #pragma unroll
        for (int it = 0; it < 8; it++) {
            int i = tid + it * 256;
            int r = i >> 4, f = i & 15;
            float4 v = E4[r * 16 + f];
            uint2 hh, ll;
            split4(v, hh, ll);
            uint32_t off = base + OFF_A + (uint32_t)(r * A_STR + f * 4) * 2;
            STS_V2(off, hh.x, hh.y);
            STS_V2(off + A_PL, ll.x, ll.y);
        }
    }

    float acc2[2][4][4];
    #pragma unroll
    for (int i = 0; i < 2; i++)
        #pragma unroll
        for (int j = 0; j < 4; j++)
            #pragma unroll
            for (int q = 0; q < 4; q++) acc2[i][j][q] = 0.f;

    for (int nc = 0; nc < 4; nc++) {
        __syncthreads();
        // B1 chunk: We[0:64][nc*128 : +128], hi+lo
        #pragma unroll
        for (int it = 0; it < 8; it++) {
            int i = tid + it * 256;
            int plane = i >> 10;
            int rem = i & 1023;
            int k = rem >> 4, g = rem & 15;
            const __nv_bfloat16* sp = (plane ? W1lo : W1hi)
                + (size_t)k * 512 + nc * 128 + g * 8;
            CP_ASYNC16(base + OFF_B1 + plane * B1_PL + (uint32_t)(k * B1_STR + g * 8) * 2, sp);
        }
        // B2 chunk: W2[nc*128 : +128][0:64], hi+lo
        #pragma unroll
        for (int it = 0; it < 8; it++) {
            int i = tid + it * 256;
            int plane = i >> 10;
            int rem = i & 1023;
            int k = rem >> 3, g = rem & 7;
            const __nv_bfloat16* sp = (plane ? W2lo : W2hi)
                + (size_t)(nc * 128 + k) * 64 + g * 8;
            CP_ASYNC16(base + OFF_B2 + plane * B2_PL + (uint32_t)(k * B2_STR + g * 8) * 2, sp);
        }
        CP_COMMIT();
        CP_WAIT0();
        __syncthreads();

        // ---- stage 1: acc1 = e @ We_chunk (128x128, K=64) ----
        float acc1[2][8][4];
        #pragma unroll
        for (int i = 0; i < 2; i++)
            #pragma unroll
            for (int j = 0; j < 8; j++)
                #pragma unroll
                for (int q = 0; q < 4; q++) acc1[i][j][q] = 0.f;

        #pragma unroll
        for (int ks = 0; ks < 4; ks++) {
            uint32_t Ah[2][4], Al[2][4];
            #pragma unroll
            for (int mt = 0; mt < 2; mt++) {
                uint32_t addr = base + OFF_A
                    + (uint32_t)((warp_m * 32 + mt * 16 + (lane & 15)) * A_STR
                                 + ks * 16 + (lane >> 4) * 8) * 2;
                ldsm_x4(Ah[mt], addr);
                ldsm_x4(Al[mt], addr + A_PL);
            }
            uint32_t Bh[4][4], Bl[4][4];
            #pragma unroll
            for (int np = 0; np < 4; np++) {
                uint32_t addr = base + OFF_B1
                    + (uint32_t)((ks * 16 + (lane & 15)) * B1_STR
                                 + warp_n * 64 + np * 16 + (lane >> 4) * 8) * 2;
                ldsm_x4t(Bh[np], addr);
                ldsm_x4t(Bl[np], addr + B1_PL);
            }
            #pragma unroll
            for (int mt = 0; mt < 2; mt++)
                #pragma unroll
                for (int nt = 0; nt < 8; nt++) {
                    const uint32_t* bh = &Bh[nt >> 1][(nt & 1) * 2];
                    const uint32_t* bl = &Bl[nt >> 1][(nt & 1) * 2];
                    mma16816(acc1[mt][nt], Ah[mt], bh);
                    mma16816(acc1[mt][nt], Ah[mt], bl);
                    mma16816(acc1[mt][nt], Al[mt], bh);
                }
        }

        // ---- stage1 epilogue: + b1 + xs[src] + xd[dst], relu, -> H smem ----
        #pragma unroll
        for (int nt = 0; nt < 8; nt++) {
            int col  = warp_n * 64 + nt * 8 + (lane & 3) * 2;
            int gcol = nc * 128 + col;
            float2 bb = *reinterpret_cast<const float2*>(b1 + gcol);
            #pragma unroll
            for (int mt = 0; mt < 2; mt++) {
                #pragma unroll
                for (int half = 0; half < 2; half++) {
                    int row_l = warp_m * 32 + mt * 16 + (lane >> 2) + half * 8;
                    float2 sv = *reinterpret_cast<const float2*>(
                        xsdb + (size_t)sidx[mt][half] * 1024 + gcol);
                    float2 dv = *reinterpret_cast<const float2*>(
                        xsdb + (size_t)didx[mt][half] * 1024 + 512 + gcol);
                    float vx = fmaxf(acc1[mt][nt][half * 2 + 0] + bb.x + sv.x + dv.x, 0.f);
                    float vy = fmaxf(acc1[mt][nt][half * 2 + 1] + bb.y + sv.y + dv.y, 0.f);
                    uint32_t hp, lp;
                    split2(vx, vy, hp, lp);
                    uint32_t off = base + OFF_H + (uint32_t)(row_l * H_STR + col) * 2;
                    STS_U32(off, hp);
                    STS_U32(off + H_PL, lp);
                }
            }
        }
        __syncthreads();

        // ---- stage 2: acc2 += hidden_chunk @ W2_chunk (K=128) ----
        #pragma unroll
        for (int ks = 0; ks < 8; ks++) {
            uint32_t Ah[2][4], Al[2][4];
            #pragma unroll
            for (int mt = 0; mt < 2; mt++) {
                uint32_t addr = base + OFF_H
                    + (uint32_t)((warp_m * 32 + mt * 16 + (lane & 15)) * H_STR
                                 + ks * 16 + (lane >> 4) * 8) * 2;
                ldsm_x4(Ah[mt], addr);
                ldsm_x4(Al[mt], addr + H_PL);
            }
            uint32_t Bh[2][4], Bl[2][4];
            #pragma unroll
            for (int np = 0; np < 2; np++) {
                uint32_t addr = base + OFF_B2
                    + (uint32_t)((ks * 16 + (lane & 15)) * B2_STR
                                 + warp_n * 32 + np * 16 + (lane >> 4) * 8) * 2;
                ldsm_x4t(Bh[np], addr);
                ldsm_x4t(Bl[np], addr + B2_PL);
            }
            #pragma unroll
            for (int mt = 0; mt < 2; mt++)
                #pragma unroll
                for (int nt = 0; nt < 4; nt++) {
                    const uint32_t* bh = &Bh[nt >> 1][(nt & 1) * 2];
                    const uint32_t* bl = &Bl[nt >> 1][(nt & 1) * 2];
                    mma16816(acc2[mt][nt], Ah[mt], bh);
                    mma16816(acc2[mt][nt], Ah[mt], bl);
                    mma16816(acc2[mt][nt], Al[mt], bh);
                }
        }
    }

    // ---- final epilogue: + b2 + ein residual, write e; stage in smem ----
    float* stage = reinterpret_cast<float*>(sm);          // over A region (33280 B)
    int*   sdst  = reinterpret_cast<int*>(sm + 33280);    // 512 B
    if (tid < 128) sdst[tid] = dst[rowBase + tid];

    #pragma unroll
    for (int nt = 0; nt < 4; nt++) {
        int n = warp_n * 32 + nt * 8 + (lane & 3) * 2;
        float2 bb = *reinterpret_cast<const float2*>(b2 + n);
        #pragma unroll
        for (int mt = 0; mt < 2; mt++) {
            #pragma unroll
            for (int half = 0; half < 2; half++) {
                int row_l = warp_m * 32 + mt * 16 + (lane >> 2) + half * 8;
                size_t off = (size_t)(rowBase + row_l) * 64 + n;
                float2 rr = *reinterpret_cast<const float2*>(einb + off);
                float vx = acc2[mt][nt][half * 2 + 0] + bb.x + rr.x;
                float vy = acc2[mt][nt][half * 2 + 1] + bb.y + rr.y;
                float2 o; o.x = vx; o.y = vy;
                *reinterpret_cast<float2*>(eoutb + off) = o;
                stage[row_l * 65 + n]     = vx;
                stage[row_l * 65 + n + 1] = vy;
            }
        }
    }
    __syncthreads();

    // ---- segmented reduction over dst-sorted rows, then few atomics ----
    {
        int col = tid & 63;
        int seg = tid >> 6;        // 0..3, 32 rows each
        int r0  = seg * 32;
        float sum = 0.f;
        int cur = sdst[r0];
        for (int r = r0; r < r0 + 32; r++) {
            int d  = sdst[r];
            float v = stage[r * 65 + col];
            if (d != cur) {
                atomicAdd(aggb + (size_t)cur * 64 + col, sum);
                sum = 0.f;
                cur = d;
            }
            sum += v;
        }
        atomicAdd(aggb + (size_t)cur * 64 + col, sum);
    }
}

// =====================================================================
//  Weight prep — single kernel (split + repack + pads + cnt zero)
// =====================================================================
__device__ __forceinline__ void splitStore(float v, __nv_bfloat16* hi,
                                           __nv_bfloat16* lo, int i) {
    __nv_bfloat16 h = __float2bfloat16_rn(v);
    hi[i] = h;
    lo[i] = __float2bfloat16_rn(v - __bfloat162float(h));
}

#define T_PE1 (NLAYERS*576*HIDD)      // 4718592
#define T_WSD (NLAYERS*256*1024)      // 4194304
#define T_PE2 (NLAYERS*HIDD*EDGE_D)   // 524288
#define T_PN1 (NLAYERS*320*HIDD)      // 2621440
#define T_PN2 (NLAYERS*HIDD*NODE_D)   // 2097152
#define T_DC1 (NODE_D*HIDD)           // 131072
#define T_EN2 (HIDD*NODE_D)           // 131072
#define T_DC2 (HIDD*80)               // 40960
#define T_ALL (T_PE1+T_WSD+T_PE2+T_PN1+T_PN2+T_DC1+T_EN2+T_DC2+80+NMESH)

__global__ void prep_all(const float* __restrict__ pe_w1, const float* __restrict__ pe_w2,
                         const float* __restrict__ pn_w1, const float* __restrict__ pn_w2,
                         const float* __restrict__ dec_w1, const float* __restrict__ enc_w2,
                         const float* __restrict__ dec_w2, const float* __restrict__ dec_b2)
{
    int i = blockIdx.x * blockDim.x + threadIdx.x;
    if (i < T_PE1) { splitStore(pe_w1[i], g_pe1hi, g_pe1lo, i); return; }
    i -= T_PE1;
    if (i < T_WSD) {
        int l = i >> 18, rem = i & 262143;
        int r = rem >> 10, n = rem & 1023;
        int srow = (n < 512) ? (64 + r) : (320 + r);
        float v = pe_w1[(size_t)l * 576 * 512 + (size_t)srow * 512 + (n & 511)];
        splitStore(v, g_wsdhi, g_wsdlo, i);
        return;
    }
    i -= T_WSD;
    if (i < T_PE2) { splitStore(pe_w2[i], g_pe2hi, g_pe2lo, i); return; }
    i -= T_PE2;
    if (i < T_PN1) { splitStore(pn_w1[i], g_pn1hi, g_pn1lo, i); return; }
    i -= T_PN1;
    if (i < T_PN2) { splitStore(pn_w2[i], g_pn2hi, g_pn2lo, i); return; }
    i -= T_PN2;
    if (i < T_DC1) { splitStore(dec_w1[i], g_dc1hi, g_dc1lo, i); return; }
    i -= T_DC1;
    if (i < T_EN2) { splitStore(enc_w2[i], g_en2hi, g_en2lo, i); return; }
    i -= T_EN2;
    if (i < T_DC2) {
        int k = i / 80, n = i % 80;
        splitStore((n < 78) ? dec_w2[k * 78 + n] : 0.f, g_dc2hi, g_dc2lo, i);
        return;
    }
    i -= T_DC2;
    if (i < 80) { g_dcb2p[i] = (i < 78) ? dec_b2[i] : 0.f; return; }
    i -= 80;
    if (i < NMESH) g_cnt[i] = 0;
}

// =====================================================================
//  Edge counting sort (by dst) — indices constant, run once per launch
// =====================================================================
__global__ void sort_hist(const int* __restrict__ dst) {
    int j = blockIdx.x * blockDim.x + threadIdx.x;
    if (j < NEDGE) atomicAdd(&g_cnt[dst[j]], 1);
}

__global__ void __launch_bounds__(1024) sort_scan() {
    __shared__ int part[1024];
    const int tid = threadIdx.x;
    const int PER = (NMESH + 1023) / 1024;   // 11
    int local[11];
    int s = 0;
    #pragma unroll
    for (int i = 0; i < PER; i++) {
        int b = tid * PER + i;
        int c = (b < NMESH) ? g_cnt[b] : 0;
        local[i] = s;
        s += c;
    }
    part[tid] = s;
    __syncthreads();
    for (int off = 1; off < 1024; off <<= 1) {
        int v = (tid >= off) ? part[tid - off] : 0;
        __syncthreads();
        part[tid] += v;
        __syncthreads();
    }
    int excl = (tid == 0) ? 0 : part[tid - 1];
    #pragma unroll
    for (int i = 0; i < PER; i++) {
        int b = tid * PER + i;
        if (b < NMESH) g_off[b] = excl + local[i];
    }
}

__global__ void sort_scatter(const int* __restrict__ src, const int* __restrict__ dst,
                             const float* __restrict__ redge) {
    int j = blockIdx.x * blockDim.x + threadIdx.x;
    if (j >= NEDGE) return;
    int d = dst[j];
    int pos = atomicAdd(&g_off[d], 1);
    g_srcS[pos] = src[j];
    g_dstS[pos] = d;
    float4 rv = reinterpret_cast<const float4*>(redge)[j];
    reinterpret_cast<float4*>(g_redgeS)[pos] = rv;
}

// =====================================================================
//  SIMT fp32 GEMM (encoder MLP1, embedder)
// =====================================================================
template<int BM, int BN, int BK, int TM, int TN>
__global__ void __launch_bounds__(256)
sgemm_bias(const float* __restrict__ A, int lda,
           const float* __restrict__ W,
           const float* __restrict__ bias,
           const float* res, float* C,
           int M, int N, int K, int doRelu)
{
    constexpr int GN      = TN / 4;
    constexpr int CSTRIDE = BN / GN;
    constexpr int NTC     = BN / TN;
    constexpr int THREADS = (BM / TM) * NTC;
    static_assert(THREADS == 256, "expect 256 threads");
    static_assert(BK == 16 && THREADS == BM * 2, "A loader mapping");

    __shared__ float As[BK][BM + 4];
    __shared__ float Bs[BK][BN];

    const int tid  = threadIdx.x;
    const int tcol = tid % NTC;
    const int trow = tid / NTC;
    const int rowBase = blockIdx.y * BM;
    const int colBase = blockIdx.x * BN;

    float acc[TM][TN];
    #pragma unroll
    for (int i = 0; i < TM; i++)
        #pragma unroll
        for (int j = 0; j < TN; j++) acc[i][j] = 0.f;

    const int am = tid >> 1;
    const int ah = (tid & 1) * 8;

    for (int k0 = 0; k0 < K; k0 += BK) {
        {
            const int gm = rowBase + am;
            const bool mok = (gm < M);
            const float* Arow = A + (size_t)gm * lda + (k0 + ah);
            #pragma unroll
            for (int i = 0; i < 8; i++) {
                int gk = k0 + ah + i;
                As[ah + i][am] = (mok && gk < K) ? Arow[i] : 0.f;
            }
        }
        #pragma unroll
        for (int it = 0; it < (BK * BN) / THREADS; it++) {
            int idx = tid + it * THREADS;
            int k = idx / BN, n = idx % BN;
            int gk = k0 + k, gn = colBase + n;
            Bs[k][n] = (gk < K && gn < N) ? W[(size_t)gk * N + gn] : 0.f;
        }
        __syncthreads();

        #pragma unroll
        for (int k = 0; k < BK; k++) {
            float ra[TM], rb[TN];
            #pragma unroll
            for (int i = 0; i < TM; i++) ra[i] = As[k][trow * TM + i];
            #pragma unroll
            for (int cg = 0; cg < GN; cg++)
                #pragma unroll
                for (int j = 0; j < 4; j++)
                    rb[cg * 4 + j] = Bs[k][cg * CSTRIDE + tcol * 4 + j];
            #pragma unroll
            for (int i = 0; i < TM; i++)
                #pragma unroll
                for (int j = 0; j < TN; j++)
                    acc[i][j] = fmaf(ra[i], rb[j], acc[i][j]);
        }
        __syncthreads();
    }

    #pragma unroll
    for (int i = 0; i < TM; i++) {
        int gm = rowBase + trow * TM + i;
        if (gm >= M) continue;
        #pragma unroll
        for (int cg = 0; cg < GN; cg++) {
            #pragma unroll
            for (int j = 0; j < 4; j++) {
                int gn = colBase + cg * CSTRIDE + tcol * 4 + j;
                if (gn >= N) continue;
                float v = acc[i][cg * 4 + j] + bias[gn];
                if (doRelu) v = fmaxf(v, 0.f);
                size_t off = (size_t)gm * N + gn;
                if (res) v += res[off];
                C[off] = v;
            }
        }
    }
}

// ---------------- builders ----------------
__global__ void build_encin(const float* __restrict__ xc, const float* __restrict__ xp,
                            const float* __restrict__ geo, const int* __restrict__ g2m,
                            float* __restrict__ out)
{
    int idx = blockIdx.x * blockDim.x + threadIdx.x;
    const int total = NBATCH * NMESH * ENC_LDA;
    if (idx >= total) return;
    int row = idx / ENC_LDA;
    int c   = idx - row * ENC_LDA;
    int b   = row / NMESH;
    int m   = row - b * NMESH;
    float v = 0.f;
    if (c < NV)            v = xc[((size_t)b * NGRID + g2m[m]) * NV + c];
    else if (c < 2 * NV)   v = xp[((size_t)b * NGRID + g2m[m]) * NV + (c - NV)];
    else if (c < ENC_IN)   v = geo[m * 7 + (c - 2 * NV)];
    out[idx] = v;
}

// ---------------- launcher ----------------
static inline dim3 gemm_grid(int M, int N, int BM, int BN) {
    return dim3((unsigned)((N + BN - 1) / BN), (unsigned)((M + BM - 1) / BM));
}

extern "C" void kernel_launch(void* const* d_in, const int* in_sizes, int n_in,
                              void* d_out, int out_size)
{
    const float* xc     = (const float*)d_in[0];
    const float* xp     = (const float*)d_in[1];
    const float* geo    = (const float*)d_in[2];
    const float* redge  = (const float*)d_in[3];
    const int*   eidx   = (const int*)  d_in[4];
    const int*   g2m    = (const int*)  d_in[5];
    const int*   m2g    = (const int*)  d_in[6];
    const float* enc_w1 = (const float*)d_in[7];
    const float* enc_b1 = (const float*)d_in[8];
    const float* enc_w2 = (const float*)d_in[9];
    const float* enc_b2 = (const float*)d_in[10];
    const float* eme_w1 = (const float*)d_in[11];
    const float* eme_b1 = (const float*)d_in[12];
    const float* eme_w2 = (const float*)d_in[13];
    const float* eme_b2 = (const float*)d_in[14];
    const float* pe_w1  = (const float*)d_in[15];
    const float* pe_b1  = (const float*)d_in[16];
    const float* pe_w2  = (const float*)d_in[17];
    const float* pe_b2  = (const float*)d_in[18];
    const float* pn_w1  = (const float*)d_in[19];
    const float* pn_b1  = (const float*)d_in[20];
    const float* pn_w2  = (const float*)d_in[21];
    const float* pn_b2  = (const float*)d_in[22];
    const float* dec_w1 = (const float*)d_in[23];
    const float* dec_b1 = (const float*)d_in[24];
    const float* dec_w2 = (const float*)d_in[25];
    const float* dec_b2 = (const float*)d_in[26];
    float* out = (float*)d_out;

    float *encin, *x, *e, *e0, *h, *agg, *xsd, *zeros, *dcb2p, *redgeS;
    int *srcS, *dstS;
    __nv_bfloat16 *pe1hi,*pe1lo,*wsdhi,*wsdlo,*pe2hi,*pe2lo,*pn1hi,*pn1lo,*pn2hi,*pn2lo;
    __nv_bfloat16 *dc1hi,*dc1lo,*dc2hi,*dc2lo,*en2hi,*en2lo;
    cudaGetSymbolAddress((void**)&encin, g_encin);
    cudaGetSymbolAddress((void**)&x,     g_x);
    cudaGetSymbolAddress((void**)&e,     g_e);
    cudaGetSymbolAddress((void**)&e0,    g_e0);
    cudaGetSymbolAddress((void**)&h,     g_h);
    cudaGetSymbolAddress((void**)&agg,   g_agg);
    cudaGetSymbolAddress((void**)&xsd,   g_xsd);
    cudaGetSymbolAddress((void**)&zeros, g_zeros);
    cudaGetSymbolAddress((void**)&dcb2p, g_dcb2p);
    cudaGetSymbolAddress((void**)&redgeS,g_redgeS);
    cudaGetSymbolAddress((void**)&srcS,  g_srcS);
    cudaGetSymbolAddress((void**)&dstS,  g_dstS);
    cudaGetSymbolAddress((void**)&pe1hi, g_pe1hi);
    cudaGetSymbolAddress((void**)&pe1lo, g_pe1lo);
    cudaGetSymbolAddress((void**)&wsdhi, g_wsdhi);
    cudaGetSymbolAddress((void**)&wsdlo, g_wsdlo);
    cudaGetSymbolAddress((void**)&pe2hi, g_pe2hi);
    cudaGetSymbolAddress((void**)&pe2lo, g_pe2lo);
    cudaGetSymbolAddress((void**)&pn1hi, g_pn1hi);
    cudaGetSymbolAddress((void**)&pn1lo, g_pn1lo);
    cudaGetSymbolAddress((void**)&pn2hi, g_pn2hi);
    cudaGetSymbolAddress((void**)&pn2lo, g_pn2lo);
    cudaGetSymbolAddress((void**)&dc1hi, g_dc1hi);
    cudaGetSymbolAddress((void**)&dc1lo, g_dc1lo);
    cudaGetSymbolAddress((void**)&dc2hi, g_dc2hi);
    cudaGetSymbolAddress((void**)&dc2lo, g_dc2lo);
    cudaGetSymbolAddress((void**)&en2hi, g_en2hi);
    cudaGetSymbolAddress((void**)&en2lo, g_en2lo);

    const int* src = eidx;
    const int* dst = eidx + NEDGE;

    constexpr int ASM    = 2 * (2 * 128 * 72 * 2);
    constexpr int SM128  = ASM + 2 * (2 * 64 * 136 * 2);  // 143360
    constexpr int SM80   = ASM + 2 * (2 * 64 * 88 * 2);   // 118784
    constexpr int SMFUSE = 178176;

    cudaFuncSetAttribute((const void*)mma_gemm<128,4,8,0,false,false>,
                         cudaFuncAttributeMaxDynamicSharedMemorySize, SM128);
    cudaFuncSetAttribute((const void*)mma_gemm<128,4,8,0,false,true>,
                         cudaFuncAttributeMaxDynamicSharedMemorySize, SM128);
    cudaFuncSetAttribute((const void*)mma_gemm<128,4,5,2,true,false>,
                         cudaFuncAttributeMaxDynamicSharedMemorySize, SM128);
    cudaFuncSetAttribute((const void*)mma_gemm<128,4,4,4,true,false>,
                         cudaFuncAttributeMaxDynamicSharedMemorySize, SM128);
    cudaFuncSetAttribute((const void*)mma_gemm<128,4,4,0,false,false>,
                         cudaFuncAttributeMaxDynamicSharedMemorySize, SM128);
    cudaFuncSetAttribute((const void*)mma_gemm<80,1,8,0,false,false>,
                         cudaFuncAttributeMaxDynamicSharedMemorySize, SM80);
    cudaFuncSetAttribute((const void*)fused_edge,
                         cudaFuncAttributeMaxDynamicSharedMemorySize, SMFUSE);

    // ---------- prep: weights + sort (launch order keeps ncu on real kernels) ----------
    prep_all<<<((int)T_ALL + 255) / 256, 256>>>(pe_w1, pe_w2, pn_w1, pn_w2,
                                                dec_w1, enc_w2, dec_w2, dec_b2);
    sort_hist<<<(NEDGE + 255) / 256, 256>>>(dst);
    sort_scan<<<1, 1024>>>();
    sort_scatter<<<(NEDGE + 255) / 256, 256>>>(src, dst, redge);

    // ---------- encoder ----------
    {
        int total = NBATCH * NMESH * ENC_LDA;
        build_encin<<<(total + 255) / 256, 256>>>(xc, xp, geo, g2m, encin);
    }
    sgemm_bias<128,128,16,8,8><<<gemm_grid(NBATCH*NMESH, HIDD, 128, 128), 256>>>(
        encin, ENC_LDA, enc_w1, enc_b1, nullptr, h, NBATCH*NMESH, HIDD, ENC_IN, 1);
    mma_gemm<128,4,8,0,false,false><<<dim3(2, (NBATCH*NMESH + 127)/128), 256, SM128>>>(
        h, nullptr, nullptr, en2hi, en2lo, enc_b2, nullptr, x,
        NBATCH*NMESH, NODE_D, NODE_D, NODE_D);

    // ---------- edge embedder (sorted edge space, shared across batches) ----------
    sgemm_bias<128,64,16,8,4><<<gemm_grid(NEDGE, EDGE_D, 128, 64), 256>>>(
        redgeS, 4, eme_w1, eme_b1, nullptr, h, NEDGE, EDGE_D, 4, 1);
    sgemm_bias<128,64,16,8,4><<<gemm_grid(NEDGE, EDGE_D, 128, 64), 256>>>(
        h, EDGE_D, eme_w2, eme_b2, nullptr, e0, NEDGE, EDGE_D, EDGE_D, 0);

    // ---------- GNN layers (both batches per launch) ----------
    const int MN = NBATCH * NMESH;   // 20484
    for (int l = 0; l < NLAYERS; l++) {
        const float* ein = (l == 0) ? e0 : e;
        size_t einStride = (l == 0) ? 0 : (size_t)NEDGE * EDGE_D;

        // xsd = x @ [Wsrc | Wdst]  (M=20484, K=256, N=1024)
        mma_gemm<128,4,4,0,false,false><<<dim3(8, (MN+127)/128), 256, SM128>>>(
            x, nullptr, nullptr,
            wsdhi + (size_t)l*256*1024, wsdlo + (size_t)l*256*1024,
            zeros, nullptr, xsd, MN, 1024, 1024, 1024);

        cudaMemsetAsync(agg, 0, (size_t)NBATCH * NMESH * EDGE_D * sizeof(float), 0);

        // fused edge MLP for both batches (dst-sorted, segmented scatter)
        fused_edge<<<dim3(NEDGE/128, NBATCH), 256, SMFUSE>>>(
            ein, xsd, srcS, dstS,
            pe1hi + (size_t)l*576*HIDD, pe1lo + (size_t)l*576*HIDD,
            pe2hi + (size_t)l*HIDD*EDGE_D, pe2lo + (size_t)l*HIDD*EDGE_D,
            pe_b1 + (size_t)l*HIDD, pe_b2 + (size_t)l*EDGE_D,
            e, agg, einStride);

        // node MLP1: [x | agg] @ W1 + b, relu  (M=20484)
        mma_gemm<128,4,5,2,true,false><<<dim3(4, (MN+127)/128), 256, SM128>>>(
            x, agg, nullptr,
            pn1hi + (size_t)l*320*HIDD, pn1lo + (size_t)l*320*HIDD,
            pn_b1 + (size_t)l*HIDD, nullptr, h, MN, HIDD, HIDD, HIDD);
        // node MLP2: h @ W2 + b + x (in place, M=20484)
        mma_gemm<128,4,8,0,false,true><<<dim3(2, (MN+127)/128), 256, SM128>>>(
            h, nullptr, nullptr,
            pn2hi + (size_t)l*HIDD*NODE_D, pn2lo + (size_t)l*HIDD*NODE_D,
            pn_b2 + (size_t)l*NODE_D, x, x, MN, NODE_D, NODE_D, NODE_D);
    }

    // ---------- decoder ----------
    mma_gemm<128,4,4,4,true,false><<<dim3(4, (NBATCH*NGRID+127)/128), 256, SM128>>>(
        x, nullptr, m2g,
        dc1hi, dc1lo, dec_b1, nullptr,
        h, NBATCH*NGRID, HIDD, HIDD, HIDD);
    mma_gemm<80,1,8,0,false,false><<<dim3(1, (NBATCH*NGRID + 127)/128), 256, SM80>>>(
        h, nullptr, nullptr, dc2hi, dc2lo, dcb2p, nullptr, out,
        NBATCH*NGRID, 80, 78, 78);
}